// round 2
// baseline (speedup 1.0000x reference)
#include <cuda_runtime.h>
#include <cuda_bf16.h>
#include <math.h>

// ---------------- problem constants ----------------
#define NB 2
#define N_IN 4096          // 64*64
#define N_OUT 484          // 22*22
#define DM 384
#define NH 12
#define HDIM 32
#define QG 22
#define GWID 64
#define KCONV 18816        // 49*384
#define BHTOT (NB*NH)      // 24
#define XOUT_SZ (NB*N_OUT*DM)              // 371712
#define ATTN_SZ ((size_t)NB*NH*N_OUT*N_IN) // 47579136
#define EPSQ 1.1920929e-07f
#define LN_EPS 1e-5f

// ---------------- scratch (static device memory; no allocations) ----------------
__device__ float g_wt[(size_t)KCONV*DM];        // transposed conv weights [k][co]
__device__ float g_convpart[4*XOUT_SZ];         // split-K conv partials
__device__ float g_xout[XOUT_SZ];
__device__ float g_kv[(size_t)NB*N_IN*2*DM];
__device__ float g_k[(size_t)NB*NH*N_IN*HDIM];
__device__ float g_v[(size_t)NB*NH*N_IN*HDIM];
__device__ float g_qlin[XOUT_SZ];
__device__ float g_q[NB*NH*N_OUT*HDIM];
__device__ float g_colinv[NB*NH*N_IN];
__device__ float g_upd[XOUT_SZ];
__device__ float g_mlp[NB*N_OUT*4*DM];
__device__ float g_mlpo[XOUT_SZ];

// ---------------- helpers ----------------
__device__ __forceinline__ float blockSum(float v, float* sred) {
    int tid = threadIdx.x, lane = tid & 31, wid = tid >> 5;
    #pragma unroll
    for (int o = 16; o; o >>= 1) v += __shfl_xor_sync(0xffffffffu, v, o);
    if (lane == 0) sred[wid] = v;
    __syncthreads();
    int nw = (blockDim.x + 31) >> 5;
    if (wid == 0) {
        float t = (lane < nw) ? sred[lane] : 0.f;
        #pragma unroll
        for (int o = 16; o; o >>= 1) t += __shfl_xor_sync(0xffffffffu, t, o);
        if (lane == 0) sred[0] = t;
    }
    __syncthreads();
    float r = sred[0];
    __syncthreads();
    return r;
}

__device__ __forceinline__ float blockMax(float v, float* sred) {
    int tid = threadIdx.x, lane = tid & 31, wid = tid >> 5;
    #pragma unroll
    for (int o = 16; o; o >>= 1) v = fmaxf(v, __shfl_xor_sync(0xffffffffu, v, o));
    if (lane == 0) sred[wid] = v;
    __syncthreads();
    int nw = (blockDim.x + 31) >> 5;
    if (wid == 0) {
        float t = (lane < nw) ? sred[lane] : -3.0e38f;
        #pragma unroll
        for (int o = 16; o; o >>= 1) t = fmaxf(t, __shfl_xor_sync(0xffffffffu, t, o));
        if (lane == 0) sred[0] = t;
    }
    __syncthreads();
    float r = sred[0];
    __syncthreads();
    return r;
}

// ---------------- conv weight transpose: (co,ci,t) -> (t,ci,co) ----------------
__global__ __launch_bounds__(256) void wt_transpose_kernel(const float* __restrict__ conv_w) {
    __shared__ float s[32][50];
    int co0 = blockIdx.x * 32;
    int ci = blockIdx.y;
    int tid = threadIdx.x;
    for (int idx = tid; idx < 32 * 49; idx += 256) {
        int r = idx / 49, t = idx - r * 49;
        s[r][t] = conv_w[(size_t)(co0 + r) * KCONV + ci * 49 + t];
    }
    __syncthreads();
    for (int idx = tid; idx < 49 * 32; idx += 256) {
        int t = idx >> 5, c = idx & 31;
        g_wt[((size_t)(t * DM + ci)) * DM + co0 + c] = s[c][t];
    }
}

// ---------------- implicit-GEMM conv (split-K=4, deterministic partials) ----------------
__global__ __launch_bounds__(256) void conv_kernel(const float* __restrict__ x) {
    __shared__ float As[16][68];
    __shared__ float Ws[16][64];
    int tid = threadIdx.x;
    int row0 = blockIdx.y * 64, col0 = blockIdx.x * 64;
    int split = blockIdx.z;
    int kbeg = split * 4704, kend = kbeg + 4704;
    int ty = tid >> 4, tx = tid & 15;
    int acol = tid & 15;
    int arow = tid >> 4;

    int mb[4], moy[4], mox[4];
    bool mval[4];
    #pragma unroll
    for (int it = 0; it < 4; it++) {
        int gr = row0 + it * 16 + arow;
        mval[it] = (gr < NB * N_OUT);
        int g2 = mval[it] ? gr : 0;
        mb[it] = g2 / N_OUT;
        int n = g2 - mb[it] * N_OUT;
        moy[it] = n / QG;
        mox[it] = n - moy[it] * QG;
    }
    float acc[4][4] = {};
    for (int k0 = kbeg; k0 < kend; k0 += 16) {
        int t = k0 / DM;
        int ci0 = k0 - t * DM;
        int ky = t / 7, kx = t - ky * 7;
        #pragma unroll
        for (int it = 0; it < 4; it++) {
            float v = 0.f;
            int iy = moy[it] * 3 - 3 + ky;
            int ix = mox[it] * 3 - 3 + kx;
            if (mval[it] && (unsigned)iy < 64u && (unsigned)ix < 64u)
                v = x[((size_t)(mb[it] * N_IN) + iy * 64 + ix) * DM + ci0 + acol];
            As[acol][it * 16 + arow] = v;
        }
        #pragma unroll
        for (int it = 0; it < 4; it++) {
            int r = it * 4 + (tid >> 6);
            Ws[r][tid & 63] = g_wt[(size_t)(k0 + r) * DM + col0 + (tid & 63)];
        }
        __syncthreads();
        #pragma unroll
        for (int kk = 0; kk < 16; kk++) {
            float a[4], b[4];
            #pragma unroll
            for (int i = 0; i < 4; i++) a[i] = As[kk][ty * 4 + i];
            #pragma unroll
            for (int j = 0; j < 4; j++) b[j] = Ws[kk][tx * 4 + j];
            #pragma unroll
            for (int i = 0; i < 4; i++)
                #pragma unroll
                for (int j = 0; j < 4; j++) acc[i][j] += a[i] * b[j];
        }
        __syncthreads();
    }
    #pragma unroll
    for (int i = 0; i < 4; i++) {
        int gr = row0 + ty * 4 + i;
        if (gr < NB * N_OUT)
            #pragma unroll
            for (int j = 0; j < 4; j++)
                g_convpart[split * XOUT_SZ + gr * DM + col0 + tx * 4 + j] = acc[i][j];
    }
}

// ---------------- conv partial reduce + bias + LN -> g_xout ----------------
__global__ __launch_bounds__(384) void conv_ln_kernel(const float* __restrict__ cb,
                                                      const float* __restrict__ g,
                                                      const float* __restrict__ b) {
    __shared__ float sred[32];
    int row = blockIdx.x, tid = threadIdx.x;
    float v = cb[tid];
    #pragma unroll
    for (int s = 0; s < 4; s++) v += g_convpart[s * XOUT_SZ + row * DM + tid];
    float mu = blockSum(v, sred) * (1.f / DM);
    float d = v - mu;
    float var = blockSum(d * d, sred) * (1.f / DM);
    float rs = rsqrtf(var + LN_EPS);
    g_xout[row * DM + tid] = d * rs * g[tid] + b[tid];
}

// ---------------- generic GEMM: C[M,N] = A[M,K] @ W[K,N] + bias, act=1 -> exact gelu ----------------
__global__ __launch_bounds__(256) void gemm_kernel(const float* __restrict__ A,
                                                   const float* __restrict__ W,
                                                   const float* __restrict__ bias,
                                                   float* __restrict__ C,
                                                   int M, int N, int K, int act) {
    __shared__ float As[16][68];
    __shared__ float Ws[16][64];
    int tid = threadIdx.x;
    int row0 = blockIdx.y * 64, col0 = blockIdx.x * 64;
    int ty = tid >> 4, tx = tid & 15;
    int arow = tid >> 4, acol = tid & 15;
    float acc[4][4] = {};
    for (int k0 = 0; k0 < K; k0 += 16) {
        #pragma unroll
        for (int it = 0; it < 4; it++) {
            int r = it * 16 + arow;
            int gr = row0 + r;
            As[acol][r] = (gr < M) ? A[(size_t)gr * K + k0 + acol] : 0.f;
        }
        #pragma unroll
        for (int it = 0; it < 4; it++) {
            int r = it * 4 + (tid >> 6);
            Ws[r][tid & 63] = W[(size_t)(k0 + r) * N + col0 + (tid & 63)];
        }
        __syncthreads();
        #pragma unroll
        for (int kk = 0; kk < 16; kk++) {
            float a[4], b[4];
            #pragma unroll
            for (int i = 0; i < 4; i++) a[i] = As[kk][ty * 4 + i];
            #pragma unroll
            for (int j = 0; j < 4; j++) b[j] = Ws[kk][tx * 4 + j];
            #pragma unroll
            for (int i = 0; i < 4; i++)
                #pragma unroll
                for (int j = 0; j < 4; j++) acc[i][j] += a[i] * b[j];
        }
        __syncthreads();
    }
    #pragma unroll
    for (int i = 0; i < 4; i++) {
        int gr = row0 + ty * 4 + i;
        if (gr >= M) continue;
        #pragma unroll
        for (int j = 0; j < 4; j++) {
            int gc = col0 + tx * 4 + j;
            float v = acc[i][j] + bias[gc];
            if (act == 1) v = 0.5f * v * (1.f + erff(v * 0.70710678118654752f));
            C[(size_t)gr * N + gc] = v;
        }
    }
}

// ---------------- rose for K (+ V transpose). one thread per output element ----------------
__global__ __launch_bounds__(256) void rose_kv_kernel(const float* __restrict__ temp,
                                                      const float* __restrict__ freqs) {
    int idx = blockIdx.x * 256 + threadIdx.x;          // < NB*NH*N_IN*32
    int d = idx & 31;
    int t = idx >> 5;
    int n = t & (N_IN - 1);
    int bh = t >> 12;
    int h = bh % NH;
    int b = bh / NH;
    const float* src = g_kv + ((size_t)(b * N_IN + n)) * (2 * DM) + h * HDIM;
    float tv = temp[0];
    float val;
    if (d < 16) {
        int j = d >> 1;
        int s = j >> 2, p = j & 3;
        float coord = (s == 0) ? (float)(n >> 6) : (float)(n & 63);
        float ang = coord * freqs[(h * 2 + s) * 4 + p];
        float sn, cs;
        sincosf(ang, &sn, &cs);
        float x1 = src[j * 2], x2 = src[j * 2 + 1];
        val = (d & 1) ? (x1 * sn + x2 * cs) : (x1 * cs - x2 * sn);
    } else {
        val = src[d];
    }
    g_k[idx] = tv * val;
    g_v[idx] = src[DM + d];
}

// ---------------- rose for Q ----------------
__global__ __launch_bounds__(256) void rose_q_kernel(const float* __restrict__ freqs) {
    int idx = blockIdx.x * 256 + threadIdx.x;          // < NB*NH*N_OUT*32
    int d = idx & 31;
    int t = idx >> 5;
    int n = t % N_OUT;
    int bh = t / N_OUT;
    int h = bh % NH;
    int b = bh / NH;
    const float* src = g_qlin + ((size_t)(b * N_OUT + n)) * DM + h * HDIM;
    float val;
    if (d < 16) {
        int j = d >> 1;
        int s = j >> 2, p = j & 3;
        float coord = (s == 0) ? (float)(n / QG) * 3.0f : (float)(n % QG) * 3.0f;
        float ang = coord * freqs[(h * 2 + s) * 4 + p];
        float sn, cs;
        sincosf(ang, &sn, &cs);
        float x1 = src[j * 2], x2 = src[j * 2 + 1];
        val = (d & 1) ? (x1 * sn + x2 * cs) : (x1 * cs - x2 * sn);
    } else {
        val = src[d];
    }
    g_q[idx] = val;
}

// ---------------- scores: S[bh][q][k] = q . k (K=32 GEMM-NT) ----------------
__global__ __launch_bounds__(256) void scores_kernel(float* __restrict__ attn) {
    __shared__ float Qs[32][65];
    __shared__ float Ks[32][65];
    int bh = blockIdx.z;
    const float* Aq = g_q + (size_t)bh * N_OUT * HDIM;
    const float* Bk = g_k + (size_t)bh * N_IN * HDIM;
    float* Cc = attn + (size_t)bh * N_OUT * N_IN;
    int row0 = blockIdx.y * 64, col0 = blockIdx.x * 64;
    int tid = threadIdx.x;
    int ty = tid >> 4, tx = tid & 15;
    #pragma unroll
    for (int it = 0; it < 8; it++) {
        int r = it * 8 + (tid >> 5);
        int c = tid & 31;
        Qs[c][r] = (row0 + r < N_OUT) ? Aq[(row0 + r) * HDIM + c] : 0.f;
        Ks[c][r] = Bk[(size_t)(col0 + r) * HDIM + c];
    }
    __syncthreads();
    float acc[4][4] = {};
    #pragma unroll
    for (int kk = 0; kk < 32; kk++) {
        float a[4], b[4];
        #pragma unroll
        for (int i = 0; i < 4; i++) a[i] = Qs[kk][ty * 4 + i];
        #pragma unroll
        for (int j = 0; j < 4; j++) b[j] = Ks[kk][tx * 4 + j];
        #pragma unroll
        for (int i = 0; i < 4; i++)
            #pragma unroll
            for (int j = 0; j < 4; j++) acc[i][j] += a[i] * b[j];
    }
    #pragma unroll
    for (int i = 0; i < 4; i++) {
        int gr = row0 + ty * 4 + i;
        if (gr >= N_OUT) continue;
        #pragma unroll
        for (int j = 0; j < 4; j++)
            Cc[(size_t)gr * N_IN + col0 + tx * 4 + j] = acc[i][j];
    }
}

// ---------------- row softmax in place ----------------
__global__ __launch_bounds__(256) void softmax_kernel(float* __restrict__ attn) {
    __shared__ float sred[32];
    int row = blockIdx.x;                      // 0 .. BHTOT*N_OUT-1
    float* p = attn + (size_t)row * N_IN;
    int tid = threadIdx.x;
    float v[16];
    #pragma unroll
    for (int i = 0; i < 16; i++) v[i] = p[i * 256 + tid];
    float m = -3.0e38f;
    #pragma unroll
    for (int i = 0; i < 16; i++) m = fmaxf(m, v[i]);
    m = blockMax(m, sred);
    float s = 0.f;
    #pragma unroll
    for (int i = 0; i < 16; i++) { v[i] = __expf(v[i] - m); s += v[i]; }
    s = blockSum(s, sred);
    float inv = 1.f / s;
    #pragma unroll
    for (int i = 0; i < 16; i++) p[i * 256 + tid] = v[i] * inv;
}

// ---------------- column-sum inverse: 1/(sum_q attn[q][k] + EPS) ----------------
__global__ __launch_bounds__(256) void colinv_kernel(const float* __restrict__ attn) {
    int bh = blockIdx.y;
    int k = blockIdx.x * 256 + threadIdx.x;
    const float* p = attn + (size_t)bh * N_OUT * N_IN + k;
    float s0 = 0.f, s1 = 0.f, s2 = 0.f, s3 = 0.f;
    int q = 0;
    for (; q + 3 < N_OUT; q += 4) {
        s0 += p[(size_t)q * N_IN];
        s1 += p[(size_t)(q + 1) * N_IN];
        s2 += p[(size_t)(q + 2) * N_IN];
        s3 += p[(size_t)(q + 3) * N_IN];
    }
    for (; q < N_OUT; q++) s0 += p[(size_t)q * N_IN];
    g_colinv[bh * N_IN + k] = 1.f / ((s0 + s1) + (s2 + s3) + EPSQ);
}

// ---------------- upd = attn_k @ (v * colinv), written to (b, q, h*32+d) layout ----------------
__global__ __launch_bounds__(256) void upd_kernel(const float* __restrict__ attn) {
    __shared__ float As[32][128];
    __shared__ float Vs[128][33];
    int bh = blockIdx.y;
    int b = bh / NH, h = bh - b * NH;
    int q0 = blockIdx.x * 32;
    int tid = threadIdx.x;
    int qi = tid >> 5, d = tid & 31;
    const float* Ap = attn + (size_t)bh * N_OUT * N_IN;
    const float* Vp = g_v + (size_t)bh * N_IN * HDIM;
    const float* Ci = g_colinv + bh * N_IN;
    float acc[4] = {0.f, 0.f, 0.f, 0.f};
    for (int kt = 0; kt < N_IN; kt += 128) {
        #pragma unroll
        for (int it = 0; it < 16; it++) {
            int idx = it * 256 + tid;
            int r = idx >> 7, kk = idx & 127;
            int q = q0 + r;
            As[r][kk] = (q < N_OUT) ? Ap[(size_t)q * N_IN + kt + kk] : 0.f;
        }
        #pragma unroll
        for (int it = 0; it < 16; it++) {
            int idx = it * 256 + tid;
            int kk = idx >> 5, c = idx & 31;
            Vs[kk][c] = Vp[(size_t)(kt + kk) * HDIM + c] * __ldg(&Ci[kt + kk]);
        }
        __syncthreads();
        #pragma unroll 8
        for (int kk = 0; kk < 128; kk++) {
            float vv = Vs[kk][d];
            acc[0] += As[qi][kk] * vv;
            acc[1] += As[qi + 8][kk] * vv;
            acc[2] += As[qi + 16][kk] * vv;
            acc[3] += As[qi + 24][kk] * vv;
        }
        __syncthreads();
    }
    #pragma unroll
    for (int i = 0; i < 4; i++) {
        int q = q0 + qi + i * 8;
        if (q < N_OUT) g_upd[((size_t)(b * N_OUT) + q) * DM + h * HDIM + d] = acc[i];
    }
}

// ---------------- x_out += LN(src)*g + b ----------------
__global__ __launch_bounds__(384) void ln_add_kernel(const float* __restrict__ src,
                                                     const float* __restrict__ g,
                                                     const float* __restrict__ b) {
    __shared__ float sred[32];
    int row = blockIdx.x, tid = threadIdx.x;
    float v = src[row * DM + tid];
    float mu = blockSum(v, sred) * (1.f / DM);
    float d = v - mu;
    float var = blockSum(d * d, sred) * (1.f / DM);
    float rs = rsqrtf(var + LN_EPS);
    g_xout[row * DM + tid] += d * rs * g[tid] + b[tid];
}

// ---------------- attn_q = attn_k * colinv ----------------
__global__ __launch_bounds__(256) void attnq_kernel(const float* __restrict__ attn_k,
                                                    float* __restrict__ attn_q) {
    size_t stride = (size_t)gridDim.x * 256;
    for (size_t i = (size_t)blockIdx.x * 256 + threadIdx.x; i < ATTN_SZ; i += stride) {
        int k = (int)(i & (N_IN - 1));
        int bh = (int)((i >> 12) / N_OUT);
        attn_q[i] = attn_k[i] * g_colinv[bh * N_IN + k];
    }
}

// ---------------- copy x_out to d_out ----------------
__global__ __launch_bounds__(256) void copy_xout_kernel(float* __restrict__ out) {
    int i = blockIdx.x * 256 + threadIdx.x;
    out[i] = g_xout[i];
}

// ---------------- launch ----------------
extern "C" void kernel_launch(void* const* d_in, const int* in_sizes, int n_in,
                              void* d_out, int out_size) {
    const float* x      = (const float*)d_in[0];
    const float* conv_w = (const float*)d_in[1];
    const float* conv_b = (const float*)d_in[2];
    const float* kv_w   = (const float*)d_in[3];
    const float* kv_b   = (const float*)d_in[4];
    const float* q_w    = (const float*)d_in[5];
    const float* q_b    = (const float*)d_in[6];
    const float* mlp_w1 = (const float*)d_in[7];
    const float* mlp_b1 = (const float*)d_in[8];
    const float* mlp_w2 = (const float*)d_in[9];
    const float* mlp_b2 = (const float*)d_in[10];
    const float* g1     = (const float*)d_in[11];
    const float* b1     = (const float*)d_in[12];
    const float* g2     = (const float*)d_in[13];
    const float* b2     = (const float*)d_in[14];
    const float* g3     = (const float*)d_in[15];
    const float* b3     = (const float*)d_in[16];
    const float* temp   = (const float*)d_in[17];
    const float* freqs  = (const float*)d_in[18];

    float* out = (float*)d_out;
    float* attn_q_out = out + XOUT_SZ;
    float* attn_k_out = out + XOUT_SZ + ATTN_SZ;

    void *p_kv_, *p_xout_, *p_qlin_, *p_mlp_, *p_mlpo_, *p_upd_;
    cudaGetSymbolAddress(&p_kv_, g_kv);
    cudaGetSymbolAddress(&p_xout_, g_xout);
    cudaGetSymbolAddress(&p_qlin_, g_qlin);
    cudaGetSymbolAddress(&p_mlp_, g_mlp);
    cudaGetSymbolAddress(&p_mlpo_, g_mlpo);
    cudaGetSymbolAddress(&p_upd_, g_upd);
    float* p_kv   = (float*)p_kv_;
    float* p_xout = (float*)p_xout_;
    float* p_qlin = (float*)p_qlin_;
    float* p_mlp  = (float*)p_mlp_;
    float* p_mlpo = (float*)p_mlpo_;
    float* p_upd  = (float*)p_upd_;

    // one-time (per call) preprocessing
    wt_transpose_kernel<<<dim3(12, 384), 256>>>(conv_w);
    conv_kernel<<<dim3(6, 16, 4), 256>>>(x);
    conv_ln_kernel<<<NB * N_OUT, 384>>>(conv_b, g1, b1);

    // loop-invariant kv / k / v
    gemm_kernel<<<dim3(12, 128), 256>>>(x, kv_w, kv_b, p_kv, NB * N_IN, 2 * DM, DM, 0);
    rose_kv_kernel<<<(NB * NH * N_IN * HDIM) / 256, 256>>>(temp, freqs);

    for (int it = 0; it < 3; it++) {
        gemm_kernel<<<dim3(6, 16), 256>>>(p_xout, q_w, q_b, p_qlin, NB * N_OUT, DM, DM, 0);
        rose_q_kernel<<<(NB * NH * N_OUT * HDIM) / 256, 256>>>(freqs);
        scores_kernel<<<dim3(64, 8, BHTOT), 256>>>(attn_k_out);
        softmax_kernel<<<BHTOT * N_OUT, 256>>>(attn_k_out);
        colinv_kernel<<<dim3(16, BHTOT), 256>>>(attn_k_out);
        upd_kernel<<<dim3(16, BHTOT), 256>>>(attn_k_out);
        ln_add_kernel<<<NB * N_OUT, 384>>>(p_upd, g2, b2);
        gemm_kernel<<<dim3(24, 16), 256>>>(p_xout, mlp_w1, mlp_b1, p_mlp, NB * N_OUT, 4 * DM, DM, 1);
        gemm_kernel<<<dim3(6, 16), 256>>>(p_mlp, mlp_w2, mlp_b2, p_mlpo, NB * N_OUT, DM, 4 * DM, 0);
        ln_add_kernel<<<NB * N_OUT, 384>>>(p_mlpo, g3, b3);
    }

    attnq_kernel<<<8192, 256>>>(attn_k_out, attn_q_out);
    copy_xout_kernel<<<XOUT_SZ / 256, 256>>>(out);
}

// round 3
// speedup vs baseline: 1.6893x; 1.6893x over previous
#include <cuda_runtime.h>
#include <cuda_bf16.h>
#include <math.h>

// ---------------- problem constants ----------------
#define NB 2
#define N_IN 4096          // 64*64
#define N_OUT 484          // 22*22
#define DM 384
#define NH 12
#define HDIM 32
#define QG 22
#define KCONV 18816        // 49*384
#define BHTOT (NB*NH)      // 24
#define XOUT_SZ (NB*N_OUT*DM)              // 371712
#define ATTN_SZ ((size_t)NB*NH*N_OUT*N_IN) // 47579136
#define NROWS (BHTOT*N_OUT)                // 11616
#define KTILES 64
#define EPSQ 1.1920929e-07f
#define LN_EPS 1e-5f

// ---------------- scratch (static device memory; no allocations) ----------------
__device__ float g_wt[(size_t)KCONV*DM];
__device__ float g_convpart[4*XOUT_SZ];
__device__ float g_xout[XOUT_SZ];
__device__ float g_kv[(size_t)NB*N_IN*2*DM];
__device__ float g_k[(size_t)NB*NH*N_IN*HDIM];
__device__ float g_v[(size_t)NB*NH*N_IN*HDIM];
__device__ float g_qlin[XOUT_SZ];
__device__ float g_q[NB*NH*N_OUT*HDIM];
__device__ float g_colinv[BHTOT*N_IN];
__device__ float g_rowpart[(size_t)NROWS*KTILES];
__device__ float g_rinv[NROWS];
__device__ float g_upd[XOUT_SZ];
__device__ float g_mlp[NB*N_OUT*4*DM];
__device__ float g_mlpo[XOUT_SZ];

// ---------------- helpers ----------------
__device__ __forceinline__ float blockSum(float v, float* sred) {
    int tid = threadIdx.x, lane = tid & 31, wid = tid >> 5;
    #pragma unroll
    for (int o = 16; o; o >>= 1) v += __shfl_xor_sync(0xffffffffu, v, o);
    if (lane == 0) sred[wid] = v;
    __syncthreads();
    int nw = (blockDim.x + 31) >> 5;
    if (wid == 0) {
        float t = (lane < nw) ? sred[lane] : 0.f;
        #pragma unroll
        for (int o = 16; o; o >>= 1) t += __shfl_xor_sync(0xffffffffu, t, o);
        if (lane == 0) sred[0] = t;
    }
    __syncthreads();
    float r = sred[0];
    __syncthreads();
    return r;
}

// ---------------- conv weight transpose: (co,ci,t) -> (t,ci,co) ----------------
__global__ __launch_bounds__(256) void wt_transpose_kernel(const float* __restrict__ conv_w) {
    __shared__ float s[32][50];
    int co0 = blockIdx.x * 32;
    int ci = blockIdx.y;
    int tid = threadIdx.x;
    for (int idx = tid; idx < 32 * 49; idx += 256) {
        int r = idx / 49, t = idx - r * 49;
        s[r][t] = conv_w[(size_t)(co0 + r) * KCONV + ci * 49 + t];
    }
    __syncthreads();
    for (int idx = tid; idx < 49 * 32; idx += 256) {
        int t = idx >> 5, c = idx & 31;
        g_wt[((size_t)(t * DM + ci)) * DM + co0 + c] = s[c][t];
    }
}

// ---------------- generic GEMM: C = A@W + bias (act=1 -> exact gelu) ----------------
// BM x 64 tile, BK=16, 256 threads, (BM/16) x 4 per-thread tile, float4 everywhere,
// register prefetch to overlap global loads with compute.
template<int BM>
__global__ __launch_bounds__(256) void gemm_t(const float* __restrict__ A,
                                              const float* __restrict__ W,
                                              const float* __restrict__ bias,
                                              float* __restrict__ C,
                                              int M, int N, int K, int act) {
    constexpr int TM = BM / 16;
    constexpr int NLA = BM / 64;      // float4 A-loads per thread
    __shared__ float As[16][BM];
    __shared__ float Bs[16][64];
    int tid = threadIdx.x, tx = tid & 15, ty = tid >> 4;
    int row0 = blockIdx.y * BM, col0 = blockIdx.x * 64;
    int ar[NLA], aq[NLA];
    #pragma unroll
    for (int l = 0; l < NLA; l++) { int f4 = tid + l * 256; ar[l] = f4 >> 2; aq[l] = f4 & 3; }
    int brow = tid >> 4, bq = tid & 15;

    float acc[TM][4] = {};
    float4 pa[NLA], pb;

    #pragma unroll
    for (int l = 0; l < NLA; l++) {
        int gr = row0 + ar[l];
        pa[l] = (gr < M) ? *reinterpret_cast<const float4*>(&A[(size_t)gr * K + aq[l] * 4])
                         : make_float4(0.f, 0.f, 0.f, 0.f);
    }
    pb = *reinterpret_cast<const float4*>(&W[(size_t)brow * N + col0 + bq * 4]);

    for (int k0 = 0;;) {
        #pragma unroll
        for (int l = 0; l < NLA; l++) {
            As[aq[l] * 4 + 0][ar[l]] = pa[l].x;
            As[aq[l] * 4 + 1][ar[l]] = pa[l].y;
            As[aq[l] * 4 + 2][ar[l]] = pa[l].z;
            As[aq[l] * 4 + 3][ar[l]] = pa[l].w;
        }
        *reinterpret_cast<float4*>(&Bs[brow][bq * 4]) = pb;
        __syncthreads();

        int kn = k0 + 16;
        if (kn < K) {
            #pragma unroll
            for (int l = 0; l < NLA; l++) {
                int gr = row0 + ar[l];
                pa[l] = (gr < M) ? *reinterpret_cast<const float4*>(&A[(size_t)gr * K + kn + aq[l] * 4])
                                 : make_float4(0.f, 0.f, 0.f, 0.f);
            }
            pb = *reinterpret_cast<const float4*>(&W[(size_t)(kn + brow) * N + col0 + bq * 4]);
        }

        #pragma unroll
        for (int kk = 0; kk < 16; kk++) {
            float4 b4 = *reinterpret_cast<const float4*>(&Bs[kk][tx * 4]);
            float bv[4] = {b4.x, b4.y, b4.z, b4.w};
            #pragma unroll
            for (int h = 0; h < TM / 4; h++) {
                float4 a4 = *reinterpret_cast<const float4*>(&As[kk][ty * TM + h * 4]);
                float av[4] = {a4.x, a4.y, a4.z, a4.w};
                #pragma unroll
                for (int i = 0; i < 4; i++)
                    #pragma unroll
                    for (int j = 0; j < 4; j++)
                        acc[h * 4 + i][j] += av[i] * bv[j];
            }
        }
        k0 = kn;
        if (k0 >= K) break;
        __syncthreads();
    }

    #pragma unroll
    for (int i = 0; i < TM; i++) {
        int gr = row0 + ty * TM + i;
        if (gr >= M) continue;
        float o[4];
        #pragma unroll
        for (int j = 0; j < 4; j++) {
            float v = acc[i][j] + bias[col0 + tx * 4 + j];
            if (act == 1) v = 0.5f * v * (1.f + erff(v * 0.70710678118654752f));
            o[j] = v;
        }
        *reinterpret_cast<float4*>(&C[(size_t)gr * N + col0 + tx * 4]) =
            make_float4(o[0], o[1], o[2], o[3]);
    }
}

// ---------------- implicit-GEMM conv (split-K=4, deterministic partials) ----------------
__global__ __launch_bounds__(256) void conv_t(const float* __restrict__ x) {
    constexpr int BM = 128;
    __shared__ float As[16][BM];
    __shared__ float Bs[16][64];
    int tid = threadIdx.x, tx = tid & 15, ty = tid >> 4;
    int row0 = blockIdx.y * BM, col0 = blockIdx.x * 64;
    int kbeg = blockIdx.z * 4704, kend = kbeg + 4704;

    int ar[2], aq[2], rb[2], roy[2], rox[2];
    bool rv[2];
    #pragma unroll
    for (int l = 0; l < 2; l++) {
        int f4 = tid + l * 256; ar[l] = f4 >> 2; aq[l] = f4 & 3;
        int gr = row0 + ar[l];
        rv[l] = gr < NB * N_OUT;
        int g2 = rv[l] ? gr : 0;
        rb[l] = g2 / N_OUT;
        int n = g2 - rb[l] * N_OUT;
        roy[l] = n / QG; rox[l] = n - roy[l] * QG;
    }
    int brow = tid >> 4, bq = tid & 15;

    float acc[8][4] = {};
    float4 pa[2], pb;

    auto ld = [&](int k0) {
        int t = k0 / DM; int ci0 = k0 - t * DM;
        int ky = t / 7, kx = t - ky * 7;
        #pragma unroll
        for (int l = 0; l < 2; l++) {
            int iy = roy[l] * 3 - 3 + ky, ix = rox[l] * 3 - 3 + kx;
            bool ok = rv[l] && (unsigned)iy < 64u && (unsigned)ix < 64u;
            pa[l] = ok ? *reinterpret_cast<const float4*>(
                             &x[((size_t)(rb[l] * N_IN) + iy * 64 + ix) * DM + ci0 + aq[l] * 4])
                       : make_float4(0.f, 0.f, 0.f, 0.f);
        }
        pb = *reinterpret_cast<const float4*>(&g_wt[(size_t)(k0 + brow) * DM + col0 + bq * 4]);
    };

    ld(kbeg);
    for (int k0 = kbeg;;) {
        #pragma unroll
        for (int l = 0; l < 2; l++) {
            As[aq[l] * 4 + 0][ar[l]] = pa[l].x;
            As[aq[l] * 4 + 1][ar[l]] = pa[l].y;
            As[aq[l] * 4 + 2][ar[l]] = pa[l].z;
            As[aq[l] * 4 + 3][ar[l]] = pa[l].w;
        }
        *reinterpret_cast<float4*>(&Bs[brow][bq * 4]) = pb;
        __syncthreads();

        int kn = k0 + 16;
        if (kn < kend) ld(kn);

        #pragma unroll
        for (int kk = 0; kk < 16; kk++) {
            float4 b4 = *reinterpret_cast<const float4*>(&Bs[kk][tx * 4]);
            float bv[4] = {b4.x, b4.y, b4.z, b4.w};
            #pragma unroll
            for (int h = 0; h < 2; h++) {
                float4 a4 = *reinterpret_cast<const float4*>(&As[kk][ty * 8 + h * 4]);
                float av[4] = {a4.x, a4.y, a4.z, a4.w};
                #pragma unroll
                for (int i = 0; i < 4; i++)
                    #pragma unroll
                    for (int j = 0; j < 4; j++)
                        acc[h * 4 + i][j] += av[i] * bv[j];
            }
        }
        k0 = kn;
        if (k0 >= kend) break;
        __syncthreads();
    }

    #pragma unroll
    for (int i = 0; i < 8; i++) {
        int gr = row0 + ty * 8 + i;
        if (gr < NB * N_OUT)
            *reinterpret_cast<float4*>(
                &g_convpart[(size_t)blockIdx.z * XOUT_SZ + gr * DM + col0 + tx * 4]) =
                make_float4(acc[i][0], acc[i][1], acc[i][2], acc[i][3]);
    }
}

// ---------------- conv partial reduce + bias + LN -> g_xout ----------------
__global__ __launch_bounds__(384) void conv_ln_kernel(const float* __restrict__ cb,
                                                      const float* __restrict__ g,
                                                      const float* __restrict__ b) {
    __shared__ float sred[32];
    int row = blockIdx.x, tid = threadIdx.x;
    float v = cb[tid];
    #pragma unroll
    for (int s = 0; s < 4; s++) v += g_convpart[(size_t)s * XOUT_SZ + row * DM + tid];
    float mu = blockSum(v, sred) * (1.f / DM);
    float d = v - mu;
    float var = blockSum(d * d, sred) * (1.f / DM);
    float rs = rsqrtf(var + LN_EPS);
    g_xout[row * DM + tid] = d * rs * g[tid] + b[tid];
}

// ---------------- rose for K (+ V split). one thread per output element ----------------
__global__ __launch_bounds__(256) void rose_kv_kernel(const float* __restrict__ temp,
                                                      const float* __restrict__ freqs) {
    int idx = blockIdx.x * 256 + threadIdx.x;
    int d = idx & 31;
    int t = idx >> 5;
    int n = t & (N_IN - 1);
    int bh = t >> 12;
    int h = bh % NH;
    int b = bh / NH;
    const float* src = g_kv + ((size_t)(b * N_IN + n)) * (2 * DM) + h * HDIM;
    float tv = temp[0];
    float val;
    if (d < 16) {
        int j = d >> 1;
        int s = j >> 2, p = j & 3;
        float coord = (s == 0) ? (float)(n >> 6) : (float)(n & 63);
        float ang = coord * freqs[(h * 2 + s) * 4 + p];
        float sn, cs;
        sincosf(ang, &sn, &cs);
        float x1 = src[j * 2], x2 = src[j * 2 + 1];
        val = (d & 1) ? (x1 * sn + x2 * cs) : (x1 * cs - x2 * sn);
    } else {
        val = src[d];
    }
    g_k[idx] = tv * val;
    g_v[idx] = src[DM + d];
}

// ---------------- rose for Q ----------------
__global__ __launch_bounds__(256) void rose_q_kernel(const float* __restrict__ freqs) {
    int idx = blockIdx.x * 256 + threadIdx.x;
    int d = idx & 31;
    int t = idx >> 5;
    int n = t % N_OUT;
    int bh = t / N_OUT;
    int h = bh % NH;
    int b = bh / NH;
    const float* src = g_qlin + ((size_t)(b * N_OUT + n)) * DM + h * HDIM;
    float val;
    if (d < 16) {
        int j = d >> 1;
        int s = j >> 2, p = j & 3;
        float coord = (s == 0) ? (float)(n / QG) * 3.0f : (float)(n % QG) * 3.0f;
        float ang = coord * freqs[(h * 2 + s) * 4 + p];
        float sn, cs;
        sincosf(ang, &sn, &cs);
        float x1 = src[j * 2], x2 = src[j * 2 + 1];
        val = (d & 1) ? (x1 * sn + x2 * cs) : (x1 * cs - x2 * sn);
    } else {
        val = src[d];
    }
    g_q[idx] = val;
}

// ---------------- scores fused with exp + partial row sums ----------------
// Writes e = exp(q.k) (logits are tiny here: |s| << 1, so no max subtraction needed)
// and per-(row, ktile) partial sums of e for deferred normalization.
__global__ __launch_bounds__(256) void scores_kernel(float* __restrict__ attn) {
    __shared__ float Qs[32][65];
    __shared__ float Ks[32][65];
    int bh = blockIdx.z;
    const float* Aq = g_q + (size_t)bh * N_OUT * HDIM;
    const float* Bk = g_k + (size_t)bh * N_IN * HDIM;
    float* Cc = attn + (size_t)bh * N_OUT * N_IN;
    int row0 = blockIdx.y * 64, col0 = blockIdx.x * 64;
    int tid = threadIdx.x;
    int ty = tid >> 4, tx = tid & 15;
    #pragma unroll
    for (int it = 0; it < 8; it++) {
        int r = it * 8 + (tid >> 5);
        int c = tid & 31;
        Qs[c][r] = (row0 + r < N_OUT) ? Aq[(row0 + r) * HDIM + c] : 0.f;
        Ks[c][r] = Bk[(size_t)(col0 + r) * HDIM + c];
    }
    __syncthreads();
    float acc[4][4] = {};
    #pragma unroll
    for (int kk = 0; kk < 32; kk++) {
        float a[4], b[4];
        #pragma unroll
        for (int i = 0; i < 4; i++) a[i] = Qs[kk][ty * 4 + i];
        #pragma unroll
        for (int j = 0; j < 4; j++) b[j] = Ks[kk][tx * 4 + j];
        #pragma unroll
        for (int i = 0; i < 4; i++)
            #pragma unroll
            for (int j = 0; j < 4; j++) acc[i][j] += a[i] * b[j];
    }
    #pragma unroll
    for (int i = 0; i < 4; i++) {
        int gr = row0 + ty * 4 + i;
        float e0 = expf(acc[i][0]), e1 = expf(acc[i][1]);
        float e2 = expf(acc[i][2]), e3 = expf(acc[i][3]);
        float s = (e0 + e1) + (e2 + e3);
        #pragma unroll
        for (int o = 1; o < 16; o <<= 1) s += __shfl_xor_sync(0xffffffffu, s, o);
        if (gr < N_OUT) {
            *reinterpret_cast<float4*>(&Cc[(size_t)gr * N_IN + col0 + tx * 4]) =
                make_float4(e0, e1, e2, e3);
            if (tx == 0)
                g_rowpart[(size_t)(bh * N_OUT + gr) * KTILES + blockIdx.x] = s;
        }
    }
}

// ---------------- reduce row partials -> rinv = 1/rowsum ----------------
__global__ __launch_bounds__(32) void rowsum_kernel() {
    int row = blockIdx.x, lane = threadIdx.x;
    const float* p = g_rowpart + (size_t)row * KTILES;
    float v = p[lane] + p[lane + 32];
    #pragma unroll
    for (int o = 16; o; o >>= 1) v += __shfl_xor_sync(0xffffffffu, v, o);
    if (lane == 0) g_rinv[row] = 1.f / v;
}

// ---------------- colinv: 1/(sum_q e[q,k]*rinv[q] + EPS) ----------------
__global__ __launch_bounds__(256) void colinv_kernel(const float* __restrict__ attn) {
    int bh = blockIdx.y;
    int k = blockIdx.x * 256 + threadIdx.x;
    const float* p = attn + (size_t)bh * N_OUT * N_IN + k;
    const float* ri = g_rinv + bh * N_OUT;
    float s0 = 0.f, s1 = 0.f, s2 = 0.f, s3 = 0.f;
    int q = 0;
    for (; q + 3 < N_OUT; q += 4) {
        s0 += p[(size_t)q * N_IN] * ri[q];
        s1 += p[(size_t)(q + 1) * N_IN] * ri[q + 1];
        s2 += p[(size_t)(q + 2) * N_IN] * ri[q + 2];
        s3 += p[(size_t)(q + 3) * N_IN] * ri[q + 3];
    }
    g_colinv[bh * N_IN + k] = 1.f / ((s0 + s1) + (s2 + s3) + EPSQ);
}

// ---------------- upd = rinv[q] * sum_k e[q,k]*colinv[k]*v[k,d] ----------------
__global__ __launch_bounds__(256) void upd_kernel(const float* __restrict__ attn) {
    __shared__ float As[32][128];
    __shared__ float Vs[128][33];
    int bh = blockIdx.y;
    int b = bh / NH, h = bh - b * NH;
    int q0 = blockIdx.x * 32;
    int tid = threadIdx.x;
    int qi = tid >> 5, d = tid & 31;
    const float* Ap = attn + (size_t)bh * N_OUT * N_IN;
    const float* Vp = g_v + (size_t)bh * N_IN * HDIM;
    const float* Ci = g_colinv + bh * N_IN;
    float acc[4] = {0.f, 0.f, 0.f, 0.f};
    for (int kt = 0; kt < N_IN; kt += 128) {
        #pragma unroll
        for (int it = 0; it < 16; it++) {
            int idx = it * 256 + tid;
            int r = idx >> 7, kk = idx & 127;
            int q = q0 + r;
            As[r][kk] = (q < N_OUT) ? Ap[(size_t)q * N_IN + kt + kk] : 0.f;
        }
        #pragma unroll
        for (int it = 0; it < 16; it++) {
            int idx = it * 256 + tid;
            int kk = idx >> 5, c = idx & 31;
            Vs[kk][c] = Vp[(size_t)(kt + kk) * HDIM + c] * __ldg(&Ci[kt + kk]);
        }
        __syncthreads();
        #pragma unroll 8
        for (int kk = 0; kk < 128; kk++) {
            float vv = Vs[kk][d];
            acc[0] += As[qi][kk] * vv;
            acc[1] += As[qi + 8][kk] * vv;
            acc[2] += As[qi + 16][kk] * vv;
            acc[3] += As[qi + 24][kk] * vv;
        }
        __syncthreads();
    }
    #pragma unroll
    for (int i = 0; i < 4; i++) {
        int q = q0 + qi + i * 8;
        if (q < N_OUT) {
            float rq = g_rinv[bh * N_OUT + q];
            g_upd[((size_t)(b * N_OUT) + q) * DM + h * HDIM + d] = acc[i] * rq;
        }
    }
}

// ---------------- x_out += LN(src)*g + b ----------------
__global__ __launch_bounds__(384) void ln_add_kernel(const float* __restrict__ src,
                                                     const float* __restrict__ g,
                                                     const float* __restrict__ b) {
    __shared__ float sred[32];
    int row = blockIdx.x, tid = threadIdx.x;
    float v = src[row * DM + tid];
    float mu = blockSum(v, sred) * (1.f / DM);
    float d = v - mu;
    float var = blockSum(d * d, sred) * (1.f / DM);
    float rs = rsqrtf(var + LN_EPS);
    g_xout[row * DM + tid] += d * rs * g[tid] + b[tid];
}

// ---------------- finalize: attn_k = e*rinv (in place); attn_q = attn_k*colinv ----------------
__global__ __launch_bounds__(256) void finalize_kernel(float* __restrict__ attn_k,
                                                       float* __restrict__ attn_q) {
    int bh = blockIdx.z, q = blockIdx.y;
    int k = blockIdx.x * 256 + threadIdx.x;
    size_t i = ((size_t)(bh * N_OUT + q) << 12) + k;
    float r = g_rinv[bh * N_OUT + q];
    float ak = attn_k[i] * r;
    attn_k[i] = ak;
    attn_q[i] = ak * g_colinv[bh * N_IN + k];
}

// ---------------- copy x_out to d_out ----------------
__global__ __launch_bounds__(256) void copy_xout_kernel(float* __restrict__ out) {
    int i = blockIdx.x * 256 + threadIdx.x;
    out[i] = g_xout[i];
}

// ---------------- launch ----------------
extern "C" void kernel_launch(void* const* d_in, const int* in_sizes, int n_in,
                              void* d_out, int out_size) {
    const float* x      = (const float*)d_in[0];
    const float* conv_w = (const float*)d_in[1];
    const float* conv_b = (const float*)d_in[2];
    const float* kv_w   = (const float*)d_in[3];
    const float* kv_b   = (const float*)d_in[4];
    const float* q_w    = (const float*)d_in[5];
    const float* q_b    = (const float*)d_in[6];
    const float* mlp_w1 = (const float*)d_in[7];
    const float* mlp_b1 = (const float*)d_in[8];
    const float* mlp_w2 = (const float*)d_in[9];
    const float* mlp_b2 = (const float*)d_in[10];
    const float* g1     = (const float*)d_in[11];
    const float* b1     = (const float*)d_in[12];
    const float* g2     = (const float*)d_in[13];
    const float* b2     = (const float*)d_in[14];
    const float* g3     = (const float*)d_in[15];
    const float* b3     = (const float*)d_in[16];
    const float* temp   = (const float*)d_in[17];
    const float* freqs  = (const float*)d_in[18];

    float* out = (float*)d_out;
    float* attn_q_out = out + XOUT_SZ;
    float* attn_k_out = out + XOUT_SZ + ATTN_SZ;

    void *p_kv_, *p_xout_, *p_qlin_, *p_mlp_, *p_mlpo_, *p_upd_;
    cudaGetSymbolAddress(&p_kv_, g_kv);
    cudaGetSymbolAddress(&p_xout_, g_xout);
    cudaGetSymbolAddress(&p_qlin_, g_qlin);
    cudaGetSymbolAddress(&p_mlp_, g_mlp);
    cudaGetSymbolAddress(&p_mlpo_, g_mlpo);
    cudaGetSymbolAddress(&p_upd_, g_upd);
    float* p_kv   = (float*)p_kv_;
    float* p_xout = (float*)p_xout_;
    float* p_qlin = (float*)p_qlin_;
    float* p_mlp  = (float*)p_mlp_;
    float* p_mlpo = (float*)p_mlpo_;
    float* p_upd  = (float*)p_upd_;

    // one-time preprocessing
    wt_transpose_kernel<<<dim3(12, 384), 256>>>(conv_w);
    conv_t<<<dim3(6, 8, 4), 256>>>(x);
    conv_ln_kernel<<<NB * N_OUT, 384>>>(conv_b, g1, b1);

    // loop-invariant kv / k / v
    gemm_t<128><<<dim3(12, 64), 256>>>(x, kv_w, kv_b, p_kv, NB * N_IN, 2 * DM, DM, 0);
    rose_kv_kernel<<<(NB * NH * N_IN * HDIM) / 256, 256>>>(temp, freqs);

    for (int it = 0; it < 3; it++) {
        gemm_t<64><<<dim3(6, 16), 256>>>(p_xout, q_w, q_b, p_qlin, NB * N_OUT, DM, DM, 0);
        rose_q_kernel<<<(NB * NH * N_OUT * HDIM) / 256, 256>>>(freqs);
        scores_kernel<<<dim3(64, 8, BHTOT), 256>>>(attn_k_out);
        rowsum_kernel<<<NROWS, 32>>>();
        colinv_kernel<<<dim3(16, BHTOT), 256>>>(attn_k_out);
        upd_kernel<<<dim3(16, BHTOT), 256>>>(attn_k_out);
        ln_add_kernel<<<NB * N_OUT, 384>>>(p_upd, g2, b2);
        gemm_t<128><<<dim3(24, 8), 256>>>(p_xout, mlp_w1, mlp_b1, p_mlp, NB * N_OUT, 4 * DM, DM, 1);
        gemm_t<64><<<dim3(6, 16), 256>>>(p_mlp, mlp_w2, mlp_b2, p_mlpo, NB * N_OUT, DM, 4 * DM, 0);
        ln_add_kernel<<<NB * N_OUT, 384>>>(p_mlpo, g3, b3);
    }

    finalize_kernel<<<dim3(16, N_OUT, BHTOT), 256>>>(attn_k_out, attn_q_out);
    copy_xout_kernel<<<XOUT_SZ / 256, 256>>>(out);
}

// round 4
// speedup vs baseline: 1.8191x; 1.0769x over previous
#include <cuda_runtime.h>
#include <cuda_bf16.h>
#include <cuda_fp16.h>
#include <math.h>

// ---------------- problem constants ----------------
#define NB 2
#define N_IN 4096          // 64*64
#define N_OUT 484          // 22*22
#define DM 384
#define NH 12
#define HDIM 32
#define QG 22
#define KCONV 18816        // 49*384
#define BHTOT (NB*NH)      // 24
#define XOUT_SZ (NB*N_OUT*DM)              // 371712
#define ATTN_SZ ((size_t)NB*NH*N_OUT*N_IN) // 47579136
#define NROWS (BHTOT*N_OUT)                // 11616
#define KTILES 64
#define CSPLIT 6
#define CKLEN (KCONV/CSPLIT)               // 3136
#define EPSQ 1.1920929e-07f
#define LN_EPS 1e-5f

// ---------------- scratch (static device memory; no allocations) ----------------
__device__ float g_wt[(size_t)KCONV*DM];
__device__ float g_convpart[(size_t)CSPLIT*XOUT_SZ];
__device__ float g_xout[XOUT_SZ];
__device__ float g_kv[(size_t)NB*N_IN*2*DM];
__device__ float g_k[(size_t)NB*NH*N_IN*HDIM];
__device__ float g_v[(size_t)NB*NH*N_IN*HDIM];
__device__ float g_qlin[XOUT_SZ];
__device__ float g_q[NB*NH*N_OUT*HDIM];
__device__ float g_colinv[BHTOT*N_IN];
__device__ float g_rowpart[(size_t)NROWS*KTILES];
__device__ float g_rinv[NROWS];
__device__ float g_upd[XOUT_SZ];
__device__ float g_mlp[NB*N_OUT*4*DM];
__device__ float g_mlpo[XOUT_SZ];
__device__ __half g_e[ATTN_SZ];            // fp16 exp-score scratch

// ---------------- helpers ----------------
__device__ __forceinline__ float blockSum(float v, float* sred) {
    int tid = threadIdx.x, lane = tid & 31, wid = tid >> 5;
    #pragma unroll
    for (int o = 16; o; o >>= 1) v += __shfl_xor_sync(0xffffffffu, v, o);
    if (lane == 0) sred[wid] = v;
    __syncthreads();
    int nw = (blockDim.x + 31) >> 5;
    if (wid == 0) {
        float t = (lane < nw) ? sred[lane] : 0.f;
        #pragma unroll
        for (int o = 16; o; o >>= 1) t += __shfl_xor_sync(0xffffffffu, t, o);
        if (lane == 0) sred[0] = t;
    }
    __syncthreads();
    float r = sred[0];
    __syncthreads();
    return r;
}

// ---------------- conv weight transpose: (co,ci,t) -> (t,ci,co) ----------------
__global__ __launch_bounds__(256) void wt_transpose_kernel(const float* __restrict__ conv_w) {
    __shared__ float s[32][50];
    int co0 = blockIdx.x * 32;
    int ci = blockIdx.y;
    int tid = threadIdx.x;
    for (int idx = tid; idx < 32 * 49; idx += 256) {
        int r = idx / 49, t = idx - r * 49;
        s[r][t] = conv_w[(size_t)(co0 + r) * KCONV + ci * 49 + t];
    }
    __syncthreads();
    for (int idx = tid; idx < 49 * 32; idx += 256) {
        int t = idx >> 5, c = idx & 31;
        g_wt[((size_t)(t * DM + ci)) * DM + co0 + c] = s[c][t];
    }
}

// ---------------- 128x128 GEMM, 8x8 per-thread tile: C = A@W + bias ----------------
__global__ __launch_bounds__(256) void gemm128_t(const float* __restrict__ A,
                                                 const float* __restrict__ W,
                                                 const float* __restrict__ bias,
                                                 float* __restrict__ C,
                                                 int M, int N, int K, int act) {
    __shared__ float As[16][132];
    __shared__ float Bs[16][128];
    int tid = threadIdx.x, tx = tid & 15, ty = tid >> 4;
    int row0 = blockIdx.y * 128, col0 = blockIdx.x * 128;

    int ar[2], aq[2], br[2], bc[2];
    #pragma unroll
    for (int l = 0; l < 2; l++) {
        int f = tid + l * 256;
        ar[l] = f >> 2; aq[l] = f & 3;
        br[l] = f >> 5; bc[l] = (f & 31) * 4;
    }
    float acc[8][8] = {};
    float4 pa[2], pb[2];

    #pragma unroll
    for (int l = 0; l < 2; l++) {
        int gr = row0 + ar[l];
        pa[l] = (gr < M) ? *reinterpret_cast<const float4*>(&A[(size_t)gr * K + aq[l] * 4])
                         : make_float4(0.f, 0.f, 0.f, 0.f);
        pb[l] = *reinterpret_cast<const float4*>(&W[(size_t)br[l] * N + col0 + bc[l]]);
    }

    for (int k0 = 0;;) {
        #pragma unroll
        for (int l = 0; l < 2; l++) {
            As[aq[l] * 4 + 0][ar[l]] = pa[l].x;
            As[aq[l] * 4 + 1][ar[l]] = pa[l].y;
            As[aq[l] * 4 + 2][ar[l]] = pa[l].z;
            As[aq[l] * 4 + 3][ar[l]] = pa[l].w;
            *reinterpret_cast<float4*>(&Bs[br[l]][bc[l]]) = pb[l];
        }
        __syncthreads();

        int kn = k0 + 16;
        if (kn < K) {
            #pragma unroll
            for (int l = 0; l < 2; l++) {
                int gr = row0 + ar[l];
                pa[l] = (gr < M) ? *reinterpret_cast<const float4*>(&A[(size_t)gr * K + kn + aq[l] * 4])
                                 : make_float4(0.f, 0.f, 0.f, 0.f);
                pb[l] = *reinterpret_cast<const float4*>(&W[(size_t)(kn + br[l]) * N + col0 + bc[l]]);
            }
        }

        #pragma unroll
        for (int kk = 0; kk < 16; kk++) {
            float4 a0 = *reinterpret_cast<const float4*>(&As[kk][ty * 8]);
            float4 a1 = *reinterpret_cast<const float4*>(&As[kk][ty * 8 + 4]);
            float4 b0 = *reinterpret_cast<const float4*>(&Bs[kk][tx * 8]);
            float4 b1 = *reinterpret_cast<const float4*>(&Bs[kk][tx * 8 + 4]);
            float av[8] = {a0.x, a0.y, a0.z, a0.w, a1.x, a1.y, a1.z, a1.w};
            float bv[8] = {b0.x, b0.y, b0.z, b0.w, b1.x, b1.y, b1.z, b1.w};
            #pragma unroll
            for (int i = 0; i < 8; i++)
                #pragma unroll
                for (int j = 0; j < 8; j++) acc[i][j] += av[i] * bv[j];
        }
        k0 = kn;
        if (k0 >= K) break;
        __syncthreads();
    }

    #pragma unroll
    for (int i = 0; i < 8; i++) {
        int gr = row0 + ty * 8 + i;
        if (gr >= M) continue;
        float o[8];
        #pragma unroll
        for (int j = 0; j < 8; j++) {
            float v = acc[i][j] + bias[col0 + tx * 8 + j];
            if (act == 1) v = 0.5f * v * (1.f + erff(v * 0.70710678118654752f));
            o[j] = v;
        }
        *reinterpret_cast<float4*>(&C[(size_t)gr * N + col0 + tx * 8]) =
            make_float4(o[0], o[1], o[2], o[3]);
        *reinterpret_cast<float4*>(&C[(size_t)gr * N + col0 + tx * 8 + 4]) =
            make_float4(o[4], o[5], o[6], o[7]);
    }
}

// ---------------- 64x64 GEMM (small M/N cases) ----------------
__global__ __launch_bounds__(256) void gemm64_t(const float* __restrict__ A,
                                                const float* __restrict__ W,
                                                const float* __restrict__ bias,
                                                float* __restrict__ C,
                                                int M, int N, int K, int act) {
    __shared__ float As[16][64];
    __shared__ float Bs[16][64];
    int tid = threadIdx.x, tx = tid & 15, ty = tid >> 4;
    int row0 = blockIdx.y * 64, col0 = blockIdx.x * 64;
    int ar = tid >> 2, aq = tid & 3;
    int br = tid >> 4, bq = tid & 15;
    float acc[4][4] = {};
    float4 pa, pb;
    {
        int gr = row0 + ar;
        pa = (gr < M) ? *reinterpret_cast<const float4*>(&A[(size_t)gr * K + aq * 4])
                      : make_float4(0.f, 0.f, 0.f, 0.f);
        pb = *reinterpret_cast<const float4*>(&W[(size_t)br * N + col0 + bq * 4]);
    }
    for (int k0 = 0;;) {
        As[aq * 4 + 0][ar] = pa.x;
        As[aq * 4 + 1][ar] = pa.y;
        As[aq * 4 + 2][ar] = pa.z;
        As[aq * 4 + 3][ar] = pa.w;
        *reinterpret_cast<float4*>(&Bs[br][bq * 4]) = pb;
        __syncthreads();
        int kn = k0 + 16;
        if (kn < K) {
            int gr = row0 + ar;
            pa = (gr < M) ? *reinterpret_cast<const float4*>(&A[(size_t)gr * K + kn + aq * 4])
                          : make_float4(0.f, 0.f, 0.f, 0.f);
            pb = *reinterpret_cast<const float4*>(&W[(size_t)(kn + br) * N + col0 + bq * 4]);
        }
        #pragma unroll
        for (int kk = 0; kk < 16; kk++) {
            float4 a4 = *reinterpret_cast<const float4*>(&As[kk][ty * 4]);
            float4 b4 = *reinterpret_cast<const float4*>(&Bs[kk][tx * 4]);
            float av[4] = {a4.x, a4.y, a4.z, a4.w};
            float bv[4] = {b4.x, b4.y, b4.z, b4.w};
            #pragma unroll
            for (int i = 0; i < 4; i++)
                #pragma unroll
                for (int j = 0; j < 4; j++) acc[i][j] += av[i] * bv[j];
        }
        k0 = kn;
        if (k0 >= K) break;
        __syncthreads();
    }
    #pragma unroll
    for (int i = 0; i < 4; i++) {
        int gr = row0 + ty * 4 + i;
        if (gr >= M) continue;
        float o[4];
        #pragma unroll
        for (int j = 0; j < 4; j++) {
            float v = acc[i][j] + bias[col0 + tx * 4 + j];
            if (act == 1) v = 0.5f * v * (1.f + erff(v * 0.70710678118654752f));
            o[j] = v;
        }
        *reinterpret_cast<float4*>(&C[(size_t)gr * N + col0 + tx * 4]) =
            make_float4(o[0], o[1], o[2], o[3]);
    }
}

// ---------------- implicit-GEMM conv, 128x128 tile, split-K=6 ----------------
__global__ __launch_bounds__(256) void conv128_t(const float* __restrict__ x) {
    __shared__ float As[16][132];
    __shared__ float Bs[16][128];
    int tid = threadIdx.x, tx = tid & 15, ty = tid >> 4;
    int row0 = blockIdx.y * 128, col0 = blockIdx.x * 128;
    int kbeg = blockIdx.z * CKLEN, kend = kbeg + CKLEN;

    int ar[2], aq[2], br[2], bc[2], rb[2], roy[2], rox[2];
    bool rv[2];
    #pragma unroll
    for (int l = 0; l < 2; l++) {
        int f = tid + l * 256;
        ar[l] = f >> 2; aq[l] = f & 3;
        br[l] = f >> 5; bc[l] = (f & 31) * 4;
        int gr = row0 + ar[l];
        rv[l] = gr < NB * N_OUT;
        int g2 = rv[l] ? gr : 0;
        rb[l] = g2 / N_OUT;
        int n = g2 - rb[l] * N_OUT;
        roy[l] = n / QG; rox[l] = n - roy[l] * QG;
    }
    float acc[8][8] = {};
    float4 pa[2], pb[2];

    auto ld = [&](int k0) {
        int t = k0 / DM; int ci0 = k0 - t * DM;
        int ky = t / 7, kx = t - ky * 7;
        #pragma unroll
        for (int l = 0; l < 2; l++) {
            int iy = roy[l] * 3 - 3 + ky, ix = rox[l] * 3 - 3 + kx;
            bool ok = rv[l] && (unsigned)iy < 64u && (unsigned)ix < 64u;
            pa[l] = ok ? *reinterpret_cast<const float4*>(
                             &x[((size_t)(rb[l] * N_IN) + iy * 64 + ix) * DM + ci0 + aq[l] * 4])
                       : make_float4(0.f, 0.f, 0.f, 0.f);
            pb[l] = *reinterpret_cast<const float4*>(&g_wt[(size_t)(k0 + br[l]) * DM + col0 + bc[l]]);
        }
    };

    ld(kbeg);
    for (int k0 = kbeg;;) {
        #pragma unroll
        for (int l = 0; l < 2; l++) {
            As[aq[l] * 4 + 0][ar[l]] = pa[l].x;
            As[aq[l] * 4 + 1][ar[l]] = pa[l].y;
            As[aq[l] * 4 + 2][ar[l]] = pa[l].z;
            As[aq[l] * 4 + 3][ar[l]] = pa[l].w;
            *reinterpret_cast<float4*>(&Bs[br[l]][bc[l]]) = pb[l];
        }
        __syncthreads();

        int kn = k0 + 16;
        if (kn < kend) ld(kn);

        #pragma unroll
        for (int kk = 0; kk < 16; kk++) {
            float4 a0 = *reinterpret_cast<const float4*>(&As[kk][ty * 8]);
            float4 a1 = *reinterpret_cast<const float4*>(&As[kk][ty * 8 + 4]);
            float4 b0 = *reinterpret_cast<const float4*>(&Bs[kk][tx * 8]);
            float4 b1 = *reinterpret_cast<const float4*>(&Bs[kk][tx * 8 + 4]);
            float av[8] = {a0.x, a0.y, a0.z, a0.w, a1.x, a1.y, a1.z, a1.w};
            float bv[8] = {b0.x, b0.y, b0.z, b0.w, b1.x, b1.y, b1.z, b1.w};
            #pragma unroll
            for (int i = 0; i < 8; i++)
                #pragma unroll
                for (int j = 0; j < 8; j++) acc[i][j] += av[i] * bv[j];
        }
        k0 = kn;
        if (k0 >= kend) break;
        __syncthreads();
    }

    #pragma unroll
    for (int i = 0; i < 8; i++) {
        int gr = row0 + ty * 8 + i;
        if (gr < NB * N_OUT) {
            *reinterpret_cast<float4*>(
                &g_convpart[(size_t)blockIdx.z * XOUT_SZ + gr * DM + col0 + tx * 8]) =
                make_float4(acc[i][0], acc[i][1], acc[i][2], acc[i][3]);
            *reinterpret_cast<float4*>(
                &g_convpart[(size_t)blockIdx.z * XOUT_SZ + gr * DM + col0 + tx * 8 + 4]) =
                make_float4(acc[i][4], acc[i][5], acc[i][6], acc[i][7]);
        }
    }
}

// ---------------- conv partial reduce + bias + LN -> g_xout ----------------
__global__ __launch_bounds__(384) void conv_ln_kernel(const float* __restrict__ cb,
                                                      const float* __restrict__ g,
                                                      const float* __restrict__ b) {
    __shared__ float sred[32];
    int row = blockIdx.x, tid = threadIdx.x;
    float v = cb[tid];
    #pragma unroll
    for (int s = 0; s < CSPLIT; s++) v += g_convpart[(size_t)s * XOUT_SZ + row * DM + tid];
    float mu = blockSum(v, sred) * (1.f / DM);
    float d = v - mu;
    float var = blockSum(d * d, sred) * (1.f / DM);
    float rs = rsqrtf(var + LN_EPS);
    g_xout[row * DM + tid] = d * rs * g[tid] + b[tid];
}

// ---------------- rose for K (+ V split) ----------------
__global__ __launch_bounds__(256) void rose_kv_kernel(const float* __restrict__ temp,
                                                      const float* __restrict__ freqs) {
    int idx = blockIdx.x * 256 + threadIdx.x;
    int d = idx & 31;
    int t = idx >> 5;
    int n = t & (N_IN - 1);
    int bh = t >> 12;
    int h = bh % NH;
    int b = bh / NH;
    const float* src = g_kv + ((size_t)(b * N_IN + n)) * (2 * DM) + h * HDIM;
    float tv = temp[0];
    float val;
    if (d < 16) {
        int j = d >> 1;
        int s = j >> 2, p = j & 3;
        float coord = (s == 0) ? (float)(n >> 6) : (float)(n & 63);
        float ang = coord * freqs[(h * 2 + s) * 4 + p];
        float sn, cs;
        sincosf(ang, &sn, &cs);
        float x1 = src[j * 2], x2 = src[j * 2 + 1];
        val = (d & 1) ? (x1 * sn + x2 * cs) : (x1 * cs - x2 * sn);
    } else {
        val = src[d];
    }
    g_k[idx] = tv * val;
    g_v[idx] = src[DM + d];
}

// ---------------- rose for Q ----------------
__global__ __launch_bounds__(256) void rose_q_kernel(const float* __restrict__ freqs) {
    int idx = blockIdx.x * 256 + threadIdx.x;
    int d = idx & 31;
    int t = idx >> 5;
    int n = t % N_OUT;
    int bh = t / N_OUT;
    int h = bh % NH;
    int b = bh / NH;
    const float* src = g_qlin + ((size_t)(b * N_OUT + n)) * DM + h * HDIM;
    float val;
    if (d < 16) {
        int j = d >> 1;
        int s = j >> 2, p = j & 3;
        float coord = (s == 0) ? (float)(n / QG) * 3.0f : (float)(n % QG) * 3.0f;
        float ang = coord * freqs[(h * 2 + s) * 4 + p];
        float sn, cs;
        sincosf(ang, &sn, &cs);
        float x1 = src[j * 2], x2 = src[j * 2 + 1];
        val = (d & 1) ? (x1 * sn + x2 * cs) : (x1 * cs - x2 * sn);
    } else {
        val = src[d];
    }
    g_q[idx] = val;
}

// ---------------- scores: e = exp(q.k) stored fp16 + partial row sums ----------------
__global__ __launch_bounds__(256) void scores_kernel() {
    __shared__ float Qs[32][65];
    __shared__ float Ks[32][65];
    int bh = blockIdx.z;
    const float* Aq = g_q + (size_t)bh * N_OUT * HDIM;
    const float* Bk = g_k + (size_t)bh * N_IN * HDIM;
    __half* Ep = g_e + (size_t)bh * N_OUT * N_IN;
    int row0 = blockIdx.y * 64, col0 = blockIdx.x * 64;
    int tid = threadIdx.x;
    int ty = tid >> 4, tx = tid & 15;
    #pragma unroll
    for (int it = 0; it < 8; it++) {
        int r = it * 8 + (tid >> 5);
        int c = tid & 31;
        Qs[c][r] = (row0 + r < N_OUT) ? Aq[(row0 + r) * HDIM + c] : 0.f;
        Ks[c][r] = Bk[(size_t)(col0 + r) * HDIM + c];
    }
    __syncthreads();
    float acc[4][4] = {};
    #pragma unroll
    for (int kk = 0; kk < 32; kk++) {
        float a[4], b[4];
        #pragma unroll
        for (int i = 0; i < 4; i++) a[i] = Qs[kk][ty * 4 + i];
        #pragma unroll
        for (int j = 0; j < 4; j++) b[j] = Ks[kk][tx * 4 + j];
        #pragma unroll
        for (int i = 0; i < 4; i++)
            #pragma unroll
            for (int j = 0; j < 4; j++) acc[i][j] += a[i] * b[j];
    }
    #pragma unroll
    for (int i = 0; i < 4; i++) {
        int gr = row0 + ty * 4 + i;
        float e0 = expf(acc[i][0]), e1 = expf(acc[i][1]);
        float e2 = expf(acc[i][2]), e3 = expf(acc[i][3]);
        float s = (e0 + e1) + (e2 + e3);
        #pragma unroll
        for (int o = 1; o < 16; o <<= 1) s += __shfl_xor_sync(0xffffffffu, s, o);
        if (gr < N_OUT) {
            __half2* dst = reinterpret_cast<__half2*>(&Ep[(size_t)gr * N_IN + col0 + tx * 4]);
            dst[0] = __floats2half2_rn(e0, e1);
            dst[1] = __floats2half2_rn(e2, e3);
            if (tx == 0)
                g_rowpart[(size_t)(bh * N_OUT + gr) * KTILES + blockIdx.x] = s;
        }
    }
}

// ---------------- reduce row partials -> rinv = 1/rowsum ----------------
__global__ __launch_bounds__(32) void rowsum_kernel() {
    int row = blockIdx.x, lane = threadIdx.x;
    const float* p = g_rowpart + (size_t)row * KTILES;
    float v = p[lane] + p[lane + 32];
    #pragma unroll
    for (int o = 16; o; o >>= 1) v += __shfl_xor_sync(0xffffffffu, v, o);
    if (lane == 0) g_rinv[row] = 1.f / v;
}

// ---------------- colinv: 1/(sum_q e[q,k]*rinv[q] + EPS), 2 cols/thread ----------------
__global__ __launch_bounds__(256) void colinv_kernel() {
    int bh = blockIdx.y;
    int k2 = blockIdx.x * 256 + threadIdx.x;  // half2 index, 0..2047
    const __half2* p = reinterpret_cast<const __half2*>(g_e + (size_t)bh * N_OUT * N_IN) + k2;
    const float* ri = g_rinv + bh * N_OUT;
    float sx = 0.f, sy = 0.f;
    #pragma unroll 4
    for (int q = 0; q < N_OUT; q++) {
        float2 e = __half22float2(p[(size_t)q * (N_IN / 2)]);
        float r = ri[q];
        sx += e.x * r;
        sy += e.y * r;
    }
    g_colinv[bh * N_IN + k2 * 2]     = 1.f / (sx + EPSQ);
    g_colinv[bh * N_IN + k2 * 2 + 1] = 1.f / (sy + EPSQ);
}

// ---------------- upd = rinv[q] * sum_k e[q,k]*colinv[k]*v[k,d] ----------------
__global__ __launch_bounds__(256) void upd_kernel() {
    __shared__ float As[32][128];
    __shared__ float Vs[128][33];
    int bh = blockIdx.y;
    int b = bh / NH, h = bh - b * NH;
    int q0 = blockIdx.x * 32;
    int tid = threadIdx.x;
    int qi = tid >> 5, d = tid & 31;
    const __half* Ap = g_e + (size_t)bh * N_OUT * N_IN;
    const float* Vp = g_v + (size_t)bh * N_IN * HDIM;
    const float* Ci = g_colinv + bh * N_IN;
    float acc[4] = {0.f, 0.f, 0.f, 0.f};
    for (int kt = 0; kt < N_IN; kt += 128) {
        #pragma unroll
        for (int it = 0; it < 8; it++) {
            int f = it * 256 + tid;            // 2048 half2 loads
            int r = f >> 6, c2 = (f & 63) * 2;
            int q = q0 + r;
            float2 e = (q < N_OUT)
                ? __half22float2(*reinterpret_cast<const __half2*>(&Ap[(size_t)q * N_IN + kt + c2]))
                : make_float2(0.f, 0.f);
            As[r][c2] = e.x;
            As[r][c2 + 1] = e.y;
        }
        #pragma unroll
        for (int it = 0; it < 16; it++) {
            int idx = it * 256 + tid;
            int kk = idx >> 5, c = idx & 31;
            Vs[kk][c] = Vp[(size_t)(kt + kk) * HDIM + c] * __ldg(&Ci[kt + kk]);
        }
        __syncthreads();
        #pragma unroll 8
        for (int kk = 0; kk < 128; kk++) {
            float vv = Vs[kk][d];
            acc[0] += As[qi][kk] * vv;
            acc[1] += As[qi + 8][kk] * vv;
            acc[2] += As[qi + 16][kk] * vv;
            acc[3] += As[qi + 24][kk] * vv;
        }
        __syncthreads();
    }
    #pragma unroll
    for (int i = 0; i < 4; i++) {
        int q = q0 + qi + i * 8;
        if (q < N_OUT) {
            float rq = g_rinv[bh * N_OUT + q];
            g_upd[((size_t)(b * N_OUT) + q) * DM + h * HDIM + d] = acc[i] * rq;
        }
    }
}

// ---------------- x_out += LN(src)*g + b ----------------
__global__ __launch_bounds__(384) void ln_add_kernel(const float* __restrict__ src,
                                                     const float* __restrict__ g,
                                                     const float* __restrict__ b) {
    __shared__ float sred[32];
    int row = blockIdx.x, tid = threadIdx.x;
    float v = src[row * DM + tid];
    float mu = blockSum(v, sred) * (1.f / DM);
    float d = v - mu;
    float var = blockSum(d * d, sred) * (1.f / DM);
    float rs = rsqrtf(var + LN_EPS);
    g_xout[row * DM + tid] += d * rs * g[tid] + b[tid];
}

// ---------------- finalize: attn_k = e*rinv ; attn_q = attn_k*colinv ----------------
__global__ __launch_bounds__(256) void finalize_kernel(float* __restrict__ attn_k,
                                                       float* __restrict__ attn_q) {
    int bh = blockIdx.z, q = blockIdx.y;
    int k4 = (blockIdx.x * 256 + threadIdx.x) * 4;
    size_t i = ((size_t)(bh * N_OUT + q) << 12) + k4;
    float r = g_rinv[bh * N_OUT + q];
    const __half2* ep = reinterpret_cast<const __half2*>(&g_e[i]);
    float2 e01 = __half22float2(ep[0]);
    float2 e23 = __half22float2(ep[1]);
    float4 ci = *reinterpret_cast<const float4*>(&g_colinv[bh * N_IN + k4]);
    float ak0 = e01.x * r, ak1 = e01.y * r, ak2 = e23.x * r, ak3 = e23.y * r;
    *reinterpret_cast<float4*>(&attn_k[i]) = make_float4(ak0, ak1, ak2, ak3);
    *reinterpret_cast<float4*>(&attn_q[i]) =
        make_float4(ak0 * ci.x, ak1 * ci.y, ak2 * ci.z, ak3 * ci.w);
}

// ---------------- copy x_out to d_out ----------------
__global__ __launch_bounds__(256) void copy_xout_kernel(float* __restrict__ out) {
    int i = blockIdx.x * 256 + threadIdx.x;
    out[i] = g_xout[i];
}

// ---------------- launch ----------------
extern "C" void kernel_launch(void* const* d_in, const int* in_sizes, int n_in,
                              void* d_out, int out_size) {
    const float* x      = (const float*)d_in[0];
    const float* conv_w = (const float*)d_in[1];
    const float* conv_b = (const float*)d_in[2];
    const float* kv_w   = (const float*)d_in[3];
    const float* kv_b   = (const float*)d_in[4];
    const float* q_w    = (const float*)d_in[5];
    const float* q_b    = (const float*)d_in[6];
    const float* mlp_w1 = (const float*)d_in[7];
    const float* mlp_b1 = (const float*)d_in[8];
    const float* mlp_w2 = (const float*)d_in[9];
    const float* mlp_b2 = (const float*)d_in[10];
    const float* g1     = (const float*)d_in[11];
    const float* b1     = (const float*)d_in[12];
    const float* g2     = (const float*)d_in[13];
    const float* b2     = (const float*)d_in[14];
    const float* g3     = (const float*)d_in[15];
    const float* b3     = (const float*)d_in[16];
    const float* temp   = (const float*)d_in[17];
    const float* freqs  = (const float*)d_in[18];

    float* out = (float*)d_out;
    float* attn_q_out = out + XOUT_SZ;
    float* attn_k_out = out + XOUT_SZ + ATTN_SZ;

    void *p_kv_, *p_xout_, *p_qlin_, *p_mlp_, *p_mlpo_, *p_upd_;
    cudaGetSymbolAddress(&p_kv_, g_kv);
    cudaGetSymbolAddress(&p_xout_, g_xout);
    cudaGetSymbolAddress(&p_qlin_, g_qlin);
    cudaGetSymbolAddress(&p_mlp_, g_mlp);
    cudaGetSymbolAddress(&p_mlpo_, g_mlpo);
    cudaGetSymbolAddress(&p_upd_, g_upd);
    float* p_kv   = (float*)p_kv_;
    float* p_xout = (float*)p_xout_;
    float* p_qlin = (float*)p_qlin_;
    float* p_mlp  = (float*)p_mlp_;
    float* p_mlpo = (float*)p_mlpo_;
    float* p_upd  = (float*)p_upd_;

    // one-time preprocessing
    wt_transpose_kernel<<<dim3(12, 384), 256>>>(conv_w);
    conv128_t<<<dim3(3, 8, CSPLIT), 256>>>(x);
    conv_ln_kernel<<<NB * N_OUT, 384>>>(conv_b, g1, b1);

    // loop-invariant kv / k / v
    gemm128_t<<<dim3(6, 64), 256>>>(x, kv_w, kv_b, p_kv, NB * N_IN, 2 * DM, DM, 0);
    rose_kv_kernel<<<(NB * NH * N_IN * HDIM) / 256, 256>>>(temp, freqs);

    for (int it = 0; it < 3; it++) {
        gemm64_t<<<dim3(6, 16), 256>>>(p_xout, q_w, q_b, p_qlin, NB * N_OUT, DM, DM, 0);
        rose_q_kernel<<<(NB * NH * N_OUT * HDIM) / 256, 256>>>(freqs);
        scores_kernel<<<dim3(64, 8, BHTOT), 256>>>();
        rowsum_kernel<<<NROWS, 32>>>();
        colinv_kernel<<<dim3(8, BHTOT), 256>>>();
        upd_kernel<<<dim3(16, BHTOT), 256>>>();
        ln_add_kernel<<<NB * N_OUT, 384>>>(p_upd, g2, b2);
        gemm128_t<<<dim3(12, 8), 256>>>(p_xout, mlp_w1, mlp_b1, p_mlp, NB * N_OUT, 4 * DM, DM, 1);
        gemm64_t<<<dim3(6, 16), 256>>>(p_mlp, mlp_w2, mlp_b2, p_mlpo, NB * N_OUT, DM, 4 * DM, 0);
        ln_add_kernel<<<NB * N_OUT, 384>>>(p_mlpo, g3, b3);
    }

    finalize_kernel<<<dim3(4, N_OUT, BHTOT), 256>>>(attn_k_out, attn_q_out);
    copy_xout_kernel<<<XOUT_SZ / 256, 256>>>(out);
}

// round 7
// speedup vs baseline: 2.5678x; 1.4116x over previous
#include <cuda_runtime.h>
#include <cuda_bf16.h>
#include <cuda_fp16.h>
#include <math.h>

// ---------------- problem constants ----------------
#define NB 2
#define N_IN 4096          // 64*64
#define N_OUT 484          // 22*22
#define DM 384
#define NH 12
#define HDIM 32
#define QG 22
#define KCONV 18816        // 49*384
#define BHTOT (NB*NH)      // 24
#define XOUT_SZ (NB*N_OUT*DM)              // 371712
#define ATTN_SZ ((size_t)NB*NH*N_OUT*N_IN) // 47579136
#define NROWS (BHTOT*N_OUT)                // 11616
#define KTILES 64
#define CSPLIT 6
#define CKLEN (KCONV/CSPLIT)               // 3136
#define EPSQ 1.1920929e-07f
#define LN_EPS 1e-5f

#define LDA 40             // As row stride (halves), conflict-free for ldmatrix
#define LDB 136            // Bs row stride (halves)

// ---------------- scratch (static device memory; no allocations) ----------------
__device__ __half g_wt_h[(size_t)KCONV*DM];     // transposed conv weights, half
__device__ __half g_kvw_h[DM*2*DM];
__device__ __half g_qw_h[DM*DM];
__device__ __half g_w1_h[DM*4*DM];
__device__ __half g_w2_h[4*DM*DM];
__device__ float g_convpart[(size_t)CSPLIT*XOUT_SZ];
__device__ float g_xout[XOUT_SZ];
__device__ float g_kv[(size_t)NB*N_IN*2*DM];
__device__ float g_k[(size_t)NB*NH*N_IN*HDIM];
__device__ float g_v[(size_t)NB*NH*N_IN*HDIM];
__device__ float g_qlin[XOUT_SZ];
__device__ float g_q[NB*NH*N_OUT*HDIM];
__device__ float g_colinv[BHTOT*N_IN];
__device__ float g_rowpart[(size_t)NROWS*KTILES];
__device__ float g_rinv[NROWS];
__device__ float g_upd[XOUT_SZ];
__device__ float g_mlp[NB*N_OUT*4*DM];
__device__ float g_mlpo[XOUT_SZ];
__device__ __half g_e[ATTN_SZ];            // fp16 exp-score scratch

// ---------------- mma / ldmatrix helpers ----------------
__device__ __forceinline__ unsigned smem_u32(const void* p) {
    return (unsigned)__cvta_generic_to_shared(p);
}
__device__ __forceinline__ void ldsm4(unsigned* r, unsigned addr) {
    asm volatile("ldmatrix.sync.aligned.m8n8.x4.shared.b16 {%0,%1,%2,%3}, [%4];"
        : "=r"(r[0]), "=r"(r[1]), "=r"(r[2]), "=r"(r[3]) : "r"(addr));
}
__device__ __forceinline__ void ldsm2t(unsigned* r, unsigned addr) {
    asm volatile("ldmatrix.sync.aligned.m8n8.x2.trans.shared.b16 {%0,%1}, [%2];"
        : "=r"(r[0]), "=r"(r[1]) : "r"(addr));
}
__device__ __forceinline__ void mma16816(float* c, const unsigned* a, const unsigned* b) {
    asm volatile("mma.sync.aligned.m16n8k16.row.col.f32.f16.f16.f32 "
        "{%0,%1,%2,%3}, {%4,%5,%6,%7}, {%8,%9}, {%0,%1,%2,%3};"
        : "+f"(c[0]), "+f"(c[1]), "+f"(c[2]), "+f"(c[3])
        : "r"(a[0]), "r"(a[1]), "r"(a[2]), "r"(a[3]), "r"(b[0]), "r"(b[1]));
}

__device__ __forceinline__ float blockSum(float v, float* sred) {
    int tid = threadIdx.x, lane = tid & 31, wid = tid >> 5;
    #pragma unroll
    for (int o = 16; o; o >>= 1) v += __shfl_xor_sync(0xffffffffu, v, o);
    if (lane == 0) sred[wid] = v;
    __syncthreads();
    int nw = (blockDim.x + 31) >> 5;
    if (wid == 0) {
        float t = (lane < nw) ? sred[lane] : 0.f;
        #pragma unroll
        for (int o = 16; o; o >>= 1) t += __shfl_xor_sync(0xffffffffu, t, o);
        if (lane == 0) sred[0] = t;
    }
    __syncthreads();
    float r = sred[0];
    __syncthreads();
    return r;
}

// ---------------- weight fp32 -> fp16 ----------------
__global__ __launch_bounds__(256) void f2h_kernel(const float4* __restrict__ src,
                                                  __half2* __restrict__ dst, int n4) {
    int i = blockIdx.x * 256 + threadIdx.x;
    if (i < n4) {
        float4 v = src[i];
        dst[2 * i]     = __floats2half2_rn(v.x, v.y);
        dst[2 * i + 1] = __floats2half2_rn(v.z, v.w);
    }
}

// ---------------- conv weight transpose: (co,ci,t) -> (t,ci,co), fp16 out ----------------
__global__ __launch_bounds__(256) void wt_transpose_kernel(const float* __restrict__ conv_w) {
    __shared__ float s[32][50];
    int co0 = blockIdx.x * 32;
    int ci = blockIdx.y;
    int tid = threadIdx.x;
    for (int idx = tid; idx < 32 * 49; idx += 256) {
        int r = idx / 49, t = idx - r * 49;
        s[r][t] = conv_w[(size_t)(co0 + r) * KCONV + ci * 49 + t];
    }
    __syncthreads();
    for (int idx = tid; idx < 49 * 32; idx += 256) {
        int t = idx >> 5, c = idx & 31;
        g_wt_h[((size_t)(t * DM + ci)) * DM + co0 + c] = __float2half(s[c][t]);
    }
}

// ---------------- fp16 tensor-core GEMM: C = A@W + bias (act=1 -> exact gelu) ----------------
// 128x128 tile, BK=32, 256 threads (8 warps in 2x4), m16n8k16 HMMA, fp32 accum.
__global__ __launch_bounds__(256) void gemm_mma(const float* __restrict__ A,
                                                const __half* __restrict__ W,
                                                const float* __restrict__ bias,
                                                float* __restrict__ C,
                                                int M, int N, int K, int act) {
    __shared__ __half As[128 * LDA];
    __shared__ __half Bs[32 * LDB];
    int tid = threadIdx.x, lane = tid & 31, warp = tid >> 5;
    int wm = warp >> 2, wn = warp & 3;
    int row0 = blockIdx.y * 128, col0 = blockIdx.x * 128;

    int arow = tid >> 1, acb = (tid & 1) * 16;
    int agrow = row0 + arow;
    bool aval = agrow < M;
    const float* Aptr = A + (size_t)(aval ? agrow : 0) * K + acb;

    int brow[2], bseg[2];
    #pragma unroll
    for (int l = 0; l < 2; l++) { int f = tid + l * 256; brow[l] = f >> 4; bseg[l] = f & 15; }

    float acc[4][4][4] = {};
    float4 pa[4]; uint4 pw[2];

    auto ldGA = [&](int k0) {
        #pragma unroll
        for (int j = 0; j < 4; j++)
            pa[j] = aval ? *reinterpret_cast<const float4*>(Aptr + k0 + j * 4)
                         : make_float4(0.f, 0.f, 0.f, 0.f);
    };
    auto ldGB = [&](int k0) {
        #pragma unroll
        for (int l = 0; l < 2; l++)
            pw[l] = *reinterpret_cast<const uint4*>(&W[(size_t)(k0 + brow[l]) * N + col0 + bseg[l] * 8]);
    };
    auto stS = [&]() {
        __half2 h[8];
        #pragma unroll
        for (int j = 0; j < 4; j++) {
            h[2 * j]     = __floats2half2_rn(pa[j].x, pa[j].y);
            h[2 * j + 1] = __floats2half2_rn(pa[j].z, pa[j].w);
        }
        *reinterpret_cast<uint4*>(&As[arow * LDA + acb])     = *reinterpret_cast<uint4*>(&h[0]);
        *reinterpret_cast<uint4*>(&As[arow * LDA + acb + 8]) = *reinterpret_cast<uint4*>(&h[4]);
        #pragma unroll
        for (int l = 0; l < 2; l++)
            *reinterpret_cast<uint4*>(&Bs[brow[l] * LDB + bseg[l] * 8]) = pw[l];
    };

    unsigned aaddr[4], baddr[4];
    #pragma unroll
    for (int mt = 0; mt < 4; mt++)
        aaddr[mt] = smem_u32(&As[(wm * 64 + mt * 16 + (lane & 15)) * LDA + (lane >> 4) * 8]);
    #pragma unroll
    for (int nt = 0; nt < 4; nt++)
        baddr[nt] = smem_u32(&Bs[(lane & 15) * LDB + wn * 32 + nt * 8]);

    ldGA(0); ldGB(0);
    for (int k0 = 0;;) {
        stS();
        __syncthreads();
        int kn = k0 + 32;
        if (kn < K) { ldGA(kn); ldGB(kn); }
        #pragma unroll
        for (int ks = 0; ks < 2; ks++) {
            unsigned af[4][4], bf[4][2];
            #pragma unroll
            for (int mt = 0; mt < 4; mt++) ldsm4(af[mt], aaddr[mt] + ks * 32);
            #pragma unroll
            for (int nt = 0; nt < 4; nt++) ldsm2t(bf[nt], baddr[nt] + ks * 16 * LDB * 2);
            #pragma unroll
            for (int mt = 0; mt < 4; mt++)
                #pragma unroll
                for (int nt = 0; nt < 4; nt++) mma16816(acc[mt][nt], af[mt], bf[nt]);
        }
        k0 = kn;
        if (k0 >= K) break;
        __syncthreads();
    }

    int g = lane >> 2, tig = lane & 3;
    #pragma unroll
    for (int mt = 0; mt < 4; mt++) {
        #pragma unroll
        for (int nt = 0; nt < 4; nt++) {
            int r = row0 + wm * 64 + mt * 16 + g;
            int c = col0 + wn * 32 + nt * 8 + tig * 2;
            float b0 = bias[c], b1 = bias[c + 1];
            if (r < M) {
                float v0 = acc[mt][nt][0] + b0, v1 = acc[mt][nt][1] + b1;
                if (act == 1) {
                    v0 = 0.5f * v0 * (1.f + erff(v0 * 0.70710678118654752f));
                    v1 = 0.5f * v1 * (1.f + erff(v1 * 0.70710678118654752f));
                }
                *reinterpret_cast<float2*>(&C[(size_t)r * N + c]) = make_float2(v0, v1);
            }
            if (r + 8 < M) {
                float v2 = acc[mt][nt][2] + b0, v3 = acc[mt][nt][3] + b1;
                if (act == 1) {
                    v2 = 0.5f * v2 * (1.f + erff(v2 * 0.70710678118654752f));
                    v3 = 0.5f * v3 * (1.f + erff(v3 * 0.70710678118654752f));
                }
                *reinterpret_cast<float2*>(&C[(size_t)(r + 8) * N + c]) = make_float2(v2, v3);
            }
        }
    }
}

// ---------------- implicit-GEMM conv with HMMA, split-K=6, fp32 partials ----------------
__global__ __launch_bounds__(256) void conv_mma(const float* __restrict__ x) {
    __shared__ __half As[128 * LDA];
    __shared__ __half Bs[32 * LDB];
    int tid = threadIdx.x, lane = tid & 31, warp = tid >> 5;
    int wm = warp >> 2, wn = warp & 3;
    int row0 = blockIdx.y * 128, col0 = blockIdx.x * 128;
    int kbeg = blockIdx.z * CKLEN, kend = kbeg + CKLEN;

    int arow = tid >> 1, acb = (tid & 1) * 16;
    int agrow = row0 + arow;
    bool aval = agrow < NB * N_OUT;
    int g2 = aval ? agrow : 0;
    int rb = g2 / N_OUT;
    int nn = g2 - rb * N_OUT;
    int oy = nn / QG, ox = nn - oy * QG;

    int brow[2], bseg[2];
    #pragma unroll
    for (int l = 0; l < 2; l++) { int f = tid + l * 256; brow[l] = f >> 4; bseg[l] = f & 15; }

    float acc[4][4][4] = {};
    float4 pa[4]; uint4 pw[2];

    auto ldGA = [&](int k0) {
        int kk = k0 + acb;
        int t = kk / DM, ci = kk - t * DM;
        int ky = t / 7, kx = t - ky * 7;
        int iy = oy * 3 - 3 + ky, ix = ox * 3 - 3 + kx;
        bool ok = aval && (unsigned)iy < 64u && (unsigned)ix < 64u;
        const float* p = x + ((size_t)(rb * N_IN) + iy * 64 + ix) * DM + ci;
        #pragma unroll
        for (int j = 0; j < 4; j++)
            pa[j] = ok ? *reinterpret_cast<const float4*>(p + j * 4)
                       : make_float4(0.f, 0.f, 0.f, 0.f);
    };
    auto ldGB = [&](int k0) {
        #pragma unroll
        for (int l = 0; l < 2; l++)
            pw[l] = *reinterpret_cast<const uint4*>(&g_wt_h[(size_t)(k0 + brow[l]) * DM + col0 + bseg[l] * 8]);
    };
    auto stS = [&]() {
        __half2 h[8];
        #pragma unroll
        for (int j = 0; j < 4; j++) {
            h[2 * j]     = __floats2half2_rn(pa[j].x, pa[j].y);
            h[2 * j + 1] = __floats2half2_rn(pa[j].z, pa[j].w);
        }
        *reinterpret_cast<uint4*>(&As[arow * LDA + acb])     = *reinterpret_cast<uint4*>(&h[0]);
        *reinterpret_cast<uint4*>(&As[arow * LDA + acb + 8]) = *reinterpret_cast<uint4*>(&h[4]);
        #pragma unroll
        for (int l = 0; l < 2; l++)
            *reinterpret_cast<uint4*>(&Bs[brow[l] * LDB + bseg[l] * 8]) = pw[l];
    };

    unsigned aaddr[4], baddr[4];
    #pragma unroll
    for (int mt = 0; mt < 4; mt++)
        aaddr[mt] = smem_u32(&As[(wm * 64 + mt * 16 + (lane & 15)) * LDA + (lane >> 4) * 8]);
    #pragma unroll
    for (int nt = 0; nt < 4; nt++)
        baddr[nt] = smem_u32(&Bs[(lane & 15) * LDB + wn * 32 + nt * 8]);

    ldGA(kbeg); ldGB(kbeg);
    for (int k0 = kbeg;;) {
        stS();
        __syncthreads();
        int kn = k0 + 32;
        if (kn < kend) { ldGA(kn); ldGB(kn); }
        #pragma unroll
        for (int ks = 0; ks < 2; ks++) {
            unsigned af[4][4], bf[4][2];
            #pragma unroll
            for (int mt = 0; mt < 4; mt++) ldsm4(af[mt], aaddr[mt] + ks * 32);
            #pragma unroll
            for (int nt = 0; nt < 4; nt++) ldsm2t(bf[nt], baddr[nt] + ks * 16 * LDB * 2);
            #pragma unroll
            for (int mt = 0; mt < 4; mt++)
                #pragma unroll
                for (int nt = 0; nt < 4; nt++) mma16816(acc[mt][nt], af[mt], bf[nt]);
        }
        k0 = kn;
        if (k0 >= kend) break;
        __syncthreads();
    }

    float* out = g_convpart + (size_t)blockIdx.z * XOUT_SZ;
    int g = lane >> 2, tig = lane & 3;
    #pragma unroll
    for (int mt = 0; mt < 4; mt++) {
        #pragma unroll
        for (int nt = 0; nt < 4; nt++) {
            int r = row0 + wm * 64 + mt * 16 + g;
            int c = col0 + wn * 32 + nt * 8 + tig * 2;
            if (r < NB * N_OUT)
                *reinterpret_cast<float2*>(&out[(size_t)r * DM + c]) =
                    make_float2(acc[mt][nt][0], acc[mt][nt][1]);
            if (r + 8 < NB * N_OUT)
                *reinterpret_cast<float2*>(&out[(size_t)(r + 8) * DM + c]) =
                    make_float2(acc[mt][nt][2], acc[mt][nt][3]);
        }
    }
}

// ---------------- conv partial reduce + bias + LN -> g_xout ----------------
__global__ __launch_bounds__(384) void conv_ln_kernel(const float* __restrict__ cb,
                                                      const float* __restrict__ g,
                                                      const float* __restrict__ b) {
    __shared__ float sred[32];
    int row = blockIdx.x, tid = threadIdx.x;
    float v = cb[tid];
    #pragma unroll
    for (int s = 0; s < CSPLIT; s++) v += g_convpart[(size_t)s * XOUT_SZ + row * DM + tid];
    float mu = blockSum(v, sred) * (1.f / DM);
    float d = v - mu;
    float var = blockSum(d * d, sred) * (1.f / DM);
    float rs = rsqrtf(var + LN_EPS);
    g_xout[row * DM + tid] = d * rs * g[tid] + b[tid];
}

// ---------------- rose for K (+ V split) ----------------
__global__ __launch_bounds__(256) void rose_kv_kernel(const float* __restrict__ temp,
                                                      const float* __restrict__ freqs) {
    int idx = blockIdx.x * 256 + threadIdx.x;
    int d = idx & 31;
    int t = idx >> 5;
    int n = t & (N_IN - 1);
    int bh = t >> 12;
    int h = bh % NH;
    int b = bh / NH;
    const float* src = g_kv + ((size_t)(b * N_IN + n)) * (2 * DM) + h * HDIM;
    float tv = temp[0];
    float val;
    if (d < 16) {
        int j = d >> 1;
        int s = j >> 2, p = j & 3;
        float coord = (s == 0) ? (float)(n >> 6) : (float)(n & 63);
        float ang = coord * freqs[(h * 2 + s) * 4 + p];
        float sn, cs;
        sincosf(ang, &sn, &cs);
        float x1 = src[j * 2], x2 = src[j * 2 + 1];
        val = (d & 1) ? (x1 * sn + x2 * cs) : (x1 * cs - x2 * sn);
    } else {
        val = src[d];
    }
    g_k[idx] = tv * val;
    g_v[idx] = src[DM + d];
}

// ---------------- rose for Q ----------------
__global__ __launch_bounds__(256) void rose_q_kernel(const float* __restrict__ freqs) {
    int idx = blockIdx.x * 256 + threadIdx.x;
    int d = idx & 31;
    int t = idx >> 5;
    int n = t % N_OUT;
    int bh = t / N_OUT;
    int h = bh % NH;
    int b = bh / NH;
    const float* src = g_qlin + ((size_t)(b * N_OUT + n)) * DM + h * HDIM;
    float val;
    if (d < 16) {
        int j = d >> 1;
        int s = j >> 2, p = j & 3;
        float coord = (s == 0) ? (float)(n / QG) * 3.0f : (float)(n % QG) * 3.0f;
        float ang = coord * freqs[(h * 2 + s) * 4 + p];
        float sn, cs;
        sincosf(ang, &sn, &cs);
        float x1 = src[j * 2], x2 = src[j * 2 + 1];
        val = (d & 1) ? (x1 * sn + x2 * cs) : (x1 * cs - x2 * sn);
    } else {
        val = src[d];
    }
    g_q[idx] = val;
}

// ---------------- scores: e = exp(q.k) stored fp16 + partial row sums ----------------
__global__ __launch_bounds__(256) void scores_kernel() {
    __shared__ float Qs[32][65];
    __shared__ float Ks[32][65];
    int bh = blockIdx.z;
    const float* Aq = g_q + (size_t)bh * N_OUT * HDIM;
    const float* Bk = g_k + (size_t)bh * N_IN * HDIM;
    __half* Ep = g_e + (size_t)bh * N_OUT * N_IN;
    int row0 = blockIdx.y * 64, col0 = blockIdx.x * 64;
    int tid = threadIdx.x;
    int ty = tid >> 4, tx = tid & 15;
    #pragma unroll
    for (int it = 0; it < 8; it++) {
        int r = it * 8 + (tid >> 5);
        int c = tid & 31;
        Qs[c][r] = (row0 + r < N_OUT) ? Aq[(row0 + r) * HDIM + c] : 0.f;
        Ks[c][r] = Bk[(size_t)(col0 + r) * HDIM + c];
    }
    __syncthreads();
    float acc[4][4] = {};
    #pragma unroll
    for (int kk = 0; kk < 32; kk++) {
        float a[4], b[4];
        #pragma unroll
        for (int i = 0; i < 4; i++) a[i] = Qs[kk][ty * 4 + i];
        #pragma unroll
        for (int j = 0; j < 4; j++) b[j] = Ks[kk][tx * 4 + j];
        #pragma unroll
        for (int i = 0; i < 4; i++)
            #pragma unroll
            for (int j = 0; j < 4; j++) acc[i][j] += a[i] * b[j];
    }
    #pragma unroll
    for (int i = 0; i < 4; i++) {
        int gr = row0 + ty * 4 + i;
        float e0 = expf(acc[i][0]), e1 = expf(acc[i][1]);
        float e2 = expf(acc[i][2]), e3 = expf(acc[i][3]);
        float s = (e0 + e1) + (e2 + e3);
        #pragma unroll
        for (int o = 1; o < 16; o <<= 1) s += __shfl_xor_sync(0xffffffffu, s, o);
        if (gr < N_OUT) {
            __half2* dst = reinterpret_cast<__half2*>(&Ep[(size_t)gr * N_IN + col0 + tx * 4]);
            dst[0] = __floats2half2_rn(e0, e1);
            dst[1] = __floats2half2_rn(e2, e3);
            if (tx == 0)
                g_rowpart[(size_t)(bh * N_OUT + gr) * KTILES + blockIdx.x] = s;
        }
    }
}

// ---------------- reduce row partials -> rinv = 1/rowsum ----------------
__global__ __launch_bounds__(32) void rowsum_kernel() {
    int row = blockIdx.x, lane = threadIdx.x;
    const float* p = g_rowpart + (size_t)row * KTILES;
    float v = p[lane] + p[lane + 32];
    #pragma unroll
    for (int o = 16; o; o >>= 1) v += __shfl_xor_sync(0xffffffffu, v, o);
    if (lane == 0) g_rinv[row] = 1.f / v;
}

// ---------------- colinv: 1/(sum_q e[q,k]*rinv[q] + EPS) ----------------
__global__ __launch_bounds__(256) void colinv_kernel() {
    int bh = blockIdx.y;
    int k2 = blockIdx.x * 256 + threadIdx.x;  // half2 index
    const __half2* p = reinterpret_cast<const __half2*>(g_e + (size_t)bh * N_OUT * N_IN) + k2;
    const float* ri = g_rinv + bh * N_OUT;
    float sx = 0.f, sy = 0.f;
    #pragma unroll 4
    for (int q = 0; q < N_OUT; q++) {
        float2 e = __half22float2(p[(size_t)q * (N_IN / 2)]);
        float r = ri[q];
        sx += e.x * r;
        sy += e.y * r;
    }
    g_colinv[bh * N_IN + k2 * 2]     = 1.f / (sx + EPSQ);
    g_colinv[bh * N_IN + k2 * 2 + 1] = 1.f / (sy + EPSQ);
}

// ---------------- upd = rinv[q] * sum_k e[q,k]*colinv[k]*v[k,d] ----------------
__global__ __launch_bounds__(256) void upd_kernel() {
    __shared__ float As[32][128];
    __shared__ float Vs[128][33];
    int bh = blockIdx.y;
    int b = bh / NH, h = bh - b * NH;
    int q0 = blockIdx.x * 32;
    int tid = threadIdx.x;
    int qi = tid >> 5, d = tid & 31;
    const __half* Ap = g_e + (size_t)bh * N_OUT * N_IN;
    const float* Vp = g_v + (size_t)bh * N_IN * HDIM;
    const float* Ci = g_colinv + bh * N_IN;
    float acc[4] = {0.f, 0.f, 0.f, 0.f};
    for (int kt = 0; kt < N_IN; kt += 128) {
        #pragma unroll
        for (int it = 0; it < 8; it++) {
            int f = it * 256 + tid;
            int r = f >> 6, c2 = (f & 63) * 2;
            int q = q0 + r;
            float2 e = (q < N_OUT)
                ? __half22float2(*reinterpret_cast<const __half2*>(&Ap[(size_t)q * N_IN + kt + c2]))
                : make_float2(0.f, 0.f);
            As[r][c2] = e.x;
            As[r][c2 + 1] = e.y;
        }
        #pragma unroll
        for (int it = 0; it < 16; it++) {
            int idx = it * 256 + tid;
            int kk = idx >> 5, c = idx & 31;
            Vs[kk][c] = Vp[(size_t)(kt + kk) * HDIM + c] * __ldg(&Ci[kt + kk]);
        }
        __syncthreads();
        #pragma unroll 8
        for (int kk = 0; kk < 128; kk++) {
            float vv = Vs[kk][d];
            acc[0] += As[qi][kk] * vv;
            acc[1] += As[qi + 8][kk] * vv;
            acc[2] += As[qi + 16][kk] * vv;
            acc[3] += As[qi + 24][kk] * vv;
        }
        __syncthreads();
    }
    #pragma unroll
    for (int i = 0; i < 4; i++) {
        int q = q0 + qi + i * 8;
        if (q < N_OUT) {
            float rq = g_rinv[bh * N_OUT + q];
            g_upd[((size_t)(b * N_OUT) + q) * DM + h * HDIM + d] = acc[i] * rq;
        }
    }
}

// ---------------- x_out += LN(src)*g + b ----------------
__global__ __launch_bounds__(384) void ln_add_kernel(const float* __restrict__ src,
                                                     const float* __restrict__ g,
                                                     const float* __restrict__ b) {
    __shared__ float sred[32];
    int row = blockIdx.x, tid = threadIdx.x;
    float v = src[row * DM + tid];
    float mu = blockSum(v, sred) * (1.f / DM);
    float d = v - mu;
    float var = blockSum(d * d, sred) * (1.f / DM);
    float rs = rsqrtf(var + LN_EPS);
    g_xout[row * DM + tid] += d * rs * g[tid] + b[tid];
}

// ---------------- finalize: attn_k = e*rinv ; attn_q = attn_k*colinv ----------------
__global__ __launch_bounds__(256) void finalize_kernel(float* __restrict__ attn_k,
                                                       float* __restrict__ attn_q) {
    int bh = blockIdx.z, q = blockIdx.y;
    int k4 = (blockIdx.x * 256 + threadIdx.x) * 4;
    size_t i = ((size_t)(bh * N_OUT + q) << 12) + k4;
    float r = g_rinv[bh * N_OUT + q];
    const __half2* ep = reinterpret_cast<const __half2*>(&g_e[i]);
    float2 e01 = __half22float2(ep[0]);
    float2 e23 = __half22float2(ep[1]);
    float4 ci = *reinterpret_cast<const float4*>(&g_colinv[bh * N_IN + k4]);
    float ak0 = e01.x * r, ak1 = e01.y * r, ak2 = e23.x * r, ak3 = e23.y * r;
    *reinterpret_cast<float4*>(&attn_k[i]) = make_float4(ak0, ak1, ak2, ak3);
    *reinterpret_cast<float4*>(&attn_q[i]) =
        make_float4(ak0 * ci.x, ak1 * ci.y, ak2 * ci.z, ak3 * ci.w);
}

// ---------------- copy x_out to d_out ----------------
__global__ __launch_bounds__(256) void copy_xout_kernel(float* __restrict__ out) {
    int i = blockIdx.x * 256 + threadIdx.x;
    out[i] = g_xout[i];
}

// ---------------- launch ----------------
extern "C" void kernel_launch(void* const* d_in, const int* in_sizes, int n_in,
                              void* d_out, int out_size) {
    const float* x      = (const float*)d_in[0];
    const float* conv_w = (const float*)d_in[1];
    const float* conv_b = (const float*)d_in[2];
    const float* kv_w   = (const float*)d_in[3];
    const float* kv_b   = (const float*)d_in[4];
    const float* q_w    = (const float*)d_in[5];
    const float* q_b    = (const float*)d_in[6];
    const float* mlp_w1 = (const float*)d_in[7];
    const float* mlp_b1 = (const float*)d_in[8];
    const float* mlp_w2 = (const float*)d_in[9];
    const float* mlp_b2 = (const float*)d_in[10];
    const float* g1     = (const float*)d_in[11];
    const float* b1     = (const float*)d_in[12];
    const float* g2     = (const float*)d_in[13];
    const float* b2     = (const float*)d_in[14];
    const float* g3     = (const float*)d_in[15];
    const float* b3     = (const float*)d_in[16];
    const float* temp   = (const float*)d_in[17];
    const float* freqs  = (const float*)d_in[18];

    float* out = (float*)d_out;
    float* attn_q_out = out + XOUT_SZ;
    float* attn_k_out = out + XOUT_SZ + ATTN_SZ;

    void *p_kv_, *p_xout_, *p_qlin_, *p_mlp_, *p_mlpo_, *p_upd_;
    void *p_kvw_, *p_qw_, *p_w1_, *p_w2_;
    cudaGetSymbolAddress(&p_kv_, g_kv);
    cudaGetSymbolAddress(&p_xout_, g_xout);
    cudaGetSymbolAddress(&p_qlin_, g_qlin);
    cudaGetSymbolAddress(&p_mlp_, g_mlp);
    cudaGetSymbolAddress(&p_mlpo_, g_mlpo);
    cudaGetSymbolAddress(&p_upd_, g_upd);
    cudaGetSymbolAddress(&p_kvw_, g_kvw_h);
    cudaGetSymbolAddress(&p_qw_, g_qw_h);
    cudaGetSymbolAddress(&p_w1_, g_w1_h);
    cudaGetSymbolAddress(&p_w2_, g_w2_h);
    float* p_kv   = (float*)p_kv_;
    float* p_xout = (float*)p_xout_;
    float* p_qlin = (float*)p_qlin_;
    float* p_mlp  = (float*)p_mlp_;
    float* p_mlpo = (float*)p_mlpo_;
    float* p_upd  = (float*)p_upd_;
    __half* p_kvw = (__half*)p_kvw_;
    __half* p_qw  = (__half*)p_qw_;
    __half* p_w1  = (__half*)p_w1_;
    __half* p_w2  = (__half*)p_w2_;

    // weight conversions (once per call)
    wt_transpose_kernel<<<dim3(12, 384), 256>>>(conv_w);
    f2h_kernel<<<(DM * 2 * DM / 4 + 255) / 256, 256>>>((const float4*)kv_w, (__half2*)p_kvw, DM * 2 * DM / 4);
    f2h_kernel<<<(DM * DM / 4 + 255) / 256, 256>>>((const float4*)q_w, (__half2*)p_qw, DM * DM / 4);
    f2h_kernel<<<(DM * 4 * DM / 4 + 255) / 256, 256>>>((const float4*)mlp_w1, (__half2*)p_w1, DM * 4 * DM / 4);
    f2h_kernel<<<(4 * DM * DM / 4 + 255) / 256, 256>>>((const float4*)mlp_w2, (__half2*)p_w2, 4 * DM * DM / 4);

    conv_mma<<<dim3(3, 8, CSPLIT), 256>>>(x);
    conv_ln_kernel<<<NB * N_OUT, 384>>>(conv_b, g1, b1);

    // loop-invariant kv / k / v
    gemm_mma<<<dim3(6, 64), 256>>>(x, p_kvw, kv_b, p_kv, NB * N_IN, 2 * DM, DM, 0);
    rose_kv_kernel<<<(NB * NH * N_IN * HDIM) / 256, 256>>>(temp, freqs);

    for (int it = 0; it < 3; it++) {
        gemm_mma<<<dim3(3, 8), 256>>>(p_xout, p_qw, q_b, p_qlin, NB * N_OUT, DM, DM, 0);
        rose_q_kernel<<<(NB * NH * N_OUT * HDIM) / 256, 256>>>(freqs);
        scores_kernel<<<dim3(64, 8, BHTOT), 256>>>();
        rowsum_kernel<<<NROWS, 32>>>();
        colinv_kernel<<<dim3(8, BHTOT), 256>>>();
        upd_kernel<<<dim3(16, BHTOT), 256>>>();
        ln_add_kernel<<<NB * N_OUT, 384>>>(p_upd, g2, b2);
        gemm_mma<<<dim3(12, 8), 256>>>(p_xout, p_w1, mlp_b1, p_mlp, NB * N_OUT, 4 * DM, DM, 1);
        gemm_mma<<<dim3(3, 8), 256>>>(p_mlp, p_w2, mlp_b2, p_mlpo, NB * N_OUT, DM, 4 * DM, 0);
        ln_add_kernel<<<NB * N_OUT, 384>>>(p_mlpo, g3, b3);
    }

    finalize_kernel<<<dim3(4, N_OUT, BHTOT), 256>>>(attn_k_out, attn_q_out);
    copy_xout_kernel<<<XOUT_SZ / 256, 256>>>(out);
}

// round 8
// speedup vs baseline: 3.7401x; 1.4565x over previous
#include <cuda_runtime.h>
#include <cuda_bf16.h>
#include <cuda_fp16.h>
#include <math.h>

// ---------------- problem constants ----------------
#define NB 2
#define N_IN 4096          // 64*64
#define N_OUT 484          // 22*22
#define DM 384
#define NH 12
#define HDIM 32
#define QG 22
#define KCONV 18816        // 49*384
#define BHTOT (NB*NH)      // 24
#define XOUT_SZ (NB*N_OUT*DM)              // 371712
#define ATTN_SZ ((size_t)NB*NH*N_OUT*N_IN) // 47579136
#define NROWS (BHTOT*N_OUT)                // 11616
#define KT2 32             // score col-tiles of 128
#define CSPLIT 6
#define CKLEN (KCONV/CSPLIT)               // 3136
#define EPSQ 1.1920929e-07f
#define LN_EPS 1e-5f

#define LDA 40             // As row stride (halves), conflict-free for ldmatrix
#define LDB 136            // Bs row stride (halves)
#define LDQ 40             // scores Q/K tile stride
#define LDE 72             // upd e-tile stride
#define LDV 40             // upd v-tile stride

// ---------------- scratch (static device memory; no allocations) ----------------
__device__ __half g_wt_h[(size_t)KCONV*DM];     // transposed conv weights, half
__device__ __half g_kvw_h[DM*2*DM];
__device__ __half g_qw_h[DM*DM];
__device__ __half g_w1_h[DM*4*DM];
__device__ __half g_w2_h[4*DM*DM];
__device__ float g_convpart[(size_t)CSPLIT*XOUT_SZ];
__device__ float g_xout[XOUT_SZ];
__device__ float g_kv[(size_t)NB*N_IN*2*DM];
__device__ __half g_kh[(size_t)NB*NH*N_IN*HDIM];
__device__ float g_v[(size_t)NB*NH*N_IN*HDIM];
__device__ __half g_vci[(size_t)NB*NH*N_IN*HDIM];
__device__ float g_qlin[XOUT_SZ];
__device__ __half g_qh[NB*NH*N_OUT*HDIM];
__device__ float g_colinv[BHTOT*N_IN];
__device__ float g_rowpart[(size_t)NROWS*KT2];
__device__ float g_rinv[NROWS];
__device__ float g_upd[XOUT_SZ];
__device__ float g_mlp[NB*N_OUT*4*DM];
__device__ float g_mlpo[XOUT_SZ];
__device__ __half g_e[ATTN_SZ];            // fp16 exp-score scratch

// ---------------- mma / ldmatrix helpers ----------------
__device__ __forceinline__ unsigned smem_u32(const void* p) {
    return (unsigned)__cvta_generic_to_shared(p);
}
__device__ __forceinline__ void ldsm4(unsigned* r, unsigned addr) {
    asm volatile("ldmatrix.sync.aligned.m8n8.x4.shared.b16 {%0,%1,%2,%3}, [%4];"
        : "=r"(r[0]), "=r"(r[1]), "=r"(r[2]), "=r"(r[3]) : "r"(addr));
}
__device__ __forceinline__ void ldsm2(unsigned* r, unsigned addr) {
    asm volatile("ldmatrix.sync.aligned.m8n8.x2.shared.b16 {%0,%1}, [%2];"
        : "=r"(r[0]), "=r"(r[1]) : "r"(addr));
}
__device__ __forceinline__ void ldsm2t(unsigned* r, unsigned addr) {
    asm volatile("ldmatrix.sync.aligned.m8n8.x2.trans.shared.b16 {%0,%1}, [%2];"
        : "=r"(r[0]), "=r"(r[1]) : "r"(addr));
}
__device__ __forceinline__ void mma16816(float* c, const unsigned* a, const unsigned* b) {
    asm volatile("mma.sync.aligned.m16n8k16.row.col.f32.f16.f16.f32 "
        "{%0,%1,%2,%3}, {%4,%5,%6,%7}, {%8,%9}, {%0,%1,%2,%3};"
        : "+f"(c[0]), "+f"(c[1]), "+f"(c[2]), "+f"(c[3])
        : "r"(a[0]), "r"(a[1]), "r"(a[2]), "r"(a[3]), "r"(b[0]), "r"(b[1]));
}

__device__ __forceinline__ float blockSum(float v, float* sred) {
    int tid = threadIdx.x, lane = tid & 31, wid = tid >> 5;
    #pragma unroll
    for (int o = 16; o; o >>= 1) v += __shfl_xor_sync(0xffffffffu, v, o);
    if (lane == 0) sred[wid] = v;
    __syncthreads();
    int nw = (blockDim.x + 31) >> 5;
    if (wid == 0) {
        float t = (lane < nw) ? sred[lane] : 0.f;
        #pragma unroll
        for (int o = 16; o; o >>= 1) t += __shfl_xor_sync(0xffffffffu, t, o);
        if (lane == 0) sred[0] = t;
    }
    __syncthreads();
    float r = sred[0];
    __syncthreads();
    return r;
}

// ---------------- weight fp32 -> fp16 ----------------
__global__ __launch_bounds__(256) void f2h_kernel(const float4* __restrict__ src,
                                                  __half2* __restrict__ dst, int n4) {
    int i = blockIdx.x * 256 + threadIdx.x;
    if (i < n4) {
        float4 v = src[i];
        dst[2 * i]     = __floats2half2_rn(v.x, v.y);
        dst[2 * i + 1] = __floats2half2_rn(v.z, v.w);
    }
}

// ---------------- conv weight transpose: (co,ci,t) -> (t,ci,co), fp16 out ----------------
__global__ __launch_bounds__(256) void wt_transpose_kernel(const float* __restrict__ conv_w) {
    __shared__ float s[32][50];
    int co0 = blockIdx.x * 32;
    int ci = blockIdx.y;
    int tid = threadIdx.x;
    for (int idx = tid; idx < 32 * 49; idx += 256) {
        int r = idx / 49, t = idx - r * 49;
        s[r][t] = conv_w[(size_t)(co0 + r) * KCONV + ci * 49 + t];
    }
    __syncthreads();
    for (int idx = tid; idx < 49 * 32; idx += 256) {
        int t = idx >> 5, c = idx & 31;
        g_wt_h[((size_t)(t * DM + ci)) * DM + co0 + c] = __float2half(s[c][t]);
    }
}

// ---------------- fp16 tensor-core GEMM: C = A@W + bias (act=1 -> exact gelu) ----------------
__global__ __launch_bounds__(256) void gemm_mma(const float* __restrict__ A,
                                                const __half* __restrict__ W,
                                                const float* __restrict__ bias,
                                                float* __restrict__ C,
                                                int M, int N, int K, int act) {
    __shared__ __half As[128 * LDA];
    __shared__ __half Bs[32 * LDB];
    int tid = threadIdx.x, lane = tid & 31, warp = tid >> 5;
    int wm = warp >> 2, wn = warp & 3;
    int row0 = blockIdx.y * 128, col0 = blockIdx.x * 128;

    int arow = tid >> 1, acb = (tid & 1) * 16;
    int agrow = row0 + arow;
    bool aval = agrow < M;
    const float* Aptr = A + (size_t)(aval ? agrow : 0) * K + acb;

    int brow[2], bseg[2];
    #pragma unroll
    for (int l = 0; l < 2; l++) { int f = tid + l * 256; brow[l] = f >> 4; bseg[l] = f & 15; }

    float acc[4][4][4] = {};
    float4 pa[4]; uint4 pw[2];

    auto ldGA = [&](int k0) {
        #pragma unroll
        for (int j = 0; j < 4; j++)
            pa[j] = aval ? *reinterpret_cast<const float4*>(Aptr + k0 + j * 4)
                         : make_float4(0.f, 0.f, 0.f, 0.f);
    };
    auto ldGB = [&](int k0) {
        #pragma unroll
        for (int l = 0; l < 2; l++)
            pw[l] = *reinterpret_cast<const uint4*>(&W[(size_t)(k0 + brow[l]) * N + col0 + bseg[l] * 8]);
    };
    auto stS = [&]() {
        __half2 h[8];
        #pragma unroll
        for (int j = 0; j < 4; j++) {
            h[2 * j]     = __floats2half2_rn(pa[j].x, pa[j].y);
            h[2 * j + 1] = __floats2half2_rn(pa[j].z, pa[j].w);
        }
        *reinterpret_cast<uint4*>(&As[arow * LDA + acb])     = *reinterpret_cast<uint4*>(&h[0]);
        *reinterpret_cast<uint4*>(&As[arow * LDA + acb + 8]) = *reinterpret_cast<uint4*>(&h[4]);
        #pragma unroll
        for (int l = 0; l < 2; l++)
            *reinterpret_cast<uint4*>(&Bs[brow[l] * LDB + bseg[l] * 8]) = pw[l];
    };

    unsigned aaddr[4], baddr[4];
    #pragma unroll
    for (int mt = 0; mt < 4; mt++)
        aaddr[mt] = smem_u32(&As[(wm * 64 + mt * 16 + (lane & 15)) * LDA + (lane >> 4) * 8]);
    #pragma unroll
    for (int nt = 0; nt < 4; nt++)
        baddr[nt] = smem_u32(&Bs[(lane & 15) * LDB + wn * 32 + nt * 8]);

    ldGA(0); ldGB(0);
    for (int k0 = 0;;) {
        stS();
        __syncthreads();
        int kn = k0 + 32;
        if (kn < K) { ldGA(kn); ldGB(kn); }
        #pragma unroll
        for (int ks = 0; ks < 2; ks++) {
            unsigned af[4][4], bf[4][2];
            #pragma unroll
            for (int mt = 0; mt < 4; mt++) ldsm4(af[mt], aaddr[mt] + ks * 32);
            #pragma unroll
            for (int nt = 0; nt < 4; nt++) ldsm2t(bf[nt], baddr[nt] + ks * 16 * LDB * 2);
            #pragma unroll
            for (int mt = 0; mt < 4; mt++)
                #pragma unroll
                for (int nt = 0; nt < 4; nt++) mma16816(acc[mt][nt], af[mt], bf[nt]);
        }
        k0 = kn;
        if (k0 >= K) break;
        __syncthreads();
    }

    int g = lane >> 2, tig = lane & 3;
    #pragma unroll
    for (int mt = 0; mt < 4; mt++) {
        #pragma unroll
        for (int nt = 0; nt < 4; nt++) {
            int r = row0 + wm * 64 + mt * 16 + g;
            int c = col0 + wn * 32 + nt * 8 + tig * 2;
            float b0 = bias[c], b1 = bias[c + 1];
            if (r < M) {
                float v0 = acc[mt][nt][0] + b0, v1 = acc[mt][nt][1] + b1;
                if (act == 1) {
                    v0 = 0.5f * v0 * (1.f + erff(v0 * 0.70710678118654752f));
                    v1 = 0.5f * v1 * (1.f + erff(v1 * 0.70710678118654752f));
                }
                *reinterpret_cast<float2*>(&C[(size_t)r * N + c]) = make_float2(v0, v1);
            }
            if (r + 8 < M) {
                float v2 = acc[mt][nt][2] + b0, v3 = acc[mt][nt][3] + b1;
                if (act == 1) {
                    v2 = 0.5f * v2 * (1.f + erff(v2 * 0.70710678118654752f));
                    v3 = 0.5f * v3 * (1.f + erff(v3 * 0.70710678118654752f));
                }
                *reinterpret_cast<float2*>(&C[(size_t)(r + 8) * N + c]) = make_float2(v2, v3);
            }
        }
    }
}

// ---------------- implicit-GEMM conv with HMMA, split-K=6, fp32 partials ----------------
__global__ __launch_bounds__(256) void conv_mma(const float* __restrict__ x) {
    __shared__ __half As[128 * LDA];
    __shared__ __half Bs[32 * LDB];
    int tid = threadIdx.x, lane = tid & 31, warp = tid >> 5;
    int wm = warp >> 2, wn = warp & 3;
    int row0 = blockIdx.y * 128, col0 = blockIdx.x * 128;
    int kbeg = blockIdx.z * CKLEN, kend = kbeg + CKLEN;

    int arow = tid >> 1, acb = (tid & 1) * 16;
    int agrow = row0 + arow;
    bool aval = agrow < NB * N_OUT;
    int g2 = aval ? agrow : 0;
    int rb = g2 / N_OUT;
    int nn = g2 - rb * N_OUT;
    int oy = nn / QG, ox = nn - oy * QG;

    int brow[2], bseg[2];
    #pragma unroll
    for (int l = 0; l < 2; l++) { int f = tid + l * 256; brow[l] = f >> 4; bseg[l] = f & 15; }

    float acc[4][4][4] = {};
    float4 pa[4]; uint4 pw[2];

    auto ldGA = [&](int k0) {
        int kk = k0 + acb;
        int t = kk / DM, ci = kk - t * DM;
        int ky = t / 7, kx = t - ky * 7;
        int iy = oy * 3 - 3 + ky, ix = ox * 3 - 3 + kx;
        bool ok = aval && (unsigned)iy < 64u && (unsigned)ix < 64u;
        const float* p = x + ((size_t)(rb * N_IN) + iy * 64 + ix) * DM + ci;
        #pragma unroll
        for (int j = 0; j < 4; j++)
            pa[j] = ok ? *reinterpret_cast<const float4*>(p + j * 4)
                       : make_float4(0.f, 0.f, 0.f, 0.f);
    };
    auto ldGB = [&](int k0) {
        #pragma unroll
        for (int l = 0; l < 2; l++)
            pw[l] = *reinterpret_cast<const uint4*>(&g_wt_h[(size_t)(k0 + brow[l]) * DM + col0 + bseg[l] * 8]);
    };
    auto stS = [&]() {
        __half2 h[8];
        #pragma unroll
        for (int j = 0; j < 4; j++) {
            h[2 * j]     = __floats2half2_rn(pa[j].x, pa[j].y);
            h[2 * j + 1] = __floats2half2_rn(pa[j].z, pa[j].w);
        }
        *reinterpret_cast<uint4*>(&As[arow * LDA + acb])     = *reinterpret_cast<uint4*>(&h[0]);
        *reinterpret_cast<uint4*>(&As[arow * LDA + acb + 8]) = *reinterpret_cast<uint4*>(&h[4]);
        #pragma unroll
        for (int l = 0; l < 2; l++)
            *reinterpret_cast<uint4*>(&Bs[brow[l] * LDB + bseg[l] * 8]) = pw[l];
    };

    unsigned aaddr[4], baddr[4];
    #pragma unroll
    for (int mt = 0; mt < 4; mt++)
        aaddr[mt] = smem_u32(&As[(wm * 64 + mt * 16 + (lane & 15)) * LDA + (lane >> 4) * 8]);
    #pragma unroll
    for (int nt = 0; nt < 4; nt++)
        baddr[nt] = smem_u32(&Bs[(lane & 15) * LDB + wn * 32 + nt * 8]);

    ldGA(kbeg); ldGB(kbeg);
    for (int k0 = kbeg;;) {
        stS();
        __syncthreads();
        int kn = k0 + 32;
        if (kn < kend) { ldGA(kn); ldGB(kn); }
        #pragma unroll
        for (int ks = 0; ks < 2; ks++) {
            unsigned af[4][4], bf[4][2];
            #pragma unroll
            for (int mt = 0; mt < 4; mt++) ldsm4(af[mt], aaddr[mt] + ks * 32);
            #pragma unroll
            for (int nt = 0; nt < 4; nt++) ldsm2t(bf[nt], baddr[nt] + ks * 16 * LDB * 2);
            #pragma unroll
            for (int mt = 0; mt < 4; mt++)
                #pragma unroll
                for (int nt = 0; nt < 4; nt++) mma16816(acc[mt][nt], af[mt], bf[nt]);
        }
        k0 = kn;
        if (k0 >= kend) break;
        __syncthreads();
    }

    float* out = g_convpart + (size_t)blockIdx.z * XOUT_SZ;
    int g = lane >> 2, tig = lane & 3;
    #pragma unroll
    for (int mt = 0; mt < 4; mt++) {
        #pragma unroll
        for (int nt = 0; nt < 4; nt++) {
            int r = row0 + wm * 64 + mt * 16 + g;
            int c = col0 + wn * 32 + nt * 8 + tig * 2;
            if (r < NB * N_OUT)
                *reinterpret_cast<float2*>(&out[(size_t)r * DM + c]) =
                    make_float2(acc[mt][nt][0], acc[mt][nt][1]);
            if (r + 8 < NB * N_OUT)
                *reinterpret_cast<float2*>(&out[(size_t)(r + 8) * DM + c]) =
                    make_float2(acc[mt][nt][2], acc[mt][nt][3]);
        }
    }
}

// ---------------- conv partial reduce + bias + LN -> g_xout ----------------
__global__ __launch_bounds__(384) void conv_ln_kernel(const float* __restrict__ cb,
                                                      const float* __restrict__ g,
                                                      const float* __restrict__ b) {
    __shared__ float sred[32];
    int row = blockIdx.x, tid = threadIdx.x;
    float v = cb[tid];
    #pragma unroll
    for (int s = 0; s < CSPLIT; s++) v += g_convpart[(size_t)s * XOUT_SZ + row * DM + tid];
    float mu = blockSum(v, sred) * (1.f / DM);
    float d = v - mu;
    float var = blockSum(d * d, sred) * (1.f / DM);
    float rs = rsqrtf(var + LN_EPS);
    g_xout[row * DM + tid] = d * rs * g[tid] + b[tid];
}

// ---------------- rose for K (fp16 out) + V split (fp32) ----------------
__global__ __launch_bounds__(256) void rose_kv_kernel(const float* __restrict__ temp,
                                                      const float* __restrict__ freqs) {
    int idx = blockIdx.x * 256 + threadIdx.x;
    int d = idx & 31;
    int t = idx >> 5;
    int n = t & (N_IN - 1);
    int bh = t >> 12;
    int h = bh % NH;
    int b = bh / NH;
    const float* src = g_kv + ((size_t)(b * N_IN + n)) * (2 * DM) + h * HDIM;
    float tv = temp[0];
    float val;
    if (d < 16) {
        int j = d >> 1;
        int s = j >> 2, p = j & 3;
        float coord = (s == 0) ? (float)(n >> 6) : (float)(n & 63);
        float ang = coord * freqs[(h * 2 + s) * 4 + p];
        float sn, cs;
        sincosf(ang, &sn, &cs);
        float x1 = src[j * 2], x2 = src[j * 2 + 1];
        val = (d & 1) ? (x1 * sn + x2 * cs) : (x1 * cs - x2 * sn);
    } else {
        val = src[d];
    }
    g_kh[idx] = __float2half(tv * val);
    g_v[idx] = src[DM + d];
}

// ---------------- rose for Q (fp16 out) ----------------
__global__ __launch_bounds__(256) void rose_q_kernel(const float* __restrict__ freqs) {
    int idx = blockIdx.x * 256 + threadIdx.x;
    int d = idx & 31;
    int t = idx >> 5;
    int n = t % N_OUT;
    int bh = t / N_OUT;
    int h = bh % NH;
    int b = bh / NH;
    const float* src = g_qlin + ((size_t)(b * N_OUT + n)) * DM + h * HDIM;
    float val;
    if (d < 16) {
        int j = d >> 1;
        int s = j >> 2, p = j & 3;
        float coord = (s == 0) ? (float)(n / QG) * 3.0f : (float)(n % QG) * 3.0f;
        float ang = coord * freqs[(h * 2 + s) * 4 + p];
        float sn, cs;
        sincosf(ang, &sn, &cs);
        float x1 = src[j * 2], x2 = src[j * 2 + 1];
        val = (d & 1) ? (x1 * sn + x2 * cs) : (x1 * cs - x2 * sn);
    } else {
        val = src[d];
    }
    g_qh[idx] = __float2half(val);
}

// ---------------- scores via HMMA: e = exp(Q.K^T) fp16 + per-tile row sums ----------------
// block tile 64(q) x 128(k), 8 warps (2m x 4n), warp tile 32x32.
__global__ __launch_bounds__(256) void scores_mma() {
    __shared__ __half Qs[64 * LDQ];
    __shared__ __half Ks[128 * LDQ];
    __shared__ float sred2[64 * 4];
    int tid = threadIdx.x, lane = tid & 31, warp = tid >> 5;
    int wm = warp >> 2, wn = warp & 3;
    int bh = blockIdx.z;
    int row0 = blockIdx.y * 64, col0 = blockIdx.x * 128;
    const __half* Qp = g_qh + (size_t)bh * N_OUT * HDIM;
    const __half* Kp = g_kh + (size_t)bh * N_IN * HDIM;
    __half* Ep = g_e + (size_t)bh * N_OUT * N_IN;

    {   // load Q tile (64 x 32): 256 uint4
        int r = tid >> 2, seg = tid & 3;
        uint4 v = (row0 + r < N_OUT)
            ? *reinterpret_cast<const uint4*>(&Qp[(size_t)(row0 + r) * HDIM + seg * 8])
            : make_uint4(0u, 0u, 0u, 0u);
        *reinterpret_cast<uint4*>(&Qs[r * LDQ + seg * 8]) = v;
    }
    #pragma unroll
    for (int l = 0; l < 2; l++) {  // load K tile (128 x 32): 512 uint4
        int f = tid + l * 256;
        int r = f >> 2, seg = f & 3;
        *reinterpret_cast<uint4*>(&Ks[r * LDQ + seg * 8]) =
            *reinterpret_cast<const uint4*>(&Kp[(size_t)(col0 + r) * HDIM + seg * 8]);
    }
    __syncthreads();

    float acc[2][4][4] = {};
    #pragma unroll
    for (int ks = 0; ks < 2; ks++) {
        unsigned af[2][4], bf[4][2];
        #pragma unroll
        for (int mt = 0; mt < 2; mt++)
            ldsm4(af[mt], smem_u32(&Qs[(wm * 32 + mt * 16 + (lane & 15)) * LDQ + (lane >> 4) * 8 + ks * 16]));
        #pragma unroll
        for (int nt = 0; nt < 4; nt++)
            ldsm2(bf[nt], smem_u32(&Ks[(wn * 32 + nt * 8 + (lane & 7)) * LDQ + ((lane >> 3) & 1) * 8 + ks * 16]));
        #pragma unroll
        for (int mt = 0; mt < 2; mt++)
            #pragma unroll
            for (int nt = 0; nt < 4; nt++) mma16816(acc[mt][nt], af[mt], bf[nt]);
    }

    int g = lane >> 2, tig = lane & 3;
    #pragma unroll
    for (int mt = 0; mt < 2; mt++) {
        float rp0 = 0.f, rp1 = 0.f;
        int r0 = row0 + wm * 32 + mt * 16 + g;
        #pragma unroll
        for (int nt = 0; nt < 4; nt++) {
            float e0 = __expf(acc[mt][nt][0]), e1 = __expf(acc[mt][nt][1]);
            float e2 = __expf(acc[mt][nt][2]), e3 = __expf(acc[mt][nt][3]);
            int c = col0 + wn * 32 + nt * 8 + tig * 2;
            if (r0 < N_OUT)
                *reinterpret_cast<__half2*>(&Ep[(size_t)r0 * N_IN + c]) = __floats2half2_rn(e0, e1);
            if (r0 + 8 < N_OUT)
                *reinterpret_cast<__half2*>(&Ep[(size_t)(r0 + 8) * N_IN + c]) = __floats2half2_rn(e2, e3);
            rp0 += e0 + e1;
            rp1 += e2 + e3;
        }
        rp0 += __shfl_xor_sync(0xffffffffu, rp0, 1);
        rp0 += __shfl_xor_sync(0xffffffffu, rp0, 2);
        rp1 += __shfl_xor_sync(0xffffffffu, rp1, 1);
        rp1 += __shfl_xor_sync(0xffffffffu, rp1, 2);
        if (tig == 0) {
            int rr = wm * 32 + mt * 16 + g;
            sred2[rr * 4 + wn] = rp0;
            sred2[(rr + 8) * 4 + wn] = rp1;
        }
    }
    __syncthreads();
    if (tid < 64) {
        int gr = row0 + tid;
        if (gr < N_OUT) {
            float s = sred2[tid * 4] + sred2[tid * 4 + 1] + sred2[tid * 4 + 2] + sred2[tid * 4 + 3];
            g_rowpart[(size_t)(bh * N_OUT + gr) * KT2 + blockIdx.x] = s;
        }
    }
}

// ---------------- reduce row partials -> rinv = 1/rowsum ----------------
__global__ __launch_bounds__(32) void rowsum_kernel() {
    int row = blockIdx.x, lane = threadIdx.x;
    float v = g_rowpart[(size_t)row * KT2 + lane];
    #pragma unroll
    for (int o = 16; o; o >>= 1) v += __shfl_xor_sync(0xffffffffu, v, o);
    if (lane == 0) g_rinv[row] = 1.f / v;
}

// ---------------- colinv: 1/(sum_q e[q,k]*rinv[q] + EPS) ----------------
__global__ __launch_bounds__(256) void colinv_kernel() {
    int bh = blockIdx.y;
    int k2 = blockIdx.x * 256 + threadIdx.x;  // half2 index
    const __half2* p = reinterpret_cast<const __half2*>(g_e + (size_t)bh * N_OUT * N_IN) + k2;
    const float* ri = g_rinv + bh * N_OUT;
    float sx = 0.f, sy = 0.f;
    #pragma unroll 4
    for (int q = 0; q < N_OUT; q++) {
        float2 e = __half22float2(p[(size_t)q * (N_IN / 2)]);
        float r = ri[q];
        sx += e.x * r;
        sy += e.y * r;
    }
    g_colinv[bh * N_IN + k2 * 2]     = 1.f / (sx + EPSQ);
    g_colinv[bh * N_IN + k2 * 2 + 1] = 1.f / (sy + EPSQ);
}

// ---------------- vci = v * colinv -> fp16 ----------------
__global__ __launch_bounds__(256) void vci_kernel() {
    int idx = blockIdx.x * 256 + threadIdx.x;   // < BHTOT*N_IN*HDIM
    int k = (idx >> 5) & (N_IN - 1);
    int bh = idx >> 17;
    g_vci[idx] = __float2half(g_v[idx] * g_colinv[bh * N_IN + k]);
}

// ---------------- upd via HMMA: upd = rinv[q] * (e @ vci) ----------------
// block: 128 q-rows, 8 warps (one m16 tile each), N=32, K chunk 64.
__global__ __launch_bounds__(256) void upd_mma() {
    __shared__ __half Es[128 * LDE];
    __shared__ __half Vs[64 * LDV];
    int tid = threadIdx.x, lane = tid & 31, warp = tid >> 5;
    int bh = blockIdx.y;
    int b = bh / NH, h = bh - b * NH;
    int q0 = blockIdx.x * 128;
    const __half* Ep = g_e + (size_t)bh * N_OUT * N_IN;
    const __half* Vp = g_vci + (size_t)bh * N_IN * HDIM;

    float acc[4][4] = {};
    for (int kt = 0; kt < N_IN; kt += 64) {
        #pragma unroll
        for (int l = 0; l < 4; l++) {   // Es: 128 rows x 64 halves = 1024 uint4
            int f = l * 256 + tid;
            int r = f >> 3, seg = f & 7;
            uint4 v = (q0 + r < N_OUT)
                ? *reinterpret_cast<const uint4*>(&Ep[(size_t)(q0 + r) * N_IN + kt + seg * 8])
                : make_uint4(0u, 0u, 0u, 0u);
            *reinterpret_cast<uint4*>(&Es[r * LDE + seg * 8]) = v;
        }
        {   // Vs: 64 rows x 32 halves = 256 uint4
            int r = tid >> 2, seg = tid & 3;
            *reinterpret_cast<uint4*>(&Vs[r * LDV + seg * 8]) =
                *reinterpret_cast<const uint4*>(&Vp[(size_t)(kt + r) * HDIM + seg * 8]);
        }
        __syncthreads();
        #pragma unroll
        for (int ks = 0; ks < 4; ks++) {
            unsigned af[4], bf[4][2];
            ldsm4(af, smem_u32(&Es[(warp * 16 + (lane & 15)) * LDE + (lane >> 4) * 8 + ks * 16]));
            #pragma unroll
            for (int nt = 0; nt < 4; nt++)
                ldsm2t(bf[nt], smem_u32(&Vs[((lane & 15) + ks * 16) * LDV + nt * 8]));
            #pragma unroll
            for (int nt = 0; nt < 4; nt++) mma16816(acc[nt], af, bf[nt]);
        }
        __syncthreads();
    }

    int g = lane >> 2, tig = lane & 3;
    int q = q0 + warp * 16 + g;
    if (q < N_OUT) {
        float rq = g_rinv[bh * N_OUT + q];
        float* dst = &g_upd[((size_t)(b * N_OUT) + q) * DM + h * HDIM];
        #pragma unroll
        for (int nt = 0; nt < 4; nt++)
            *reinterpret_cast<float2*>(&dst[nt * 8 + tig * 2]) =
                make_float2(acc[nt][0] * rq, acc[nt][1] * rq);
    }
    if (q + 8 < N_OUT) {
        float rq = g_rinv[bh * N_OUT + q + 8];
        float* dst = &g_upd[((size_t)(b * N_OUT) + q + 8) * DM + h * HDIM];
        #pragma unroll
        for (int nt = 0; nt < 4; nt++)
            *reinterpret_cast<float2*>(&dst[nt * 8 + tig * 2]) =
                make_float2(acc[nt][2] * rq, acc[nt][3] * rq);
    }
}

// ---------------- x_out += LN(src)*g + b ----------------
__global__ __launch_bounds__(384) void ln_add_kernel(const float* __restrict__ src,
                                                     const float* __restrict__ g,
                                                     const float* __restrict__ b) {
    __shared__ float sred[32];
    int row = blockIdx.x, tid = threadIdx.x;
    float v = src[row * DM + tid];
    float mu = blockSum(v, sred) * (1.f / DM);
    float d = v - mu;
    float var = blockSum(d * d, sred) * (1.f / DM);
    float rs = rsqrtf(var + LN_EPS);
    g_xout[row * DM + tid] += d * rs * g[tid] + b[tid];
}

// ---------------- finalize: attn_k = e*rinv ; attn_q = attn_k*colinv ----------------
__global__ __launch_bounds__(256) void finalize_kernel(float* __restrict__ attn_k,
                                                       float* __restrict__ attn_q) {
    int bh = blockIdx.z, q = blockIdx.y;
    int k4 = (blockIdx.x * 256 + threadIdx.x) * 4;
    size_t i = ((size_t)(bh * N_OUT + q) << 12) + k4;
    float r = g_rinv[bh * N_OUT + q];
    const __half2* ep = reinterpret_cast<const __half2*>(&g_e[i]);
    float2 e01 = __half22float2(ep[0]);
    float2 e23 = __half22float2(ep[1]);
    float4 ci = *reinterpret_cast<const float4*>(&g_colinv[bh * N_IN + k4]);
    float ak0 = e01.x * r, ak1 = e01.y * r, ak2 = e23.x * r, ak3 = e23.y * r;
    *reinterpret_cast<float4*>(&attn_k[i]) = make_float4(ak0, ak1, ak2, ak3);
    *reinterpret_cast<float4*>(&attn_q[i]) =
        make_float4(ak0 * ci.x, ak1 * ci.y, ak2 * ci.z, ak3 * ci.w);
}

// ---------------- copy x_out to d_out ----------------
__global__ __launch_bounds__(256) void copy_xout_kernel(float* __restrict__ out) {
    int i = blockIdx.x * 256 + threadIdx.x;
    out[i] = g_xout[i];
}

// ---------------- launch ----------------
extern "C" void kernel_launch(void* const* d_in, const int* in_sizes, int n_in,
                              void* d_out, int out_size) {
    const float* x      = (const float*)d_in[0];
    const float* conv_w = (const float*)d_in[1];
    const float* conv_b = (const float*)d_in[2];
    const float* kv_w   = (const float*)d_in[3];
    const float* kv_b   = (const float*)d_in[4];
    const float* q_w    = (const float*)d_in[5];
    const float* q_b    = (const float*)d_in[6];
    const float* mlp_w1 = (const float*)d_in[7];
    const float* mlp_b1 = (const float*)d_in[8];
    const float* mlp_w2 = (const float*)d_in[9];
    const float* mlp_b2 = (const float*)d_in[10];
    const float* g1     = (const float*)d_in[11];
    const float* b1     = (const float*)d_in[12];
    const float* g2     = (const float*)d_in[13];
    const float* b2     = (const float*)d_in[14];
    const float* g3     = (const float*)d_in[15];
    const float* b3     = (const float*)d_in[16];
    const float* temp   = (const float*)d_in[17];
    const float* freqs  = (const float*)d_in[18];

    float* out = (float*)d_out;
    float* attn_q_out = out + XOUT_SZ;
    float* attn_k_out = out + XOUT_SZ + ATTN_SZ;

    void *p_kv_, *p_xout_, *p_qlin_, *p_mlp_, *p_mlpo_, *p_upd_;
    void *p_kvw_, *p_qw_, *p_w1_, *p_w2_;
    cudaGetSymbolAddress(&p_kv_, g_kv);
    cudaGetSymbolAddress(&p_xout_, g_xout);
    cudaGetSymbolAddress(&p_qlin_, g_qlin);
    cudaGetSymbolAddress(&p_mlp_, g_mlp);
    cudaGetSymbolAddress(&p_mlpo_, g_mlpo);
    cudaGetSymbolAddress(&p_upd_, g_upd);
    cudaGetSymbolAddress(&p_kvw_, g_kvw_h);
    cudaGetSymbolAddress(&p_qw_, g_qw_h);
    cudaGetSymbolAddress(&p_w1_, g_w1_h);
    cudaGetSymbolAddress(&p_w2_, g_w2_h);
    float* p_kv   = (float*)p_kv_;
    float* p_xout = (float*)p_xout_;
    float* p_qlin = (float*)p_qlin_;
    float* p_mlp  = (float*)p_mlp_;
    float* p_mlpo = (float*)p_mlpo_;
    float* p_upd  = (float*)p_upd_;
    __half* p_kvw = (__half*)p_kvw_;
    __half* p_qw  = (__half*)p_qw_;
    __half* p_w1  = (__half*)p_w1_;
    __half* p_w2  = (__half*)p_w2_;

    // weight conversions (once per call)
    wt_transpose_kernel<<<dim3(12, 384), 256>>>(conv_w);
    f2h_kernel<<<(DM * 2 * DM / 4 + 255) / 256, 256>>>((const float4*)kv_w, (__half2*)p_kvw, DM * 2 * DM / 4);
    f2h_kernel<<<(DM * DM / 4 + 255) / 256, 256>>>((const float4*)q_w, (__half2*)p_qw, DM * DM / 4);
    f2h_kernel<<<(DM * 4 * DM / 4 + 255) / 256, 256>>>((const float4*)mlp_w1, (__half2*)p_w1, DM * 4 * DM / 4);
    f2h_kernel<<<(4 * DM * DM / 4 + 255) / 256, 256>>>((const float4*)mlp_w2, (__half2*)p_w2, 4 * DM * DM / 4);

    conv_mma<<<dim3(3, 8, CSPLIT), 256>>>(x);
    conv_ln_kernel<<<NB * N_OUT, 384>>>(conv_b, g1, b1);

    // loop-invariant kv / k / v
    gemm_mma<<<dim3(6, 64), 256>>>(x, p_kvw, kv_b, p_kv, NB * N_IN, 2 * DM, DM, 0);
    rose_kv_kernel<<<(NB * NH * N_IN * HDIM) / 256, 256>>>(temp, freqs);

    for (int it = 0; it < 3; it++) {
        gemm_mma<<<dim3(3, 8), 256>>>(p_xout, p_qw, q_b, p_qlin, NB * N_OUT, DM, DM, 0);
        rose_q_kernel<<<(NB * NH * N_OUT * HDIM) / 256, 256>>>(freqs);
        scores_mma<<<dim3(KT2, 8, BHTOT), 256>>>();
        rowsum_kernel<<<NROWS, 32>>>();
        colinv_kernel<<<dim3(8, BHTOT), 256>>>();
        vci_kernel<<<(BHTOT * N_IN * HDIM) / 256, 256>>>();
        upd_mma<<<dim3(4, BHTOT), 256>>>();
        ln_add_kernel<<<NB * N_OUT, 384>>>(p_upd, g2, b2);
        gemm_mma<<<dim3(12, 8), 256>>>(p_xout, p_w1, mlp_b1, p_mlp, NB * N_OUT, 4 * DM, DM, 1);
        gemm_mma<<<dim3(3, 8), 256>>>(p_mlp, p_w2, mlp_b2, p_mlpo, NB * N_OUT, DM, 4 * DM, 0);
        ln_add_kernel<<<NB * N_OUT, 384>>>(p_mlpo, g3, b3);
    }

    finalize_kernel<<<dim3(4, N_OUT, BHTOT), 256>>>(attn_k_out, attn_q_out);
    copy_xout_kernel<<<XOUT_SZ / 256, 256>>>(out);
}

// round 9
// speedup vs baseline: 3.8288x; 1.0237x over previous
#include <cuda_runtime.h>
#include <cuda_bf16.h>
#include <cuda_fp16.h>
#include <math.h>

// ---------------- problem constants ----------------
#define NB 2
#define N_IN 4096          // 64*64
#define N_OUT 484          // 22*22
#define DM 384
#define NH 12
#define HDIM 32
#define QG 22
#define KCONV 18816        // 49*384
#define BHTOT (NB*NH)      // 24
#define XOUT_SZ (NB*N_OUT*DM)              // 371712
#define ATTN_SZ ((size_t)NB*NH*N_OUT*N_IN) // 47579136
#define NROWS (BHTOT*N_OUT)                // 11616
#define KT2 32             // score col-tiles of 128
#define CSPLIT 6
#define CKLEN (KCONV/CSPLIT)               // 3136
#define EPSQ 1.1920929e-07f
#define LN_EPS 1e-5f

#define LDA 40             // As row stride (halves), conflict-free for ldmatrix
#define LDB 136            // Bs row stride (halves)
#define LDQ 40             // scores Q/K tile stride
#define LDE2 136           // scores e-staging stride
#define LDE 72             // upd e-tile stride
#define LDV 40             // upd v-tile stride

// ---------------- scratch (static device memory; no allocations) ----------------
__device__ __half g_wt_h[(size_t)KCONV*DM];
__device__ __half g_kvw_h[DM*2*DM];
__device__ __half g_qw_h[DM*DM];
__device__ __half g_w1_h[DM*4*DM];
__device__ __half g_w2_h[4*DM*DM];
__device__ float g_convpart[(size_t)CSPLIT*XOUT_SZ];
__device__ float g_xout[XOUT_SZ];
__device__ __half g_kh[(size_t)NB*NH*N_IN*HDIM];
__device__ float g_v[(size_t)NB*NH*N_IN*HDIM];
__device__ __half g_vci[(size_t)NB*NH*N_IN*HDIM];
__device__ __half g_qh[NB*NH*N_OUT*HDIM];
__device__ float g_colinv[BHTOT*N_IN];
__device__ float g_rowpart[(size_t)NROWS*KT2];
__device__ float g_rinv[NROWS];
__device__ float g_upd[XOUT_SZ];
__device__ float g_mlp[NB*N_OUT*4*DM];
__device__ float g_mlpo[XOUT_SZ];
__device__ __half g_e[ATTN_SZ];

// ---------------- mma / ldmatrix helpers ----------------
__device__ __forceinline__ unsigned smem_u32(const void* p) {
    return (unsigned)__cvta_generic_to_shared(p);
}
__device__ __forceinline__ void ldsm4(unsigned* r, unsigned addr) {
    asm volatile("ldmatrix.sync.aligned.m8n8.x4.shared.b16 {%0,%1,%2,%3}, [%4];"
        : "=r"(r[0]), "=r"(r[1]), "=r"(r[2]), "=r"(r[3]) : "r"(addr));
}
__device__ __forceinline__ void ldsm2(unsigned* r, unsigned addr) {
    asm volatile("ldmatrix.sync.aligned.m8n8.x2.shared.b16 {%0,%1}, [%2];"
        : "=r"(r[0]), "=r"(r[1]) : "r"(addr));
}
__device__ __forceinline__ void ldsm2t(unsigned* r, unsigned addr) {
    asm volatile("ldmatrix.sync.aligned.m8n8.x2.trans.shared.b16 {%0,%1}, [%2];"
        : "=r"(r[0]), "=r"(r[1]) : "r"(addr));
}
__device__ __forceinline__ void mma16816(float* c, const unsigned* a, const unsigned* b) {
    asm volatile("mma.sync.aligned.m16n8k16.row.col.f32.f16.f16.f32 "
        "{%0,%1,%2,%3}, {%4,%5,%6,%7}, {%8,%9}, {%0,%1,%2,%3};"
        : "+f"(c[0]), "+f"(c[1]), "+f"(c[2]), "+f"(c[3])
        : "r"(a[0]), "r"(a[1]), "r"(a[2]), "r"(a[3]), "r"(b[0]), "r"(b[1]));
}

__device__ __forceinline__ float blockSum(float v, float* sred) {
    int tid = threadIdx.x, lane = tid & 31, wid = tid >> 5;
    #pragma unroll
    for (int o = 16; o; o >>= 1) v += __shfl_xor_sync(0xffffffffu, v, o);
    if (lane == 0) sred[wid] = v;
    __syncthreads();
    int nw = (blockDim.x + 31) >> 5;
    if (wid == 0) {
        float t = (lane < nw) ? sred[lane] : 0.f;
        #pragma unroll
        for (int o = 16; o; o >>= 1) t += __shfl_xor_sync(0xffffffffu, t, o);
        if (lane == 0) sred[0] = t;
    }
    __syncthreads();
    float r = sred[0];
    __syncthreads();
    return r;
}

// ---------------- weight fp32 -> fp16 ----------------
__global__ __launch_bounds__(256) void f2h_kernel(const float4* __restrict__ src,
                                                  __half2* __restrict__ dst, int n4) {
    int i = blockIdx.x * 256 + threadIdx.x;
    if (i < n4) {
        float4 v = src[i];
        dst[2 * i]     = __floats2half2_rn(v.x, v.y);
        dst[2 * i + 1] = __floats2half2_rn(v.z, v.w);
    }
}

// ---------------- conv weight transpose: (co,ci,t) -> (t,ci,co), fp16 out ----------------
__global__ __launch_bounds__(256) void wt_transpose_kernel(const float* __restrict__ conv_w) {
    __shared__ float s[32][50];
    int co0 = blockIdx.x * 32;
    int ci = blockIdx.y;
    int tid = threadIdx.x;
    for (int idx = tid; idx < 32 * 49; idx += 256) {
        int r = idx / 49, t = idx - r * 49;
        s[r][t] = conv_w[(size_t)(co0 + r) * KCONV + ci * 49 + t];
    }
    __syncthreads();
    for (int idx = tid; idx < 49 * 32; idx += 256) {
        int t = idx >> 5, c = idx & 31;
        g_wt_h[((size_t)(t * DM + ci)) * DM + co0 + c] = __float2half(s[c][t]);
    }
}

// ---------------- fp16 tensor-core GEMM, BM x 128 tile, templated BM ----------------
// act: 0 = bias, 1 = bias+gelu, 2 = rose-Q (write g_qh fp16), 3 = rose-KV (write g_kh/g_v)
template<int BM>
__global__ __launch_bounds__(256) void gemm_mma(const float* __restrict__ A,
                                                const __half* __restrict__ W,
                                                const float* __restrict__ bias,
                                                float* __restrict__ C,
                                                int M, int N, int K, int act,
                                                const float* __restrict__ freqs,
                                                const float* __restrict__ temp) {
    constexpr int MT = BM / 32;        // m16 tiles per warp
    constexpr int NL4 = BM / 32;       // float4 A-loads per thread
    __shared__ __half As[BM * LDA];
    __shared__ __half Bs[32 * LDB];
    int tid = threadIdx.x, lane = tid & 31, warp = tid >> 5;
    int wm = warp >> 2, wn = warp & 3;
    int row0 = blockIdx.y * BM, col0 = blockIdx.x * 128;

    int ar[NL4], aseg[NL4];
    bool av[NL4];
    #pragma unroll
    for (int l = 0; l < NL4; l++) {
        int f4 = tid + l * 256;
        ar[l] = f4 >> 3; aseg[l] = f4 & 7;
        av[l] = (row0 + ar[l]) < M;
    }
    int brow[2], bseg[2];
    #pragma unroll
    for (int l = 0; l < 2; l++) { int f = tid + l * 256; brow[l] = f >> 4; bseg[l] = f & 15; }

    float acc[MT][4][4] = {};
    float4 pa[NL4]; uint4 pw[2];

    auto ldGA = [&](int k0) {
        #pragma unroll
        for (int l = 0; l < NL4; l++)
            pa[l] = av[l] ? *reinterpret_cast<const float4*>(&A[(size_t)(row0 + ar[l]) * K + k0 + aseg[l] * 4])
                          : make_float4(0.f, 0.f, 0.f, 0.f);
    };
    auto ldGB = [&](int k0) {
        #pragma unroll
        for (int l = 0; l < 2; l++)
            pw[l] = *reinterpret_cast<const uint4*>(&W[(size_t)(k0 + brow[l]) * N + col0 + bseg[l] * 8]);
    };
    auto stS = [&]() {
        #pragma unroll
        for (int l = 0; l < NL4; l++) {
            __half2 h0 = __floats2half2_rn(pa[l].x, pa[l].y);
            __half2 h1 = __floats2half2_rn(pa[l].z, pa[l].w);
            uint2 u; u.x = *reinterpret_cast<unsigned*>(&h0); u.y = *reinterpret_cast<unsigned*>(&h1);
            *reinterpret_cast<uint2*>(&As[ar[l] * LDA + aseg[l] * 4]) = u;
        }
        #pragma unroll
        for (int l = 0; l < 2; l++)
            *reinterpret_cast<uint4*>(&Bs[brow[l] * LDB + bseg[l] * 8]) = pw[l];
    };

    unsigned aaddr[MT], baddr[4];
    #pragma unroll
    for (int mt = 0; mt < MT; mt++)
        aaddr[mt] = smem_u32(&As[(wm * (BM / 2) + mt * 16 + (lane & 15)) * LDA + (lane >> 4) * 8]);
    #pragma unroll
    for (int nt = 0; nt < 4; nt++)
        baddr[nt] = smem_u32(&Bs[(lane & 15) * LDB + wn * 32 + nt * 8]);

    ldGA(0); ldGB(0);
    for (int k0 = 0;;) {
        stS();
        __syncthreads();
        int kn = k0 + 32;
        if (kn < K) { ldGA(kn); ldGB(kn); }
        #pragma unroll
        for (int ks = 0; ks < 2; ks++) {
            unsigned af[MT][4], bf[4][2];
            #pragma unroll
            for (int mt = 0; mt < MT; mt++) ldsm4(af[mt], aaddr[mt] + ks * 32);
            #pragma unroll
            for (int nt = 0; nt < 4; nt++) ldsm2t(bf[nt], baddr[nt] + ks * 16 * LDB * 2);
            #pragma unroll
            for (int mt = 0; mt < MT; mt++)
                #pragma unroll
                for (int nt = 0; nt < 4; nt++) mma16816(acc[mt][nt], af[mt], bf[nt]);
        }
        k0 = kn;
        if (k0 >= K) break;
        __syncthreads();
    }

    float tv = (act == 3) ? temp[0] : 0.f;
    int g = lane >> 2, tig = lane & 3;

    auto emit = [&](int r, int c, float v0, float v1) {
        if (r >= M) return;
        v0 += bias[c]; v1 += bias[c + 1];
        if (act == 0) {
            *reinterpret_cast<float2*>(&C[(size_t)r * N + c]) = make_float2(v0, v1);
        } else if (act == 1) {
            v0 = 0.5f * v0 * (1.f + erff(v0 * 0.70710678118654752f));
            v1 = 0.5f * v1 * (1.f + erff(v1 * 0.70710678118654752f));
            *reinterpret_cast<float2*>(&C[(size_t)r * N + c]) = make_float2(v0, v1);
        } else if (act == 2) {
            int n = r % N_OUT, b = r / N_OUT;
            int h = c >> 5, d = c & 31;
            float o0 = v0, o1 = v1;
            if (d < 16) {
                int j = d >> 1, s = j >> 2, p = j & 3;
                float coord = (s == 0) ? (float)(n / QG) * 3.0f : (float)(n % QG) * 3.0f;
                float ang = coord * freqs[(h * 2 + s) * 4 + p];
                float sn, cs; sincosf(ang, &sn, &cs);
                o0 = v0 * cs - v1 * sn;
                o1 = v0 * sn + v1 * cs;
            }
            *reinterpret_cast<__half2*>(&g_qh[((size_t)(b * NH + h) * N_OUT + n) * HDIM + d]) =
                __floats2half2_rn(o0, o1);
        } else {
            int n = r & (N_IN - 1), b = r >> 12;
            if (c < DM) {
                int h = c >> 5, d = c & 31;
                float o0 = v0, o1 = v1;
                if (d < 16) {
                    int j = d >> 1, s = j >> 2, p = j & 3;
                    float coord = (s == 0) ? (float)(n >> 6) : (float)(n & 63);
                    float ang = coord * freqs[(h * 2 + s) * 4 + p];
                    float sn, cs; sincosf(ang, &sn, &cs);
                    o0 = v0 * cs - v1 * sn;
                    o1 = v0 * sn + v1 * cs;
                }
                *reinterpret_cast<__half2*>(&g_kh[((size_t)(b * NH + h) * N_IN + n) * HDIM + d]) =
                    __floats2half2_rn(tv * o0, tv * o1);
            } else {
                int cc = c - DM;
                int h = cc >> 5, d = cc & 31;
                *reinterpret_cast<float2*>(&g_v[((size_t)(b * NH + h) * N_IN + n) * HDIM + d]) =
                    make_float2(v0, v1);
            }
        }
    };

    #pragma unroll
    for (int mt = 0; mt < MT; mt++) {
        #pragma unroll
        for (int nt = 0; nt < 4; nt++) {
            int r = row0 + wm * (BM / 2) + mt * 16 + g;
            int c = col0 + wn * 32 + nt * 8 + tig * 2;
            emit(r, c, acc[mt][nt][0], acc[mt][nt][1]);
            emit(r + 8, c, acc[mt][nt][2], acc[mt][nt][3]);
        }
    }
}

// ---------------- implicit-GEMM conv with HMMA, split-K=6, fp32 partials ----------------
__global__ __launch_bounds__(256) void conv_mma(const float* __restrict__ x) {
    __shared__ __half As[128 * LDA];
    __shared__ __half Bs[32 * LDB];
    int tid = threadIdx.x, lane = tid & 31, warp = tid >> 5;
    int wm = warp >> 2, wn = warp & 3;
    int row0 = blockIdx.y * 128, col0 = blockIdx.x * 128;
    int kbeg = blockIdx.z * CKLEN, kend = kbeg + CKLEN;

    int arow = tid >> 1, acb = (tid & 1) * 16;
    int agrow = row0 + arow;
    bool aval = agrow < NB * N_OUT;
    int g2 = aval ? agrow : 0;
    int rb = g2 / N_OUT;
    int nn = g2 - rb * N_OUT;
    int oy = nn / QG, ox = nn - oy * QG;

    int brow[2], bseg[2];
    #pragma unroll
    for (int l = 0; l < 2; l++) { int f = tid + l * 256; brow[l] = f >> 4; bseg[l] = f & 15; }

    float acc[4][4][4] = {};
    float4 pa[4]; uint4 pw[2];

    auto ldGA = [&](int k0) {
        int kk = k0 + acb;
        int t = kk / DM, ci = kk - t * DM;
        int ky = t / 7, kx = t - ky * 7;
        int iy = oy * 3 - 3 + ky, ix = ox * 3 - 3 + kx;
        bool ok = aval && (unsigned)iy < 64u && (unsigned)ix < 64u;
        const float* p = x + ((size_t)(rb * N_IN) + iy * 64 + ix) * DM + ci;
        #pragma unroll
        for (int j = 0; j < 4; j++)
            pa[j] = ok ? *reinterpret_cast<const float4*>(p + j * 4)
                       : make_float4(0.f, 0.f, 0.f, 0.f);
    };
    auto ldGB = [&](int k0) {
        #pragma unroll
        for (int l = 0; l < 2; l++)
            pw[l] = *reinterpret_cast<const uint4*>(&g_wt_h[(size_t)(k0 + brow[l]) * DM + col0 + bseg[l] * 8]);
    };
    auto stS = [&]() {
        __half2 h[8];
        #pragma unroll
        for (int j = 0; j < 4; j++) {
            h[2 * j]     = __floats2half2_rn(pa[j].x, pa[j].y);
            h[2 * j + 1] = __floats2half2_rn(pa[j].z, pa[j].w);
        }
        *reinterpret_cast<uint4*>(&As[arow * LDA + acb])     = *reinterpret_cast<uint4*>(&h[0]);
        *reinterpret_cast<uint4*>(&As[arow * LDA + acb + 8]) = *reinterpret_cast<uint4*>(&h[4]);
        #pragma unroll
        for (int l = 0; l < 2; l++)
            *reinterpret_cast<uint4*>(&Bs[brow[l] * LDB + bseg[l] * 8]) = pw[l];
    };

    unsigned aaddr[4], baddr[4];
    #pragma unroll
    for (int mt = 0; mt < 4; mt++)
        aaddr[mt] = smem_u32(&As[(wm * 64 + mt * 16 + (lane & 15)) * LDA + (lane >> 4) * 8]);
    #pragma unroll
    for (int nt = 0; nt < 4; nt++)
        baddr[nt] = smem_u32(&Bs[(lane & 15) * LDB + wn * 32 + nt * 8]);

    ldGA(kbeg); ldGB(kbeg);
    for (int k0 = kbeg;;) {
        stS();
        __syncthreads();
        int kn = k0 + 32;
        if (kn < kend) { ldGA(kn); ldGB(kn); }
        #pragma unroll
        for (int ks = 0; ks < 2; ks++) {
            unsigned af[4][4], bf[4][2];
            #pragma unroll
            for (int mt = 0; mt < 4; mt++) ldsm4(af[mt], aaddr[mt] + ks * 32);
            #pragma unroll
            for (int nt = 0; nt < 4; nt++) ldsm2t(bf[nt], baddr[nt] + ks * 16 * LDB * 2);
            #pragma unroll
            for (int mt = 0; mt < 4; mt++)
                #pragma unroll
                for (int nt = 0; nt < 4; nt++) mma16816(acc[mt][nt], af[mt], bf[nt]);
        }
        k0 = kn;
        if (k0 >= kend) break;
        __syncthreads();
    }

    float* out = g_convpart + (size_t)blockIdx.z * XOUT_SZ;
    int g = lane >> 2, tig = lane & 3;
    #pragma unroll
    for (int mt = 0; mt < 4; mt++) {
        #pragma unroll
        for (int nt = 0; nt < 4; nt++) {
            int r = row0 + wm * 64 + mt * 16 + g;
            int c = col0 + wn * 32 + nt * 8 + tig * 2;
            if (r < NB * N_OUT)
                *reinterpret_cast<float2*>(&out[(size_t)r * DM + c]) =
                    make_float2(acc[mt][nt][0], acc[mt][nt][1]);
            if (r + 8 < NB * N_OUT)
                *reinterpret_cast<float2*>(&out[(size_t)(r + 8) * DM + c]) =
                    make_float2(acc[mt][nt][2], acc[mt][nt][3]);
        }
    }
}

// ---------------- conv partial reduce + bias + LN -> g_xout ----------------
__global__ __launch_bounds__(384) void conv_ln_kernel(const float* __restrict__ cb,
                                                      const float* __restrict__ g,
                                                      const float* __restrict__ b) {
    __shared__ float sred[32];
    int row = blockIdx.x, tid = threadIdx.x;
    float v = cb[tid];
    #pragma unroll
    for (int s = 0; s < CSPLIT; s++) v += g_convpart[(size_t)s * XOUT_SZ + row * DM + tid];
    float mu = blockSum(v, sred) * (1.f / DM);
    float d = v - mu;
    float var = blockSum(d * d, sred) * (1.f / DM);
    float rs = rsqrtf(var + LN_EPS);
    g_xout[row * DM + tid] = d * rs * g[tid] + b[tid];
}

// ---------------- scores via HMMA, smem-staged e stores + per-tile row sums ----------------
__global__ __launch_bounds__(256) void scores_mma() {
    __shared__ __half Qs[64 * LDQ];
    __shared__ __half Ks[128 * LDQ];
    __shared__ __half Es[64 * LDE2];
    __shared__ float sred2[64 * 4];
    int tid = threadIdx.x, lane = tid & 31, warp = tid >> 5;
    int wm = warp >> 2, wn = warp & 3;
    int bh = blockIdx.z;
    int row0 = blockIdx.y * 64, col0 = blockIdx.x * 128;
    const __half* Qp = g_qh + (size_t)bh * N_OUT * HDIM;
    const __half* Kp = g_kh + (size_t)bh * N_IN * HDIM;
    __half* Ep = g_e + (size_t)bh * N_OUT * N_IN;

    {   // load Q tile (64 x 32)
        int r = tid >> 2, seg = tid & 3;
        uint4 v = (row0 + r < N_OUT)
            ? *reinterpret_cast<const uint4*>(&Qp[(size_t)(row0 + r) * HDIM + seg * 8])
            : make_uint4(0u, 0u, 0u, 0u);
        *reinterpret_cast<uint4*>(&Qs[r * LDQ + seg * 8]) = v;
    }
    #pragma unroll
    for (int l = 0; l < 2; l++) {  // load K tile (128 x 32)
        int f = tid + l * 256;
        int r = f >> 2, seg = f & 3;
        *reinterpret_cast<uint4*>(&Ks[r * LDQ + seg * 8]) =
            *reinterpret_cast<const uint4*>(&Kp[(size_t)(col0 + r) * HDIM + seg * 8]);
    }
    __syncthreads();

    float acc[2][4][4] = {};
    #pragma unroll
    for (int ks = 0; ks < 2; ks++) {
        unsigned af[2][4], bf[4][2];
        #pragma unroll
        for (int mt = 0; mt < 2; mt++)
            ldsm4(af[mt], smem_u32(&Qs[(wm * 32 + mt * 16 + (lane & 15)) * LDQ + (lane >> 4) * 8 + ks * 16]));
        #pragma unroll
        for (int nt = 0; nt < 4; nt++)
            ldsm2(bf[nt], smem_u32(&Ks[(wn * 32 + nt * 8 + (lane & 7)) * LDQ + ((lane >> 3) & 1) * 8 + ks * 16]));
        #pragma unroll
        for (int mt = 0; mt < 2; mt++)
            #pragma unroll
            for (int nt = 0; nt < 4; nt++) mma16816(acc[mt][nt], af[mt], bf[nt]);
    }

    int g = lane >> 2, tig = lane & 3;
    #pragma unroll
    for (int mt = 0; mt < 2; mt++) {
        float rp0 = 0.f, rp1 = 0.f;
        int rl = wm * 32 + mt * 16 + g;
        #pragma unroll
        for (int nt = 0; nt < 4; nt++) {
            float e0 = __expf(acc[mt][nt][0]), e1 = __expf(acc[mt][nt][1]);
            float e2 = __expf(acc[mt][nt][2]), e3 = __expf(acc[mt][nt][3]);
            int cl = wn * 32 + nt * 8 + tig * 2;
            *reinterpret_cast<__half2*>(&Es[rl * LDE2 + cl])       = __floats2half2_rn(e0, e1);
            *reinterpret_cast<__half2*>(&Es[(rl + 8) * LDE2 + cl]) = __floats2half2_rn(e2, e3);
            rp0 += e0 + e1;
            rp1 += e2 + e3;
        }
        rp0 += __shfl_xor_sync(0xffffffffu, rp0, 1);
        rp0 += __shfl_xor_sync(0xffffffffu, rp0, 2);
        rp1 += __shfl_xor_sync(0xffffffffu, rp1, 1);
        rp1 += __shfl_xor_sync(0xffffffffu, rp1, 2);
        if (tig == 0) {
            sred2[rl * 4 + wn] = rp0;
            sred2[(rl + 8) * 4 + wn] = rp1;
        }
    }
    __syncthreads();
    // coalesced write-out of the 64x128 e tile
    #pragma unroll
    for (int it = 0; it < 4; it++) {
        int f = it * 256 + tid;
        int r = f >> 4, s = f & 15;
        if (row0 + r < N_OUT)
            *reinterpret_cast<uint4*>(&Ep[(size_t)(row0 + r) * N_IN + col0 + s * 8]) =
                *reinterpret_cast<const uint4*>(&Es[r * LDE2 + s * 8]);
    }
    if (tid < 64) {
        int gr = row0 + tid;
        if (gr < N_OUT) {
            float s = sred2[tid * 4] + sred2[tid * 4 + 1] + sred2[tid * 4 + 2] + sred2[tid * 4 + 3];
            g_rowpart[(size_t)(bh * N_OUT + gr) * KT2 + blockIdx.x] = s;
        }
    }
}

// ---------------- fused: rinv + colinv + vci ----------------
__global__ __launch_bounds__(256) void colinv_fused() {
    __shared__ float rinv_s[N_OUT];
    __shared__ float cis[512];
    int bh = blockIdx.y, bx = blockIdx.x, tid = threadIdx.x;
    // phase A: rinv (redundant per bx; bx 0 publishes)
    for (int row = tid; row < N_OUT; row += 256) {
        const float4* p = reinterpret_cast<const float4*>(&g_rowpart[(size_t)(bh * N_OUT + row) * KT2]);
        float s = 0.f;
        #pragma unroll
        for (int j = 0; j < 8; j++) { float4 v = p[j]; s += (v.x + v.y) + (v.z + v.w); }
        float r = 1.f / s;
        rinv_s[row] = r;
        if (bx == 0) g_rinv[bh * N_OUT + row] = r;
    }
    __syncthreads();
    // phase B: colinv for 512 columns
    int k2 = bx * 256 + tid;
    const __half2* p = reinterpret_cast<const __half2*>(g_e + (size_t)bh * N_OUT * N_IN) + k2;
    float sx = 0.f, sy = 0.f;
    #pragma unroll 4
    for (int q = 0; q < N_OUT; q++) {
        float2 e = __half22float2(p[(size_t)q * (N_IN / 2)]);
        float r = rinv_s[q];
        sx += e.x * r;
        sy += e.y * r;
    }
    float cx = 1.f / (sx + EPSQ), cy = 1.f / (sy + EPSQ);
    g_colinv[bh * N_IN + 2 * k2]     = cx;
    g_colinv[bh * N_IN + 2 * k2 + 1] = cy;
    cis[2 * tid] = cx; cis[2 * tid + 1] = cy;
    __syncthreads();
    // phase C: vci = v * colinv (fp16) for these 512 k rows
    int base = bx * 512;
    #pragma unroll
    for (int it = 0; it < 32; it++) {
        int f = it * 256 + tid;
        int kk = f >> 4, d2 = (f & 15) * 2;
        float2 v = *reinterpret_cast<const float2*>(&g_v[((size_t)bh * N_IN + base + kk) * HDIM + d2]);
        float ci = cis[kk];
        *reinterpret_cast<__half2*>(&g_vci[((size_t)bh * N_IN + base + kk) * HDIM + d2]) =
            __floats2half2_rn(v.x * ci, v.y * ci);
    }
}

// ---------------- upd via HMMA: upd = rinv[q] * (e @ vci) ----------------
__global__ __launch_bounds__(256) void upd_mma() {
    __shared__ __half Es[128 * LDE];
    __shared__ __half Vs[64 * LDV];
    int tid = threadIdx.x, lane = tid & 31, warp = tid >> 5;
    int bh = blockIdx.y;
    int b = bh / NH, h = bh - b * NH;
    int q0 = blockIdx.x * 128;
    const __half* Ep = g_e + (size_t)bh * N_OUT * N_IN;
    const __half* Vp = g_vci + (size_t)bh * N_IN * HDIM;

    float acc[4][4] = {};
    for (int kt = 0; kt < N_IN; kt += 64) {
        #pragma unroll
        for (int l = 0; l < 4; l++) {
            int f = l * 256 + tid;
            int r = f >> 3, seg = f & 7;
            uint4 v = (q0 + r < N_OUT)
                ? *reinterpret_cast<const uint4*>(&Ep[(size_t)(q0 + r) * N_IN + kt + seg * 8])
                : make_uint4(0u, 0u, 0u, 0u);
            *reinterpret_cast<uint4*>(&Es[r * LDE + seg * 8]) = v;
        }
        {
            int r = tid >> 2, seg = tid & 3;
            *reinterpret_cast<uint4*>(&Vs[r * LDV + seg * 8]) =
                *reinterpret_cast<const uint4*>(&Vp[(size_t)(kt + r) * HDIM + seg * 8]);
        }
        __syncthreads();
        #pragma unroll
        for (int ks = 0; ks < 4; ks++) {
            unsigned af[4], bf[4][2];
            ldsm4(af, smem_u32(&Es[(warp * 16 + (lane & 15)) * LDE + (lane >> 4) * 8 + ks * 16]));
            #pragma unroll
            for (int nt = 0; nt < 4; nt++)
                ldsm2t(bf[nt], smem_u32(&Vs[((lane & 15) + ks * 16) * LDV + nt * 8]));
            #pragma unroll
            for (int nt = 0; nt < 4; nt++) mma16816(acc[nt], af, bf[nt]);
        }
        __syncthreads();
    }

    int g = lane >> 2, tig = lane & 3;
    int q = q0 + warp * 16 + g;
    if (q < N_OUT) {
        float rq = g_rinv[bh * N_OUT + q];
        float* dst = &g_upd[((size_t)(b * N_OUT) + q) * DM + h * HDIM];
        #pragma unroll
        for (int nt = 0; nt < 4; nt++)
            *reinterpret_cast<float2*>(&dst[nt * 8 + tig * 2]) =
                make_float2(acc[nt][0] * rq, acc[nt][1] * rq);
    }
    if (q + 8 < N_OUT) {
        float rq = g_rinv[bh * N_OUT + q + 8];
        float* dst = &g_upd[((size_t)(b * N_OUT) + q + 8) * DM + h * HDIM];
        #pragma unroll
        for (int nt = 0; nt < 4; nt++)
            *reinterpret_cast<float2*>(&dst[nt * 8 + tig * 2]) =
                make_float2(acc[nt][2] * rq, acc[nt][3] * rq);
    }
}

// ---------------- x_out += LN(src)*g + b ----------------
__global__ __launch_bounds__(384) void ln_add_kernel(const float* __restrict__ src,
                                                     const float* __restrict__ g,
                                                     const float* __restrict__ b) {
    __shared__ float sred[32];
    int row = blockIdx.x, tid = threadIdx.x;
    float v = src[row * DM + tid];
    float mu = blockSum(v, sred) * (1.f / DM);
    float d = v - mu;
    float var = blockSum(d * d, sred) * (1.f / DM);
    float rs = rsqrtf(var + LN_EPS);
    g_xout[row * DM + tid] += d * rs * g[tid] + b[tid];
}

// ---------------- finalize: attn_k = e*rinv ; attn_q = attn_k*colinv ----------------
__global__ __launch_bounds__(256) void finalize_kernel(float* __restrict__ attn_k,
                                                       float* __restrict__ attn_q) {
    int bh = blockIdx.z, q = blockIdx.y;
    int k4 = (blockIdx.x * 256 + threadIdx.x) * 4;
    size_t i = ((size_t)(bh * N_OUT + q) << 12) + k4;
    float r = g_rinv[bh * N_OUT + q];
    const __half2* ep = reinterpret_cast<const __half2*>(&g_e[i]);
    float2 e01 = __half22float2(ep[0]);
    float2 e23 = __half22float2(ep[1]);
    float4 ci = *reinterpret_cast<const float4*>(&g_colinv[bh * N_IN + k4]);
    float ak0 = e01.x * r, ak1 = e01.y * r, ak2 = e23.x * r, ak3 = e23.y * r;
    *reinterpret_cast<float4*>(&attn_k[i]) = make_float4(ak0, ak1, ak2, ak3);
    *reinterpret_cast<float4*>(&attn_q[i]) =
        make_float4(ak0 * ci.x, ak1 * ci.y, ak2 * ci.z, ak3 * ci.w);
}

// ---------------- copy x_out to d_out ----------------
__global__ __launch_bounds__(256) void copy_xout_kernel(float* __restrict__ out) {
    int i = blockIdx.x * 256 + threadIdx.x;
    out[i] = g_xout[i];
}

// ---------------- launch ----------------
extern "C" void kernel_launch(void* const* d_in, const int* in_sizes, int n_in,
                              void* d_out, int out_size) {
    const float* x      = (const float*)d_in[0];
    const float* conv_w = (const float*)d_in[1];
    const float* conv_b = (const float*)d_in[2];
    const float* kv_w   = (const float*)d_in[3];
    const float* kv_b   = (const float*)d_in[4];
    const float* q_w    = (const float*)d_in[5];
    const float* q_b    = (const float*)d_in[6];
    const float* mlp_w1 = (const float*)d_in[7];
    const float* mlp_b1 = (const float*)d_in[8];
    const float* mlp_w2 = (const float*)d_in[9];
    const float* mlp_b2 = (const float*)d_in[10];
    const float* g1     = (const float*)d_in[11];
    const float* b1     = (const float*)d_in[12];
    const float* g2     = (const float*)d_in[13];
    const float* b2     = (const float*)d_in[14];
    const float* g3     = (const float*)d_in[15];
    const float* b3     = (const float*)d_in[16];
    const float* temp   = (const float*)d_in[17];
    const float* freqs  = (const float*)d_in[18];

    float* out = (float*)d_out;
    float* attn_q_out = out + XOUT_SZ;
    float* attn_k_out = out + XOUT_SZ + ATTN_SZ;

    void *p_xout_, *p_mlp_, *p_mlpo_, *p_upd_;
    void *p_kvw_, *p_qw_, *p_w1_, *p_w2_;
    cudaGetSymbolAddress(&p_xout_, g_xout);
    cudaGetSymbolAddress(&p_mlp_, g_mlp);
    cudaGetSymbolAddress(&p_mlpo_, g_mlpo);
    cudaGetSymbolAddress(&p_upd_, g_upd);
    cudaGetSymbolAddress(&p_kvw_, g_kvw_h);
    cudaGetSymbolAddress(&p_qw_, g_qw_h);
    cudaGetSymbolAddress(&p_w1_, g_w1_h);
    cudaGetSymbolAddress(&p_w2_, g_w2_h);
    float* p_xout = (float*)p_xout_;
    float* p_mlp  = (float*)p_mlp_;
    float* p_mlpo = (float*)p_mlpo_;
    float* p_upd  = (float*)p_upd_;
    __half* p_kvw = (__half*)p_kvw_;
    __half* p_qw  = (__half*)p_qw_;
    __half* p_w1  = (__half*)p_w1_;
    __half* p_w2  = (__half*)p_w2_;

    // weight conversions (once per call)
    wt_transpose_kernel<<<dim3(12, 384), 256>>>(conv_w);
    f2h_kernel<<<(DM * 2 * DM / 4 + 255) / 256, 256>>>((const float4*)kv_w, (__half2*)p_kvw, DM * 2 * DM / 4);
    f2h_kernel<<<(DM * DM / 4 + 255) / 256, 256>>>((const float4*)q_w, (__half2*)p_qw, DM * DM / 4);
    f2h_kernel<<<(DM * 4 * DM / 4 + 255) / 256, 256>>>((const float4*)mlp_w1, (__half2*)p_w1, DM * 4 * DM / 4);
    f2h_kernel<<<(4 * DM * DM / 4 + 255) / 256, 256>>>((const float4*)mlp_w2, (__half2*)p_w2, 4 * DM * DM / 4);

    conv_mma<<<dim3(3, 8, CSPLIT), 256>>>(x);
    conv_ln_kernel<<<NB * N_OUT, 384>>>(conv_b, g1, b1);

    // loop-invariant kv with fused rose-K + V split (act=3)
    gemm_mma<128><<<dim3(6, 64), 256>>>(x, p_kvw, kv_b, nullptr, NB * N_IN, 2 * DM, DM, 3, freqs, temp);

    for (int it = 0; it < 3; it++) {
        // qlin with fused rose-Q (act=2)
        gemm_mma<64><<<dim3(3, 16), 256>>>(p_xout, p_qw, q_b, nullptr, NB * N_OUT, DM, DM, 2, freqs, temp);
        scores_mma<<<dim3(KT2, 8, BHTOT), 256>>>();
        colinv_fused<<<dim3(8, BHTOT), 256>>>();
        upd_mma<<<dim3(4, BHTOT), 256>>>();
        ln_add_kernel<<<NB * N_OUT, 384>>>(p_upd, g2, b2);
        gemm_mma<64><<<dim3(12, 16), 256>>>(p_xout, p_w1, mlp_b1, p_mlp, NB * N_OUT, 4 * DM, DM, 1, freqs, temp);
        gemm_mma<64><<<dim3(3, 16), 256>>>(p_mlp, p_w2, mlp_b2, p_mlpo, NB * N_OUT, DM, 4 * DM, 0, freqs, temp);
        ln_add_kernel<<<NB * N_OUT, 384>>>(p_mlpo, g3, b3);
    }

    finalize_kernel<<<dim3(4, N_OUT, BHTOT), 256>>>(attn_k_out, attn_q_out);
    copy_xout_kernel<<<XOUT_SZ / 256, 256>>>(out);
}

// round 11
// speedup vs baseline: 5.9477x; 1.5534x over previous
#include <cuda_runtime.h>
#include <cuda_bf16.h>
#include <cuda_fp16.h>
#include <math.h>

// ---------------- problem constants ----------------
#define NB 2
#define N_IN 4096
#define N_OUT 484
#define DM 384
#define NH 12
#define HDIM 32
#define QG 22
#define KCONV 18816
#define BHTOT (NB*NH)
#define XOUT_SZ (NB*N_OUT*DM)
#define ATTN_SZ ((size_t)NB*NH*N_OUT*N_IN)
#define NROWS (BHTOT*N_OUT)
#define CSPLIT 6
#define CKLEN (KCONV/CSPLIT)
#define EPSQ 1.1920929e-07f
#define LN_EPS 1e-5f

#define LDA 40
#define LDB 136
#define LDQ 40
#define LDV 40

// ---------------- scratch ----------------
__device__ __half g_wt_h[(size_t)KCONV*DM];
__device__ __half g_kvw_h[DM*2*DM];
__device__ __half g_qw_h[DM*DM];
__device__ __half g_w1_h[DM*4*DM];
__device__ __half g_w2_h[4*DM*DM];
__device__ float g_convpart[(size_t)CSPLIT*XOUT_SZ];
__device__ float g_xout[XOUT_SZ];
__device__ __half g_kh[(size_t)NB*NH*N_IN*HDIM];
__device__ float g_v[(size_t)NB*NH*N_IN*HDIM];
__device__ __half g_vci[(size_t)NB*NH*N_IN*HDIM];
__device__ __half g_qh[NB*NH*N_OUT*HDIM];
__device__ float g_colinv[BHTOT*N_IN];
__device__ float g_rinv[NROWS];
__device__ float g_upd[XOUT_SZ];
__device__ float g_mlp[NB*N_OUT*4*DM];
__device__ float g_mlpo[XOUT_SZ];

// ---------------- mma / ldmatrix helpers ----------------
__device__ __forceinline__ unsigned smem_u32(const void* p) {
    return (unsigned)__cvta_generic_to_shared(p);
}
__device__ __forceinline__ void ldsm4(unsigned* r, unsigned addr) {
    asm volatile("ldmatrix.sync.aligned.m8n8.x4.shared.b16 {%0,%1,%2,%3}, [%4];"
        : "=r"(r[0]), "=r"(r[1]), "=r"(r[2]), "=r"(r[3]) : "r"(addr));
}
__device__ __forceinline__ void ldsm2(unsigned* r, unsigned addr) {
    asm volatile("ldmatrix.sync.aligned.m8n8.x2.shared.b16 {%0,%1}, [%2];"
        : "=r"(r[0]), "=r"(r[1]) : "r"(addr));
}
__device__ __forceinline__ void ldsm2t(unsigned* r, unsigned addr) {
    asm volatile("ldmatrix.sync.aligned.m8n8.x2.trans.shared.b16 {%0,%1}, [%2];"
        : "=r"(r[0]), "=r"(r[1]) : "r"(addr));
}
__device__ __forceinline__ void mma16816(float* c, const unsigned* a, const unsigned* b) {
    asm volatile("mma.sync.aligned.m16n8k16.row.col.f32.f16.f16.f32 "
        "{%0,%1,%2,%3}, {%4,%5,%6,%7}, {%8,%9}, {%0,%1,%2,%3};"
        : "+f"(c[0]), "+f"(c[1]), "+f"(c[2]), "+f"(c[3])
        : "r"(a[0]), "r"(a[1]), "r"(a[2]), "r"(a[3]), "r"(b[0]), "r"(b[1]));
}
__device__ __forceinline__ unsigned packh2(float a, float b) {
    __half2 h = __floats2half2_rn(a, b);
    return *reinterpret_cast<unsigned*>(&h);
}

__device__ __forceinline__ float blockSum(float v, float* sred) {
    int tid = threadIdx.x, lane = tid & 31, wid = tid >> 5;
    #pragma unroll
    for (int o = 16; o; o >>= 1) v += __shfl_xor_sync(0xffffffffu, v, o);
    if (lane == 0) sred[wid] = v;
    __syncthreads();
    int nw = (blockDim.x + 31) >> 5;
    if (wid == 0) {
        float t = (lane < nw) ? sred[lane] : 0.f;
        #pragma unroll
        for (int o = 16; o; o >>= 1) t += __shfl_xor_sync(0xffffffffu, t, o);
        if (lane == 0) sred[0] = t;
    }
    __syncthreads();
    float r = sred[0];
    __syncthreads();
    return r;
}

// ---------------- weight fp32 -> fp16 ----------------
__global__ __launch_bounds__(256) void f2h_kernel(const float4* __restrict__ src,
                                                  __half2* __restrict__ dst, int n4) {
    int i = blockIdx.x * 256 + threadIdx.x;
    if (i < n4) {
        float4 v = src[i];
        dst[2 * i]     = __floats2half2_rn(v.x, v.y);
        dst[2 * i + 1] = __floats2half2_rn(v.z, v.w);
    }
}

// ---------------- conv weight transpose ----------------
__global__ __launch_bounds__(256) void wt_transpose_kernel(const float* __restrict__ conv_w) {
    __shared__ float s[32][50];
    int co0 = blockIdx.x * 32;
    int ci = blockIdx.y;
    int tid = threadIdx.x;
    for (int idx = tid; idx < 32 * 49; idx += 256) {
        int r = idx / 49, t = idx - r * 49;
        s[r][t] = conv_w[(size_t)(co0 + r) * KCONV + ci * 49 + t];
    }
    __syncthreads();
    for (int idx = tid; idx < 49 * 32; idx += 256) {
        int t = idx >> 5, c = idx & 31;
        g_wt_h[((size_t)(t * DM + ci)) * DM + co0 + c] = __float2half(s[c][t]);
    }
}

// ---------------- fp16 tensor-core GEMM, BM x 128 tile ----------------
// act: 0 = bias, 1 = bias+gelu, 2 = rose-Q -> g_qh, 3 = rose-KV -> g_kh/g_v
template<int BM>
__global__ __launch_bounds__(256) void gemm_mma(const float* __restrict__ A,
                                                const __half* __restrict__ W,
                                                const float* __restrict__ bias,
                                                float* __restrict__ C,
                                                int M, int N, int K, int act,
                                                const float* __restrict__ freqs,
                                                const float* __restrict__ temp) {
    constexpr int MT = BM / 32;
    constexpr int NL4 = BM / 32;
    __shared__ __half As[BM * LDA];
    __shared__ __half Bs[32 * LDB];
    int tid = threadIdx.x, lane = tid & 31, warp = tid >> 5;
    int wm = warp >> 2, wn = warp & 3;
    int row0 = blockIdx.y * BM, col0 = blockIdx.x * 128;

    int ar[NL4], aseg[NL4];
    bool av[NL4];
    #pragma unroll
    for (int l = 0; l < NL4; l++) {
        int f4 = tid + l * 256;
        ar[l] = f4 >> 3; aseg[l] = f4 & 7;
        av[l] = (row0 + ar[l]) < M;
    }
    int brow[2], bseg[2];
    #pragma unroll
    for (int l = 0; l < 2; l++) { int f = tid + l * 256; brow[l] = f >> 4; bseg[l] = f & 15; }

    float acc[MT][4][4] = {};
    float4 pa[NL4]; uint4 pw[2];

    auto ldGA = [&](int k0) {
        #pragma unroll
        for (int l = 0; l < NL4; l++)
            pa[l] = av[l] ? *reinterpret_cast<const float4*>(&A[(size_t)(row0 + ar[l]) * K + k0 + aseg[l] * 4])
                          : make_float4(0.f, 0.f, 0.f, 0.f);
    };
    auto ldGB = [&](int k0) {
        #pragma unroll
        for (int l = 0; l < 2; l++)
            pw[l] = *reinterpret_cast<const uint4*>(&W[(size_t)(k0 + brow[l]) * N + col0 + bseg[l] * 8]);
    };
    auto stS = [&]() {
        #pragma unroll
        for (int l = 0; l < NL4; l++) {
            uint2 u; u.x = packh2(pa[l].x, pa[l].y); u.y = packh2(pa[l].z, pa[l].w);
            *reinterpret_cast<uint2*>(&As[ar[l] * LDA + aseg[l] * 4]) = u;
        }
        #pragma unroll
        for (int l = 0; l < 2; l++)
            *reinterpret_cast<uint4*>(&Bs[brow[l] * LDB + bseg[l] * 8]) = pw[l];
    };

    unsigned aaddr[MT], baddr[4];
    #pragma unroll
    for (int mt = 0; mt < MT; mt++)
        aaddr[mt] = smem_u32(&As[(wm * (BM / 2) + mt * 16 + (lane & 15)) * LDA + (lane >> 4) * 8]);
    #pragma unroll
    for (int nt = 0; nt < 4; nt++)
        baddr[nt] = smem_u32(&Bs[(lane & 15) * LDB + wn * 32 + nt * 8]);

    ldGA(0); ldGB(0);
    for (int k0 = 0;;) {
        stS();
        __syncthreads();
        int kn = k0 + 32;
        if (kn < K) { ldGA(kn); ldGB(kn); }
        #pragma unroll
        for (int ks = 0; ks < 2; ks++) {
            unsigned af[MT][4], bf[4][2];
            #pragma unroll
            for (int mt = 0; mt < MT; mt++) ldsm4(af[mt], aaddr[mt] + ks * 32);
            #pragma unroll
            for (int nt = 0; nt < 4; nt++) ldsm2t(bf[nt], baddr[nt] + ks * 16 * LDB * 2);
            #pragma unroll
            for (int mt = 0; mt < MT; mt++)
                #pragma unroll
                for (int nt = 0; nt < 4; nt++) mma16816(acc[mt][nt], af[mt], bf[nt]);
        }
        k0 = kn;
        if (k0 >= K) break;
        __syncthreads();
    }

    float tv = (act == 3) ? temp[0] : 0.f;
    int g = lane >> 2, tig = lane & 3;

    auto emit = [&](int r, int c, float v0, float v1) {
        if (r >= M) return;
        v0 += bias[c]; v1 += bias[c + 1];
        if (act == 0) {
            *reinterpret_cast<float2*>(&C[(size_t)r * N + c]) = make_float2(v0, v1);
        } else if (act == 1) {
            v0 = 0.5f * v0 * (1.f + erff(v0 * 0.70710678118654752f));
            v1 = 0.5f * v1 * (1.f + erff(v1 * 0.70710678118654752f));
            *reinterpret_cast<float2*>(&C[(size_t)r * N + c]) = make_float2(v0, v1);
        } else if (act == 2) {
            int n = r % N_OUT, b = r / N_OUT;
            int h = c >> 5, d = c & 31;
            float o0 = v0, o1 = v1;
            if (d < 16) {
                int j = d >> 1, s = j >> 2, p = j & 3;
                float coord = (s == 0) ? (float)(n / QG) * 3.0f : (float)(n % QG) * 3.0f;
                float ang = coord * freqs[(h * 2 + s) * 4 + p];
                float sn, cs; sincosf(ang, &sn, &cs);
                o0 = v0 * cs - v1 * sn;
                o1 = v0 * sn + v1 * cs;
            }
            *reinterpret_cast<__half2*>(&g_qh[((size_t)(b * NH + h) * N_OUT + n) * HDIM + d]) =
                __floats2half2_rn(o0, o1);
        } else {
            int n = r & (N_IN - 1), b = r >> 12;
            if (c < DM) {
                int h = c >> 5, d = c & 31;
                float o0 = v0, o1 = v1;
                if (d < 16) {
                    int j = d >> 1, s = j >> 2, p = j & 3;
                    float coord = (s == 0) ? (float)(n >> 6) : (float)(n & 63);
                    float ang = coord * freqs[(h * 2 + s) * 4 + p];
                    float sn, cs; sincosf(ang, &sn, &cs);
                    o0 = v0 * cs - v1 * sn;
                    o1 = v0 * sn + v1 * cs;
                }
                *reinterpret_cast<__half2*>(&g_kh[((size_t)(b * NH + h) * N_IN + n) * HDIM + d]) =
                    __floats2half2_rn(tv * o0, tv * o1);
            } else {
                int cc = c - DM;
                int h = cc >> 5, d = cc & 31;
                *reinterpret_cast<float2*>(&g_v[((size_t)(b * NH + h) * N_IN + n) * HDIM + d]) =
                    make_float2(v0, v1);
            }
        }
    };

    #pragma unroll
    for (int mt = 0; mt < MT; mt++) {
        #pragma unroll
        for (int nt = 0; nt < 4; nt++) {
            int r = row0 + wm * (BM / 2) + mt * 16 + g;
            int c = col0 + wn * 32 + nt * 8 + tig * 2;
            emit(r, c, acc[mt][nt][0], acc[mt][nt][1]);
            emit(r + 8, c, acc[mt][nt][2], acc[mt][nt][3]);
        }
    }
}

// ---------------- implicit-GEMM conv with HMMA, split-K=6 ----------------
__global__ __launch_bounds__(256) void conv_mma(const float* __restrict__ x) {
    __shared__ __half As[128 * LDA];
    __shared__ __half Bs[32 * LDB];
    int tid = threadIdx.x, lane = tid & 31, warp = tid >> 5;
    int wm = warp >> 2, wn = warp & 3;
    int row0 = blockIdx.y * 128, col0 = blockIdx.x * 128;
    int kbeg = blockIdx.z * CKLEN, kend = kbeg + CKLEN;

    int arow = tid >> 1, acb = (tid & 1) * 16;
    int agrow = row0 + arow;
    bool aval = agrow < NB * N_OUT;
    int g2 = aval ? agrow : 0;
    int rb = g2 / N_OUT;
    int nn = g2 - rb * N_OUT;
    int oy = nn / QG, ox = nn - oy * QG;

    int brow[2], bseg[2];
    #pragma unroll
    for (int l = 0; l < 2; l++) { int f = tid + l * 256; brow[l] = f >> 4; bseg[l] = f & 15; }

    float acc[4][4][4] = {};
    float4 pa[4]; uint4 pw[2];

    auto ldGA = [&](int k0) {
        int kk = k0 + acb;
        int t = kk / DM, ci = kk - t * DM;
        int ky = t / 7, kx = t - ky * 7;
        int iy = oy * 3 - 3 + ky, ix = ox * 3 - 3 + kx;
        bool ok = aval && (unsigned)iy < 64u && (unsigned)ix < 64u;
        const float* p = x + ((size_t)(rb * N_IN) + iy * 64 + ix) * DM + ci;
        #pragma unroll
        for (int j = 0; j < 4; j++)
            pa[j] = ok ? *reinterpret_cast<const float4*>(p + j * 4)
                       : make_float4(0.f, 0.f, 0.f, 0.f);
    };
    auto ldGB = [&](int k0) {
        #pragma unroll
        for (int l = 0; l < 2; l++)
            pw[l] = *reinterpret_cast<const uint4*>(&g_wt_h[(size_t)(k0 + brow[l]) * DM + col0 + bseg[l] * 8]);
    };
    auto stS = [&]() {
        __half2 h[8];
        #pragma unroll
        for (int j = 0; j < 4; j++) {
            h[2 * j]     = __floats2half2_rn(pa[j].x, pa[j].y);
            h[2 * j + 1] = __floats2half2_rn(pa[j].z, pa[j].w);
        }
        *reinterpret_cast<uint4*>(&As[arow * LDA + acb])     = *reinterpret_cast<uint4*>(&h[0]);
        *reinterpret_cast<uint4*>(&As[arow * LDA + acb + 8]) = *reinterpret_cast<uint4*>(&h[4]);
        #pragma unroll
        for (int l = 0; l < 2; l++)
            *reinterpret_cast<uint4*>(&Bs[brow[l] * LDB + bseg[l] * 8]) = pw[l];
    };

    unsigned aaddr[4], baddr[4];
    #pragma unroll
    for (int mt = 0; mt < 4; mt++)
        aaddr[mt] = smem_u32(&As[(wm * 64 + mt * 16 + (lane & 15)) * LDA + (lane >> 4) * 8]);
    #pragma unroll
    for (int nt = 0; nt < 4; nt++)
        baddr[nt] = smem_u32(&Bs[(lane & 15) * LDB + wn * 32 + nt * 8]);

    ldGA(kbeg); ldGB(kbeg);
    for (int k0 = kbeg;;) {
        stS();
        __syncthreads();
        int kn = k0 + 32;
        if (kn < kend) { ldGA(kn); ldGB(kn); }
        #pragma unroll
        for (int ks = 0; ks < 2; ks++) {
            unsigned af[4][4], bf[4][2];
            #pragma unroll
            for (int mt = 0; mt < 4; mt++) ldsm4(af[mt], aaddr[mt] + ks * 32);
            #pragma unroll
            for (int nt = 0; nt < 4; nt++) ldsm2t(bf[nt], baddr[nt] + ks * 16 * LDB * 2);
            #pragma unroll
            for (int mt = 0; mt < 4; mt++)
                #pragma unroll
                for (int nt = 0; nt < 4; nt++) mma16816(acc[mt][nt], af[mt], bf[nt]);
        }
        k0 = kn;
        if (k0 >= kend) break;
        __syncthreads();
    }

    float* out = g_convpart + (size_t)blockIdx.z * XOUT_SZ;
    int g = lane >> 2, tig = lane & 3;
    #pragma unroll
    for (int mt = 0; mt < 4; mt++) {
        #pragma unroll
        for (int nt = 0; nt < 4; nt++) {
            int r = row0 + wm * 64 + mt * 16 + g;
            int c = col0 + wn * 32 + nt * 8 + tig * 2;
            if (r < NB * N_OUT)
                *reinterpret_cast<float2*>(&out[(size_t)r * DM + c]) =
                    make_float2(acc[mt][nt][0], acc[mt][nt][1]);
            if (r + 8 < NB * N_OUT)
                *reinterpret_cast<float2*>(&out[(size_t)(r + 8) * DM + c]) =
                    make_float2(acc[mt][nt][2], acc[mt][nt][3]);
        }
    }
}

// ---------------- conv partial reduce + bias + LN ----------------
__global__ __launch_bounds__(384) void conv_ln_kernel(const float* __restrict__ cb,
                                                      const float* __restrict__ g,
                                                      const float* __restrict__ b) {
    __shared__ float sred[32];
    int row = blockIdx.x, tid = threadIdx.x;
    float v = cb[tid];
    #pragma unroll
    for (int s = 0; s < CSPLIT; s++) v += g_convpart[(size_t)s * XOUT_SZ + row * DM + tid];
    float mu = blockSum(v, sred) * (1.f / DM);
    float d = v - mu;
    float var = blockSum(d * d, sred) * (1.f / DM);
    float rs = rsqrtf(var + LN_EPS);
    g_xout[row * DM + tid] = d * rs * g[tid] + b[tid];
}

// ---------------- rowsum: rinv = 1/sum_k exp(q.k), no e store ----------------
// block = (qtile of 64, bh); sweeps all k in 128-chunks. warps 2m x 4n.
__global__ __launch_bounds__(256) void rowsum_mma() {
    __shared__ __half Qs[64 * LDQ];
    __shared__ __half Ks[128 * LDQ];
    __shared__ float sred2[64 * 4];
    int tid = threadIdx.x, lane = tid & 31, warp = tid >> 5;
    int wm = warp >> 2, wn = warp & 3;
    int bh = blockIdx.y;
    int row0 = blockIdx.x * 64;
    const __half* Qp = g_qh + (size_t)bh * N_OUT * HDIM;
    const __half* Kp = g_kh + (size_t)bh * N_IN * HDIM;

    {   // Q tile once
        int r = tid >> 2, seg = tid & 3;
        uint4 v = (row0 + r < N_OUT)
            ? *reinterpret_cast<const uint4*>(&Qp[(size_t)(row0 + r) * HDIM + seg * 8])
            : make_uint4(0u, 0u, 0u, 0u);
        *reinterpret_cast<uint4*>(&Qs[r * LDQ + seg * 8]) = v;
    }

    int kr[2], kseg[2];
    #pragma unroll
    for (int l = 0; l < 2; l++) { int f = tid + l * 256; kr[l] = f >> 2; kseg[l] = f & 3; }
    uint4 pk[2];
    auto ldK = [&](int kc) {
        #pragma unroll
        for (int l = 0; l < 2; l++)
            pk[l] = *reinterpret_cast<const uint4*>(&Kp[(size_t)(kc + kr[l]) * HDIM + kseg[l] * 8]);
    };

    float rp[2][2] = {};   // [mt][row g / g+8]
    ldK(0);
    for (int kc = 0;;) {
        #pragma unroll
        for (int l = 0; l < 2; l++)
            *reinterpret_cast<uint4*>(&Ks[kr[l] * LDQ + kseg[l] * 8]) = pk[l];
        __syncthreads();
        int kn = kc + 128;
        if (kn < N_IN) ldK(kn);

        float sacc[2][4][4] = {};
        #pragma unroll
        for (int ks = 0; ks < 2; ks++) {
            unsigned af[2][4], bf[4][2];
            #pragma unroll
            for (int mt = 0; mt < 2; mt++)
                ldsm4(af[mt], smem_u32(&Qs[(wm * 32 + mt * 16 + (lane & 15)) * LDQ + (lane >> 4) * 8 + ks * 16]));
            #pragma unroll
            for (int nt = 0; nt < 4; nt++)
                ldsm2(bf[nt], smem_u32(&Ks[(wn * 32 + nt * 8 + (lane & 7)) * LDQ + ((lane >> 3) & 1) * 8 + ks * 16]));
            #pragma unroll
            for (int mt = 0; mt < 2; mt++)
                #pragma unroll
                for (int nt = 0; nt < 4; nt++) mma16816(sacc[mt][nt], af[mt], bf[nt]);
        }
        #pragma unroll
        for (int mt = 0; mt < 2; mt++)
            #pragma unroll
            for (int nt = 0; nt < 4; nt++) {
                rp[mt][0] += __expf(sacc[mt][nt][0]) + __expf(sacc[mt][nt][1]);
                rp[mt][1] += __expf(sacc[mt][nt][2]) + __expf(sacc[mt][nt][3]);
            }
        kc = kn;
        if (kc >= N_IN) break;
        __syncthreads();
    }

    int g = lane >> 2, tig = lane & 3;
    #pragma unroll
    for (int mt = 0; mt < 2; mt++) {
        float r0 = rp[mt][0], r1 = rp[mt][1];
        r0 += __shfl_xor_sync(0xffffffffu, r0, 1);
        r0 += __shfl_xor_sync(0xffffffffu, r0, 2);
        r1 += __shfl_xor_sync(0xffffffffu, r1, 1);
        r1 += __shfl_xor_sync(0xffffffffu, r1, 2);
        if (tig == 0) {
            int rl = wm * 32 + mt * 16 + g;
            sred2[rl * 4 + wn] = r0;
            sred2[(rl + 8) * 4 + wn] = r1;
        }
    }
    __syncthreads();
    if (tid < 64) {
        int gr = row0 + tid;
        if (gr < N_OUT) {
            float s = sred2[tid * 4] + sred2[tid * 4 + 1] + sred2[tid * 4 + 2] + sred2[tid * 4 + 3];
            g_rinv[bh * N_OUT + gr] = 1.f / s;
        }
    }
}

// ---------------- colinv: recompute e, colinv = 1/(sum_q e*rinv + eps); vci ----------------
// block = (ktile of 128, bh); sweeps all q in 64-chunks.
__global__ __launch_bounds__(256) void colinv_mma() {
    __shared__ __half Ks[128 * LDQ];
    __shared__ __half Qs[64 * LDQ];
    __shared__ float rinv_s[512];
    __shared__ float csum[2][128];
    __shared__ float cis[128];
    int tid = threadIdx.x, lane = tid & 31, warp = tid >> 5;
    int wm = warp >> 2, wn = warp & 3;
    int bh = blockIdx.y;
    int k0 = blockIdx.x * 128;
    const __half* Qp = g_qh + (size_t)bh * N_OUT * HDIM;
    const __half* Kp = g_kh + (size_t)bh * N_IN * HDIM;

    for (int i = tid; i < 512; i += 256)
        rinv_s[i] = (i < N_OUT) ? g_rinv[bh * N_OUT + i] : 0.f;
    #pragma unroll
    for (int l = 0; l < 2; l++) {
        int f = tid + l * 256;
        int r = f >> 2, seg = f & 3;
        *reinterpret_cast<uint4*>(&Ks[r * LDQ + seg * 8]) =
            *reinterpret_cast<const uint4*>(&Kp[(size_t)(k0 + r) * HDIM + seg * 8]);
    }

    int qr = tid >> 2, qseg = tid & 3;
    uint4 pq;
    auto ldQ = [&](int qc) {
        int row = qc + qr;
        pq = (row < N_OUT)
            ? *reinterpret_cast<const uint4*>(&Qp[(size_t)row * HDIM + qseg * 8])
            : make_uint4(0u, 0u, 0u, 0u);
    };

    float ca[4][2] = {};
    int g = lane >> 2;
    ldQ(0);
    __syncthreads();
    for (int qc = 0;;) {
        *reinterpret_cast<uint4*>(&Qs[qr * LDQ + qseg * 8]) = pq;
        __syncthreads();
        int qn = qc + 64;
        if (qn < N_OUT) ldQ(qn);

        float sacc[2][4][4] = {};
        #pragma unroll
        for (int ks = 0; ks < 2; ks++) {
            unsigned af[2][4], bf[4][2];
            #pragma unroll
            for (int mt = 0; mt < 2; mt++)
                ldsm4(af[mt], smem_u32(&Qs[(wm * 32 + mt * 16 + (lane & 15)) * LDQ + (lane >> 4) * 8 + ks * 16]));
            #pragma unroll
            for (int nt = 0; nt < 4; nt++)
                ldsm2(bf[nt], smem_u32(&Ks[(wn * 32 + nt * 8 + (lane & 7)) * LDQ + ((lane >> 3) & 1) * 8 + ks * 16]));
            #pragma unroll
            for (int mt = 0; mt < 2; mt++)
                #pragma unroll
                for (int nt = 0; nt < 4; nt++) mma16816(sacc[mt][nt], af[mt], bf[nt]);
        }
        #pragma unroll
        for (int mt = 0; mt < 2; mt++) {
            float rv0 = rinv_s[qc + wm * 32 + mt * 16 + g];
            float rv8 = rinv_s[qc + wm * 32 + mt * 16 + g + 8];
            #pragma unroll
            for (int nt = 0; nt < 4; nt++) {
                ca[nt][0] += __expf(sacc[mt][nt][0]) * rv0 + __expf(sacc[mt][nt][2]) * rv8;
                ca[nt][1] += __expf(sacc[mt][nt][1]) * rv0 + __expf(sacc[mt][nt][3]) * rv8;
            }
        }
        qc = qn;
        if (qc >= N_OUT) break;
        __syncthreads();
    }

    // reduce over g (lanes sharing tig)
    #pragma unroll
    for (int nt = 0; nt < 4; nt++)
        #pragma unroll
        for (int j = 0; j < 2; j++) {
            float v = ca[nt][j];
            v += __shfl_xor_sync(0xffffffffu, v, 4);
            v += __shfl_xor_sync(0xffffffffu, v, 8);
            v += __shfl_xor_sync(0xffffffffu, v, 16);
            ca[nt][j] = v;
        }
    if (lane < 4) {
        int tig = lane;
        #pragma unroll
        for (int nt = 0; nt < 4; nt++) {
            int col = wn * 32 + nt * 8 + tig * 2;
            csum[wm][col] = ca[nt][0];
            csum[wm][col + 1] = ca[nt][1];
        }
    }
    __syncthreads();
    if (tid < 128) {
        float t = csum[0][tid] + csum[1][tid];
        float ci = 1.f / (t + EPSQ);
        g_colinv[bh * N_IN + k0 + tid] = ci;
        cis[tid] = ci;
    }
    __syncthreads();
    // vci = v * colinv, fp16, for these 128 k rows
    #pragma unroll
    for (int it = 0; it < 8; it++) {
        int f = it * 256 + tid;           // half2 index over 128x16
        int kk = f >> 4, d2 = (f & 15) * 2;
        float2 v = *reinterpret_cast<const float2*>(&g_v[((size_t)bh * N_IN + k0 + kk) * HDIM + d2]);
        float ci = cis[kk];
        *reinterpret_cast<__half2*>(&g_vci[((size_t)bh * N_IN + k0 + kk) * HDIM + d2]) =
            __floats2half2_rn(v.x * ci, v.y * ci);
    }
}

// ---------------- upd: recompute e, upd = rinv*(e @ vci); FINAL also writes attn ----------------
// block = (qblock of 128, bh); 8 warps, warp w owns rows [w*16, w*16+16).
template<bool FINAL>
__global__ __launch_bounds__(256) void upd_mma2(float* __restrict__ attn_k,
                                                float* __restrict__ attn_q) {
    __shared__ __half Qs[128 * LDQ];
    __shared__ __half Ks[64 * LDQ];
    __shared__ __half Vs[64 * LDV];
    __shared__ float rinv_s[128];
    __shared__ float cinv_s[64];
    int tid = threadIdx.x, lane = tid & 31, warp = tid >> 5;
    int bh = blockIdx.y;
    int b = bh / NH, h = bh - b * NH;
    int q0 = blockIdx.x * 128;
    const __half* Qp = g_qh + (size_t)bh * N_OUT * HDIM;
    const __half* Kp = g_kh + (size_t)bh * N_IN * HDIM;
    const __half* Vp = g_vci + (size_t)bh * N_IN * HDIM;

    #pragma unroll
    for (int l = 0; l < 2; l++) {
        int f = tid + l * 256;
        int r = f >> 2, seg = f & 3;
        uint4 v = (q0 + r < N_OUT)
            ? *reinterpret_cast<const uint4*>(&Qp[(size_t)(q0 + r) * HDIM + seg * 8])
            : make_uint4(0u, 0u, 0u, 0u);
        *reinterpret_cast<uint4*>(&Qs[r * LDQ + seg * 8]) = v;
    }
    if (tid < 128)
        rinv_s[tid] = (q0 + tid < N_OUT) ? g_rinv[bh * N_OUT + q0 + tid] : 0.f;

    int cr = tid >> 2, cseg = tid & 3;
    uint4 pk, pv; float pc = 0.f;
    auto ldch = [&](int kt) {
        pk = *reinterpret_cast<const uint4*>(&Kp[(size_t)(kt + cr) * HDIM + cseg * 8]);
        pv = *reinterpret_cast<const uint4*>(&Vp[(size_t)(kt + cr) * HDIM + cseg * 8]);
        if (FINAL && tid < 64) pc = g_colinv[bh * N_IN + kt + tid];
    };

    float acc[4][4] = {};
    int g = lane >> 2, tig = lane & 3;
    ldch(0);
    __syncthreads();
    for (int kt = 0;;) {
        *reinterpret_cast<uint4*>(&Ks[cr * LDQ + cseg * 8]) = pk;
        *reinterpret_cast<uint4*>(&Vs[cr * LDV + cseg * 8]) = pv;
        if (FINAL && tid < 64) cinv_s[tid] = pc;
        __syncthreads();
        int kn = kt + 64;
        if (kn < N_IN) ldch(kn);

        // S = Q(16x32) . K^T(64) per warp
        unsigned af[2][4];
        #pragma unroll
        for (int ks = 0; ks < 2; ks++)
            ldsm4(af[ks], smem_u32(&Qs[(warp * 16 + (lane & 15)) * LDQ + (lane >> 4) * 8 + ks * 16]));
        float e[8][4];
        #pragma unroll
        for (int nt8 = 0; nt8 < 8; nt8++) {
            float sacc[4] = {};
            #pragma unroll
            for (int ks = 0; ks < 2; ks++) {
                unsigned bf[2];
                ldsm2(bf, smem_u32(&Ks[(nt8 * 8 + (lane & 7)) * LDQ + ((lane >> 3) & 1) * 8 + ks * 16]));
                mma16816(sacc, af[ks], bf);
            }
            #pragma unroll
            for (int j = 0; j < 4; j++) e[nt8][j] = __expf(sacc[j]);
        }

        if (FINAL) {
            int r = q0 + warp * 16 + g;
            float rv0 = rinv_s[warp * 16 + g];
            float rv8 = rinv_s[warp * 16 + g + 8];
            #pragma unroll
            for (int nt8 = 0; nt8 < 8; nt8++) {
                int kc = nt8 * 8 + tig * 2;
                int k = kt + kc;
                float c0 = cinv_s[kc], c1 = cinv_s[kc + 1];
                if (r < N_OUT) {
                    float ak0 = e[nt8][0] * rv0, ak1 = e[nt8][1] * rv0;
                    size_t i = ((size_t)(bh * N_OUT + r) << 12) + k;
                    *reinterpret_cast<float2*>(&attn_k[i]) = make_float2(ak0, ak1);
                    *reinterpret_cast<float2*>(&attn_q[i]) = make_float2(ak0 * c0, ak1 * c1);
                }
                if (r + 8 < N_OUT) {
                    float ak2 = e[nt8][2] * rv8, ak3 = e[nt8][3] * rv8;
                    size_t i = ((size_t)(bh * N_OUT + r + 8) << 12) + k;
                    *reinterpret_cast<float2*>(&attn_k[i]) = make_float2(ak2, ak3);
                    *reinterpret_cast<float2*>(&attn_q[i]) = make_float2(ak2 * c0, ak3 * c1);
                }
            }
        }

        // second mma: acc += e(16x64) @ vci(64x32)
        #pragma unroll
        for (int kg = 0; kg < 4; kg++) {
            unsigned a2[4];
            a2[0] = packh2(e[2 * kg][0], e[2 * kg][1]);
            a2[1] = packh2(e[2 * kg][2], e[2 * kg][3]);
            a2[2] = packh2(e[2 * kg + 1][0], e[2 * kg + 1][1]);
            a2[3] = packh2(e[2 * kg + 1][2], e[2 * kg + 1][3]);
            #pragma unroll
            for (int nt = 0; nt < 4; nt++) {
                unsigned bf[2];
                ldsm2t(bf, smem_u32(&Vs[((lane & 15) + kg * 16) * LDV + nt * 8]));
                mma16816(acc[nt], a2, bf);
            }
        }
        kt = kn;
        if (kt >= N_IN) break;
        __syncthreads();
    }

    int q = q0 + warp * 16 + g;
    if (q < N_OUT) {
        float rq = rinv_s[warp * 16 + g];
        float* dst = &g_upd[((size_t)(b * N_OUT) + q) * DM + h * HDIM];
        #pragma unroll
        for (int nt = 0; nt < 4; nt++)
            *reinterpret_cast<float2*>(&dst[nt * 8 + tig * 2]) =
                make_float2(acc[nt][0] * rq, acc[nt][1] * rq);
    }
    if (q + 8 < N_OUT) {
        float rq = rinv_s[warp * 16 + g + 8];
        float* dst = &g_upd[((size_t)(b * N_OUT) + q + 8) * DM + h * HDIM];
        #pragma unroll
        for (int nt = 0; nt < 4; nt++)
            *reinterpret_cast<float2*>(&dst[nt * 8 + tig * 2]) =
                make_float2(acc[nt][2] * rq, acc[nt][3] * rq);
    }
}

// ---------------- dst = g_xout + LN(src)*g + b ----------------
__global__ __launch_bounds__(384) void ln_add_kernel(const float* __restrict__ src,
                                                     const float* __restrict__ g,
                                                     const float* __restrict__ b,
                                                     float* __restrict__ dst) {
    __shared__ float sred[32];
    int row = blockIdx.x, tid = threadIdx.x;
    float v = src[row * DM + tid];
    float mu = blockSum(v, sred) * (1.f / DM);
    float d = v - mu;
    float var = blockSum(d * d, sred) * (1.f / DM);
    float rs = rsqrtf(var + LN_EPS);
    dst[row * DM + tid] = g_xout[row * DM + tid] + d * rs * g[tid] + b[tid];
}

// ---------------- launch ----------------
extern "C" void kernel_launch(void* const* d_in, const int* in_sizes, int n_in,
                              void* d_out, int out_size) {
    const float* x      = (const float*)d_in[0];
    const float* conv_w = (const float*)d_in[1];
    const float* conv_b = (const float*)d_in[2];
    const float* kv_w   = (const float*)d_in[3];
    const float* kv_b   = (const float*)d_in[4];
    const float* q_w    = (const float*)d_in[5];
    const float* q_b    = (const float*)d_in[6];
    const float* mlp_w1 = (const float*)d_in[7];
    const float* mlp_b1 = (const float*)d_in[8];
    const float* mlp_w2 = (const float*)d_in[9];
    const float* mlp_b2 = (const float*)d_in[10];
    const float* g1     = (const float*)d_in[11];
    const float* b1     = (const float*)d_in[12];
    const float* g2     = (const float*)d_in[13];
    const float* b2     = (const float*)d_in[14];
    const float* g3     = (const float*)d_in[15];
    const float* b3     = (const float*)d_in[16];
    const float* temp   = (const float*)d_in[17];
    const float* freqs  = (const float*)d_in[18];

    float* out = (float*)d_out;
    float* attn_q_out = out + XOUT_SZ;
    float* attn_k_out = out + XOUT_SZ + ATTN_SZ;

    void *p_xout_, *p_mlp_, *p_mlpo_, *p_upd_;
    void *p_kvw_, *p_qw_, *p_w1_, *p_w2_;
    cudaGetSymbolAddress(&p_xout_, g_xout);
    cudaGetSymbolAddress(&p_mlp_, g_mlp);
    cudaGetSymbolAddress(&p_mlpo_, g_mlpo);
    cudaGetSymbolAddress(&p_upd_, g_upd);
    cudaGetSymbolAddress(&p_kvw_, g_kvw_h);
    cudaGetSymbolAddress(&p_qw_, g_qw_h);
    cudaGetSymbolAddress(&p_w1_, g_w1_h);
    cudaGetSymbolAddress(&p_w2_, g_w2_h);
    float* p_xout = (float*)p_xout_;
    float* p_mlp  = (float*)p_mlp_;
    float* p_mlpo = (float*)p_mlpo_;
    float* p_upd  = (float*)p_upd_;
    __half* p_kvw = (__half*)p_kvw_;
    __half* p_qw  = (__half*)p_qw_;
    __half* p_w1  = (__half*)p_w1_;
    __half* p_w2  = (__half*)p_w2_;

    // weight conversions (once per call)
    wt_transpose_kernel<<<dim3(12, 384), 256>>>(conv_w);
    f2h_kernel<<<(DM * 2 * DM / 4 + 255) / 256, 256>>>((const float4*)kv_w, (__half2*)p_kvw, DM * 2 * DM / 4);
    f2h_kernel<<<(DM * DM / 4 + 255) / 256, 256>>>((const float4*)q_w, (__half2*)p_qw, DM * DM / 4);
    f2h_kernel<<<(DM * 4 * DM / 4 + 255) / 256, 256>>>((const float4*)mlp_w1, (__half2*)p_w1, DM * 4 * DM / 4);
    f2h_kernel<<<(4 * DM * DM / 4 + 255) / 256, 256>>>((const float4*)mlp_w2, (__half2*)p_w2, 4 * DM * DM / 4);

    conv_mma<<<dim3(3, 8, CSPLIT), 256>>>(x);
    conv_ln_kernel<<<NB * N_OUT, 384>>>(conv_b, g1, b1);

    // loop-invariant kv with fused rose-K + V split
    gemm_mma<128><<<dim3(6, 64), 256>>>(x, p_kvw, kv_b, nullptr, NB * N_IN, 2 * DM, DM, 3, freqs, temp);

    for (int it = 0; it < 3; it++) {
        gemm_mma<64><<<dim3(3, 16), 256>>>(p_xout, p_qw, q_b, nullptr, NB * N_OUT, DM, DM, 2, freqs, temp);
        rowsum_mma<<<dim3(8, BHTOT), 256>>>();
        colinv_mma<<<dim3(32, BHTOT), 256>>>();
        if (it < 2)
            upd_mma2<false><<<dim3(4, BHTOT), 256>>>(nullptr, nullptr);
        else
            upd_mma2<true><<<dim3(4, BHTOT), 256>>>(attn_k_out, attn_q_out);
        ln_add_kernel<<<NB * N_OUT, 384>>>(p_upd, g2, b2, p_xout);
        gemm_mma<64><<<dim3(12, 16), 256>>>(p_xout, p_w1, mlp_b1, p_mlp, NB * N_OUT, 4 * DM, DM, 1, freqs, temp);
        gemm_mma<64><<<dim3(3, 16), 256>>>(p_mlp, p_w2, mlp_b2, p_mlpo, NB * N_OUT, DM, 4 * DM, 0, freqs, temp);
        ln_add_kernel<<<NB * N_OUT, 384>>>(p_mlpo, g3, b3, it == 2 ? out : p_xout);
    }
}